// round 9
// baseline (speedup 1.0000x reference)
#include <cuda_runtime.h>
#include <cuda_bf16.h>
#include <cstdint>
#include <math.h>

// Problem constants
#define B_ 8
#define T_ 8192
#define C_ 256
#define H_ 8
#define G_ 64
#define D_ 32
#define N_ (B_*T_)
#define NCH2 16
#define ASTR 40   // GEMM smem row stride (80B, conflict-free for ldmatrix)

// ---------------- scratch ------------------------------------------------------
__device__ __nv_bfloat16 g_tmphi[(size_t)N_ * C_];
__device__ __nv_bfloat16 g_tmplo[(size_t)N_ * C_];
__device__ __nv_bfloat16 g_swhi[(size_t)N_ * H_ * G_];
__device__ __nv_bfloat16 g_swlo[(size_t)N_ * H_ * G_];
__device__ float g_part[(size_t)B_ * H_ * NCH2 * G_ * D_];
__device__ float g_pnorm[(size_t)B_ * H_ * NCH2 * G_];
__device__ float g_os[(size_t)B_ * H_ * G_ * D_];
__device__ __nv_bfloat16 g_Whi[(size_t)C_ * C_];
__device__ __nv_bfloat16 g_Wlo[(size_t)C_ * C_];
__device__ __nv_bfloat16 g_Mhi[(size_t)B_ * C_ * (H_ * G_)];
__device__ __nv_bfloat16 g_Mlo[(size_t)B_ * C_ * (H_ * G_)];

// ---------------- small helpers ------------------------------------------------
__device__ __forceinline__ float2 ffma2(float2 a, float2 b, float2 c) {
    float2 d;
    asm("fma.rn.f32x2 %0, %1, %2, %3;"
        : "=l"(reinterpret_cast<unsigned long long&>(d))
        : "l"(reinterpret_cast<unsigned long long&>(a)),
          "l"(reinterpret_cast<unsigned long long&>(b)),
          "l"(reinterpret_cast<unsigned long long&>(c)));
    return d;
}
__device__ __forceinline__ uint32_t smem_to_u32(const void* p) {
    uint32_t a;
    asm("{ .reg .u64 t; cvta.to.shared.u64 t, %1; cvt.u32.u64 %0, t; }" : "=r"(a) : "l"(p));
    return a;
}
__device__ __forceinline__ void ldsm_x4(uint32_t& r0, uint32_t& r1, uint32_t& r2, uint32_t& r3,
                                        uint32_t addr) {
    asm volatile("ldmatrix.sync.aligned.m8n8.x4.shared.b16 {%0,%1,%2,%3}, [%4];"
                 : "=r"(r0), "=r"(r1), "=r"(r2), "=r"(r3) : "r"(addr));
}
__device__ __forceinline__ void ldsm_x4_t(uint32_t& r0, uint32_t& r1, uint32_t& r2, uint32_t& r3,
                                          uint32_t addr) {
    asm volatile("ldmatrix.sync.aligned.m8n8.x4.trans.shared.b16 {%0,%1,%2,%3}, [%4];"
                 : "=r"(r0), "=r"(r1), "=r"(r2), "=r"(r3) : "r"(addr));
}
__device__ __forceinline__ void ldsm_x2_t(uint32_t& r0, uint32_t& r1, uint32_t addr) {
    asm volatile("ldmatrix.sync.aligned.m8n8.x2.trans.shared.b16 {%0,%1}, [%2];"
                 : "=r"(r0), "=r"(r1) : "r"(addr));
}
__device__ __forceinline__ void mma_bf16(float* d, const uint32_t* a, uint32_t b0, uint32_t b1) {
    asm volatile("mma.sync.aligned.m16n8k16.row.col.f32.bf16.bf16.f32 "
        "{%0,%1,%2,%3}, {%4,%5,%6,%7}, {%8,%9}, {%0,%1,%2,%3};"
        : "+f"(d[0]), "+f"(d[1]), "+f"(d[2]), "+f"(d[3])
        : "r"(a[0]), "r"(a[1]), "r"(a[2]), "r"(a[3]), "r"(b0), "r"(b1));
}
__device__ __forceinline__ uint32_t bits2(__nv_bfloat162 h) {
    return *reinterpret_cast<uint32_t*>(&h);
}
__device__ __forceinline__ float2 upk2(uint32_t hu, uint32_t lu) {
    __nv_bfloat162 hh = *reinterpret_cast<__nv_bfloat162*>(&hu);
    __nv_bfloat162 ll = *reinterpret_cast<__nv_bfloat162*>(&lu);
    return make_float2(__bfloat162float(hh.x) + __bfloat162float(ll.x),
                       __bfloat162float(hh.y) + __bfloat162float(ll.y));
}
#define CP_ASYNC16(dst, src) \
    asm volatile("cp.async.cg.shared.global [%0], [%1], 16;" :: "r"(dst), "l"(src))
#define CP_COMMIT() asm volatile("cp.async.commit_group;" ::: "memory")
#define CP_WAIT0()  asm volatile("cp.async.wait_group 0;" ::: "memory")
#define CP_WAIT1()  asm volatile("cp.async.wait_group 1;" ::: "memory")

#define STG_BYTES (128 * ASTR * 2)
#define STAGE_BYTES (4 * STG_BYTES)
#define K1_SMEM (2 * STAGE_BYTES)            // 81920 B (2-stage)
#define AB_SMEM (3 * STAGE_BYTES)            // 122880 B (3-stage)
#define OAH 0
#define OAL STG_BYTES
#define OBH (2 * STG_BYTES)
#define OBL (3 * STG_BYTES)

// ============== GEMM variant 1 (K1): A fp32 in, bf16 hi/lo out =================
__global__ __launch_bounds__(256, 1) void hmma_gemm_k1_kernel(
    const float* __restrict__ A, int lda,
    const __nv_bfloat16* __restrict__ Bhi, const __nv_bfloat16* __restrict__ Blo,
    __nv_bfloat16* __restrict__ Chi, __nv_bfloat16* __restrict__ Clo, int ldc,
    const float* __restrict__ bias, int K)
{
    extern __shared__ __align__(16) char smd[];
    const uint32_t sbase = smem_to_u32(smd);

    const int tid = threadIdx.x;
    const int wid = tid >> 5, lane = tid & 31;
    const int wm = wid & 3, wn = wid >> 2;
    const int m0 = wm * 32, n0w = wn * 64;

    const float* Ab = A + (size_t)blockIdx.y * 128 * lda;
    const __nv_bfloat16* Bhb = Bhi + (size_t)(blockIdx.x * 128) * K;
    const __nv_bfloat16* Blb = Blo + (size_t)(blockIdx.x * 128) * K;

    const int lrow = lane & 15;
    const int lcol = (lane >> 4) * 8;
    const int arow = tid >> 1;
    const int akh  = (tid & 1) << 4;
    const int c0row = tid >> 1, c0seg = (tid & 1) * 2;

    float acc[2][8][4];
    #pragma unroll
    for (int mi = 0; mi < 2; mi++)
        #pragma unroll
        for (int n = 0; n < 8; n++)
            #pragma unroll
            for (int q = 0; q < 4; q++) acc[mi][n][q] = 0.f;

    float fst[16];

    auto load_A_regs = [&](int kt) {
        const float* ap = Ab + (size_t)arow * lda + kt + akh;
        *(float4*)(fst + 0)  = *(const float4*)(ap);
        *(float4*)(fst + 4)  = *(const float4*)(ap + 4);
        *(float4*)(fst + 8)  = *(const float4*)(ap + 8);
        *(float4*)(fst + 12) = *(const float4*)(ap + 12);
    };
    auto cpasync_B = [&](int kt, int stg) {
        uint32_t dst = sbase + stg * STAGE_BYTES + c0row * (ASTR * 2) + c0seg * 16;
        const char* srch = (const char*)(Bhb + (size_t)c0row * K + kt) + c0seg * 16;
        const char* srcl = (const char*)(Blb + (size_t)c0row * K + kt) + c0seg * 16;
        CP_ASYNC16(dst + OBH, srch);
        CP_ASYNC16(dst + OBH + 16, srch + 16);
        CP_ASYNC16(dst + OBL, srcl);
        CP_ASYNC16(dst + OBL + 16, srcl + 16);
    };
    auto store_A = [&](int stg) {
        uint32_t h[8], l[8];
        #pragma unroll
        for (int i = 0; i < 8; i++) {
            __nv_bfloat162 hb = __floats2bfloat162_rn(fst[2*i], fst[2*i+1]);
            float r0 = fst[2*i]   - __bfloat162float(hb.x);
            float r1 = fst[2*i+1] - __bfloat162float(hb.y);
            h[i] = bits2(hb);
            l[i] = bits2(__floats2bfloat162_rn(r0, r1));
        }
        char* dh = smd + stg * STAGE_BYTES + OAH + arow * (ASTR * 2) + akh * 2;
        char* dl = smd + stg * STAGE_BYTES + OAL + arow * (ASTR * 2) + akh * 2;
        ((uint4*)dh)[0] = make_uint4(h[0], h[1], h[2], h[3]);
        ((uint4*)dh)[1] = make_uint4(h[4], h[5], h[6], h[7]);
        ((uint4*)dl)[0] = make_uint4(l[0], l[1], l[2], l[3]);
        ((uint4*)dl)[1] = make_uint4(l[4], l[5], l[6], l[7]);
    };

    load_A_regs(0);
    cpasync_B(0, 0);
    CP_COMMIT();
    store_A(0);
    CP_WAIT0();
    __syncthreads();

    int stage = 0;
    for (int kt = 0; kt < K; kt += 32) {
        const bool has_next = (kt + 32 < K);
        if (has_next) {
            load_A_regs(kt + 32);
            cpasync_B(kt + 32, stage ^ 1);
            CP_COMMIT();
        }

        const uint32_t sb = sbase + stage * STAGE_BYTES;
        #pragma unroll
        for (int ks = 0; ks < 2; ks++) {
            const int cb = ks * 16 + lcol;
            uint32_t ahi[2][4], alo[2][4], bh[4][4], bl[4][4];
            #pragma unroll
            for (int mi = 0; mi < 2; mi++) {
                uint32_t off = ((m0 + mi * 16 + lrow) * ASTR + cb) * 2;
                ldsm_x4(ahi[mi][0], ahi[mi][1], ahi[mi][2], ahi[mi][3], sb + OAH + off);
                ldsm_x4(alo[mi][0], alo[mi][1], alo[mi][2], alo[mi][3], sb + OAL + off);
            }
            #pragma unroll
            for (int nj = 0; nj < 4; nj++) {
                uint32_t off = ((n0w + nj * 16 + lrow) * ASTR + cb) * 2;
                ldsm_x4(bh[nj][0], bh[nj][1], bh[nj][2], bh[nj][3], sb + OBH + off);
                ldsm_x4(bl[nj][0], bl[nj][1], bl[nj][2], bl[nj][3], sb + OBL + off);
            }
            #pragma unroll
            for (int mi = 0; mi < 2; mi++) {
                #pragma unroll
                for (int nj = 0; nj < 4; nj++) {
                    float* d0 = acc[mi][nj * 2];
                    mma_bf16(d0, ahi[mi], bh[nj][0], bh[nj][2]);
                    mma_bf16(d0, ahi[mi], bl[nj][0], bl[nj][2]);
                    mma_bf16(d0, alo[mi], bh[nj][0], bh[nj][2]);
                    float* d1 = acc[mi][nj * 2 + 1];
                    mma_bf16(d1, ahi[mi], bh[nj][1], bh[nj][3]);
                    mma_bf16(d1, ahi[mi], bl[nj][1], bl[nj][3]);
                    mma_bf16(d1, alo[mi], bh[nj][1], bh[nj][3]);
                }
            }
        }

        if (has_next) {
            store_A(stage ^ 1);
            CP_WAIT0();
            __syncthreads();
            stage ^= 1;
        }
    }

    // epilogue: bias + split into bf16 hi/lo
    const int grp = lane >> 2, qid = lane & 3;
    #pragma unroll
    for (int mi = 0; mi < 2; mi++) {
        #pragma unroll
        for (int nj = 0; nj < 8; nj++) {
            int row = blockIdx.y * 128 + m0 + mi * 16 + grp;
            int col = blockIdx.x * 128 + n0w + nj * 8 + qid * 2;
            float b0 = bias[col], b1 = bias[col + 1];
            float v0 = acc[mi][nj][0] + b0, v1 = acc[mi][nj][1] + b1;
            float v2 = acc[mi][nj][2] + b0, v3 = acc[mi][nj][3] + b1;
            __nv_bfloat162 h01 = __floats2bfloat162_rn(v0, v1);
            __nv_bfloat162 h23 = __floats2bfloat162_rn(v2, v3);
            *(uint32_t*)(Chi + (size_t)row * ldc + col) = bits2(h01);
            *(uint32_t*)(Chi + (size_t)(row + 8) * ldc + col) = bits2(h23);
            *(uint32_t*)(Clo + (size_t)row * ldc + col) =
                bits2(__floats2bfloat162_rn(v0 - __bfloat162float(h01.x),
                                            v1 - __bfloat162float(h01.y)));
            *(uint32_t*)(Clo + (size_t)(row + 8) * ldc + col) =
                bits2(__floats2bfloat162_rn(v2 - __bfloat162float(h23.x),
                                            v3 - __bfloat162float(h23.y)));
        }
    }
}

// ============== GEMM variant 2 (K5): pre-split bf16, 3-stage, occ 1 ============
__global__ __launch_bounds__(256, 1) void hmma_gemm_ab_kernel(
    const __nv_bfloat16* __restrict__ Ahi, const __nv_bfloat16* __restrict__ Alo,
    size_t strideA,
    const __nv_bfloat16* __restrict__ Bhi, const __nv_bfloat16* __restrict__ Blo,
    size_t strideB,
    float* __restrict__ Cm, int ldc, size_t strideC,
    const float* __restrict__ bias, int K)
{
    extern __shared__ __align__(16) char smd[];
    const uint32_t sbase = smem_to_u32(smd);

    const int tid = threadIdx.x;
    const int wid = tid >> 5, lane = tid & 31;
    const int wm = wid & 3, wn = wid >> 2;
    const int m0 = wm * 32, n0w = wn * 64;

    const __nv_bfloat16* Ahb = Ahi + (size_t)blockIdx.z * strideA + (size_t)(blockIdx.y * 128) * K;
    const __nv_bfloat16* Alb = Alo + (size_t)blockIdx.z * strideA + (size_t)(blockIdx.y * 128) * K;
    const __nv_bfloat16* Bhb = Bhi + (size_t)blockIdx.z * strideB + (size_t)(blockIdx.x * 128) * K;
    const __nv_bfloat16* Blb = Blo + (size_t)blockIdx.z * strideB + (size_t)(blockIdx.x * 128) * K;
    float* Cb = Cm + (size_t)blockIdx.z * strideC;

    const int lrow = lane & 15;
    const int lcol = (lane >> 4) * 8;
    const int c0row = tid >> 1, c0seg = (tid & 1) * 2;

    float acc[2][8][4];
    #pragma unroll
    for (int mi = 0; mi < 2; mi++)
        #pragma unroll
        for (int n = 0; n < 8; n++)
            #pragma unroll
            for (int q = 0; q < 4; q++) acc[mi][n][q] = 0.f;

    auto cpasync_all = [&](int kt, int stg) {
        uint32_t dst = sbase + stg * STAGE_BYTES + c0row * (ASTR * 2) + c0seg * 16;
        const char* sah = (const char*)(Ahb + (size_t)c0row * K + kt) + c0seg * 16;
        const char* sal = (const char*)(Alb + (size_t)c0row * K + kt) + c0seg * 16;
        const char* sbh = (const char*)(Bhb + (size_t)c0row * K + kt) + c0seg * 16;
        const char* sbl = (const char*)(Blb + (size_t)c0row * K + kt) + c0seg * 16;
        CP_ASYNC16(dst + OAH, sah); CP_ASYNC16(dst + OAH + 16, sah + 16);
        CP_ASYNC16(dst + OAL, sal); CP_ASYNC16(dst + OAL + 16, sal + 16);
        CP_ASYNC16(dst + OBH, sbh); CP_ASYNC16(dst + OBH + 16, sbh + 16);
        CP_ASYNC16(dst + OBL, sbl); CP_ASYNC16(dst + OBL + 16, sbl + 16);
    };

    const int NT = K >> 5;
    // prologue: stage 0 and 1 in flight
    cpasync_all(0, 0);
    CP_COMMIT();
    if (NT > 1) { cpasync_all(32, 1); CP_COMMIT(); CP_WAIT1(); }
    else        { CP_WAIT0(); }
    __syncthreads();

    for (int t = 0; t < NT; t++) {
        const bool has_n2 = (t + 2 < NT);
        if (has_n2) {
            cpasync_all((t + 2) * 32, (t + 2) % 3);
            CP_COMMIT();
        }

        const uint32_t sb = sbase + (t % 3) * STAGE_BYTES;
        #pragma unroll
        for (int ks = 0; ks < 2; ks++) {
            const int cb = ks * 16 + lcol;
            uint32_t ahi[2][4], alo[2][4], bh[4][4], bl[4][4];
            #pragma unroll
            for (int mi = 0; mi < 2; mi++) {
                uint32_t off = ((m0 + mi * 16 + lrow) * ASTR + cb) * 2;
                ldsm_x4(ahi[mi][0], ahi[mi][1], ahi[mi][2], ahi[mi][3], sb + OAH + off);
                ldsm_x4(alo[mi][0], alo[mi][1], alo[mi][2], alo[mi][3], sb + OAL + off);
            }
            #pragma unroll
            for (int nj = 0; nj < 4; nj++) {
                uint32_t off = ((n0w + nj * 16 + lrow) * ASTR + cb) * 2;
                ldsm_x4(bh[nj][0], bh[nj][1], bh[nj][2], bh[nj][3], sb + OBH + off);
                ldsm_x4(bl[nj][0], bl[nj][1], bl[nj][2], bl[nj][3], sb + OBL + off);
            }
            #pragma unroll
            for (int mi = 0; mi < 2; mi++) {
                #pragma unroll
                for (int nj = 0; nj < 4; nj++) {
                    float* d0 = acc[mi][nj * 2];
                    mma_bf16(d0, ahi[mi], bh[nj][0], bh[nj][2]);
                    mma_bf16(d0, ahi[mi], bl[nj][0], bl[nj][2]);
                    mma_bf16(d0, alo[mi], bh[nj][0], bh[nj][2]);
                    float* d1 = acc[mi][nj * 2 + 1];
                    mma_bf16(d1, ahi[mi], bh[nj][1], bh[nj][3]);
                    mma_bf16(d1, ahi[mi], bl[nj][1], bl[nj][3]);
                    mma_bf16(d1, alo[mi], bh[nj][1], bh[nj][3]);
                }
            }
        }

        if (t + 1 < NT) {
            if (has_n2) { CP_WAIT1(); } else { CP_WAIT0(); }
            __syncthreads();
        }
    }

    const int grp = lane >> 2, qid = lane & 3;
    #pragma unroll
    for (int mi = 0; mi < 2; mi++) {
        #pragma unroll
        for (int nj = 0; nj < 8; nj++) {
            int row = blockIdx.y * 128 + m0 + mi * 16 + grp;
            int col = blockIdx.x * 128 + n0w + nj * 8 + qid * 2;
            float b0 = bias[col], b1 = bias[col + 1];
            *(float2*)(Cb + (size_t)row * ldc + col) =
                make_float2(acc[mi][nj][0] + b0, acc[mi][nj][1] + b1);
            *(float2*)(Cb + (size_t)(row + 8) * ldc + col) =
                make_float2(acc[mi][nj][2] + b0, acc[mi][nj][3] + b1);
        }
    }
}

// ---------------- prep: split W_in into transposed bf16 hi/lo ------------------
__global__ __launch_bounds__(256) void split_w_kernel(const float* __restrict__ W)
{
    int idx = blockIdx.x * 256 + threadIdx.x;   // k*256 + n
    int k = idx >> 8, n = idx & 255;
    float v = W[idx];
    __nv_bfloat16 h = __float2bfloat16_rn(v);
    g_Whi[(size_t)n * C_ + k] = h;
    g_Wlo[(size_t)n * C_ + k] = __float2bfloat16_rn(v - __bfloat162float(h));
}

// ---------------- K2: slice weights -> bf16 hi/lo ------------------------------
__global__ __launch_bounds__(256) void slicew_kernel(
    const float* __restrict__ Wslice, const float* __restrict__ bslice,
    const float* __restrict__ temp)
{
    __shared__ float Ws[D_ * G_];
    __shared__ float bs[G_];
    __shared__ float it[H_];
    int tid = threadIdx.x;
    #pragma unroll
    for (int i = 0; i < 8; i++) Ws[tid + i * 256] = Wslice[tid + i * 256];
    if (tid < G_) bs[tid] = bslice[tid];
    if (tid < H_) it[tid] = 1.f / temp[tid];
    __syncthreads();

    int gid = blockIdx.x * 256 + tid;
    int n = gid >> 3, h = gid & 7;

    float x[D_];
    const uint4* XH = (const uint4*)(g_tmphi + (size_t)n * C_ + h * D_);
    const uint4* XL = (const uint4*)(g_tmplo + (size_t)n * C_ + h * D_);
    #pragma unroll
    for (int i = 0; i < 4; i++) {
        uint4 hv = XH[i], lv = XL[i];
        float2 p0 = upk2(hv.x, lv.x), p1 = upk2(hv.y, lv.y);
        float2 p2 = upk2(hv.z, lv.z), p3 = upk2(hv.w, lv.w);
        x[8*i+0] = p0.x; x[8*i+1] = p0.y; x[8*i+2] = p1.x; x[8*i+3] = p1.y;
        x[8*i+4] = p2.x; x[8*i+5] = p2.y; x[8*i+6] = p3.x; x[8*i+7] = p3.y;
    }

    float2 lg[G_ / 2];
    const float2* bs2 = (const float2*)bs;
    #pragma unroll
    for (int j = 0; j < G_ / 2; j++) lg[j] = bs2[j];

    const float2* Ws2 = (const float2*)Ws;
    for (int d = 0; d < D_; d++) {
        float2 xv = make_float2(x[d], x[d]);
        #pragma unroll
        for (int j = 0; j < G_ / 2; j++) lg[j] = ffma2(xv, Ws2[d * (G_ / 2) + j], lg[j]);
    }

    float sc = it[h];
    float mx = -1e30f;
    #pragma unroll
    for (int j = 0; j < G_ / 2; j++) {
        lg[j].x *= sc; lg[j].y *= sc;
        mx = fmaxf(mx, fmaxf(lg[j].x, lg[j].y));
    }
    float sum = 0.f;
    #pragma unroll
    for (int j = 0; j < G_ / 2; j++) {
        lg[j].x = __expf(lg[j].x - mx);
        lg[j].y = __expf(lg[j].y - mx);
        sum += lg[j].x + lg[j].y;
    }
    float inv = 1.f / sum;

    size_t base = (size_t)n * (H_ * G_) + h * G_;
    uint2* dhi = (uint2*)(g_swhi + base);
    uint2* dlo = (uint2*)(g_swlo + base);
    #pragma unroll
    for (int j = 0; j < 16; j++) {
        float v0 = lg[2*j].x * inv, v1 = lg[2*j].y * inv;
        float v2 = lg[2*j+1].x * inv, v3 = lg[2*j+1].y * inv;
        __nv_bfloat162 h01 = __floats2bfloat162_rn(v0, v1);
        __nv_bfloat162 h23 = __floats2bfloat162_rn(v2, v3);
        dhi[j] = make_uint2(bits2(h01), bits2(h23));
        __nv_bfloat162 l01 = __floats2bfloat162_rn(v0 - __bfloat162float(h01.x),
                                                   v1 - __bfloat162float(h01.y));
        __nv_bfloat162 l23 = __floats2bfloat162_rn(v2 - __bfloat162float(h23.x),
                                                   v3 - __bfloat162float(h23.y));
        dlo[j] = make_uint2(bits2(l01), bits2(l23));
    }
}

// ---------------- K3: pooling GEMM, ldmatrix.trans, 2 ping-pong warp groups ----
#define PG_SWH 0
#define PG_SWL 9216
#define PG_XH  18432
#define PG_XL  23552
#define PG_SIZE 28672
#define P_TOTAL (2 * PG_SIZE)

__global__ __launch_bounds__(256, 1) void pool_mma_kernel()
{
    extern __shared__ __align__(16) char psm[];
    const uint32_t sbm = smem_to_u32(psm);

    const int tid = threadIdx.x, lane = tid & 31, w = tid >> 5;
    const int wg = w >> 2, wl = w & 3;
    const int g_tid = tid & 127;
    const int pc = blockIdx.x, bh = blockIdx.y;
    const int b = bh >> 3, h = bh & 7;
    const uint32_t gb = sbm + wg * PG_SIZE;

    for (int i = tid; i < 128; i += 256) {
        int gg = i >> 6, row = i & 63;
        *(uint4*)(psm + gg * PG_SIZE + PG_XH + row * 80 + 64) =
            make_uint4(0x00003F80u, 0u, 0u, 0u);
        *(uint4*)(psm + gg * PG_SIZE + PG_XL + row * 80 + 64) =
            make_uint4(0u, 0u, 0u, 0u);
    }
    __syncthreads();

    float acc[4][5][4];
    #pragma unroll
    for (int mi = 0; mi < 4; mi++)
        #pragma unroll
        for (int nj = 0; nj < 5; nj++)
            #pragma unroll
            for (int q = 0; q < 4; q++) acc[mi][nj][q] = 0.f;

    const int cb = wl * 16;
    const int trow = cb + ((lane >> 4) << 3) + (lane & 7);
    const int tcol8 = ((lane >> 3) & 1) << 3;
    const int r2 = cb + (((lane >> 3) & 1) << 3) + (lane & 7);

    for (int it = 0; it < 4; it++) {
        int sc = 2 * it + wg;
        size_t gn = (size_t)b * T_ + pc * 512 + (size_t)sc * 64;

        #pragma unroll
        for (int i = 0; i < 4; i++) {
            int c = g_tid + i * 128;
            int row = c >> 3, seg = c & 7;
            const char* sh = (const char*)(g_swhi + (gn + row) * (H_ * G_) + h * G_) + seg * 16;
            const char* sl = (const char*)(g_swlo + (gn + row) * (H_ * G_) + h * G_) + seg * 16;
            CP_ASYNC16(gb + PG_SWH + row * 144 + seg * 16, sh);
            CP_ASYNC16(gb + PG_SWL + row * 144 + seg * 16, sl);
        }
        #pragma unroll
        for (int i = 0; i < 2; i++) {
            int c = g_tid + i * 128;
            int row = c >> 2, seg = c & 3;
            const char* xh = (const char*)(g_tmphi + (gn + row) * C_ + h * D_) + seg * 16;
            const char* xl = (const char*)(g_tmplo + (gn + row) * C_ + h * D_) + seg * 16;
            CP_ASYNC16(gb + PG_XH + row * 80 + seg * 16, xh);
            CP_ASYNC16(gb + PG_XL + row * 80 + seg * 16, xl);
        }
        CP_COMMIT();
        CP_WAIT0();
        asm volatile("bar.sync %0, 128;" :: "r"(wg + 1) : "memory");

        uint32_t bxh[2][4], bxl[2][4], b2h[2], b2l[2];
        #pragma unroll
        for (int t = 0; t < 2; t++) {
            uint32_t off = (trow * 40 + t * 16 + tcol8) * 2;
            ldsm_x4_t(bxh[t][0], bxh[t][1], bxh[t][2], bxh[t][3], gb + PG_XH + off);
            ldsm_x4_t(bxl[t][0], bxl[t][1], bxl[t][2], bxl[t][3], gb + PG_XL + off);
        }
        {
            uint32_t off = (r2 * 40 + 32) * 2;
            ldsm_x2_t(b2h[0], b2h[1], gb + PG_XH + off);
            ldsm_x2_t(b2l[0], b2l[1], gb + PG_XL + off);
        }

        #pragma unroll
        for (int mi = 0; mi < 4; mi++) {
            uint32_t ah[4], al[4];
            uint32_t off = (trow * 72 + mi * 16 + tcol8) * 2;
            ldsm_x4_t(ah[0], ah[1], ah[2], ah[3], gb + PG_SWH + off);
            ldsm_x4_t(al[0], al[1], al[2], al[3], gb + PG_SWL + off);
            #pragma unroll
            for (int nj = 0; nj < 5; nj++) {
                uint32_t b0h, b1h, b0l, b1l;
                if (nj < 4) {
                    int t = nj >> 1, p = nj & 1;
                    b0h = bxh[t][p]; b1h = bxh[t][p + 2];
                    b0l = bxl[t][p]; b1l = bxl[t][p + 2];
                } else {
                    b0h = b2h[0]; b1h = b2h[1];
                    b0l = b2l[0]; b1l = b2l[1];
                }
                float* d = acc[mi][nj];
                mma_bf16(d, ah, b0h, b1h);
                mma_bf16(d, ah, b0l, b1l);
                mma_bf16(d, al, b0h, b1h);
            }
        }
        asm volatile("bar.sync %0, 128;" :: "r"(wg + 1) : "memory");
    }

    __syncthreads();
    float* red = (float*)psm;
    const int grp = lane >> 2, qid = lane & 3;
    if (wg == 0) {
        #pragma unroll
        for (int mi = 0; mi < 4; mi++)
            #pragma unroll
            for (int nj = 0; nj < 5; nj++) {
                int g0 = mi * 16 + grp, nn = nj * 8 + qid * 2;
                red[(wl * 64 + g0) * 40 + nn]         = acc[mi][nj][0];
                red[(wl * 64 + g0) * 40 + nn + 1]     = acc[mi][nj][1];
                red[(wl * 64 + g0 + 8) * 40 + nn]     = acc[mi][nj][2];
                red[(wl * 64 + g0 + 8) * 40 + nn + 1] = acc[mi][nj][3];
            }
    }
    __syncthreads();
    if (wg == 1) {
        #pragma unroll
        for (int mi = 0; mi < 4; mi++)
            #pragma unroll
            for (int nj = 0; nj < 5; nj++) {
                int g0 = mi * 16 + grp, nn = nj * 8 + qid * 2;
                red[(wl * 64 + g0) * 40 + nn]         += acc[mi][nj][0];
                red[(wl * 64 + g0) * 40 + nn + 1]     += acc[mi][nj][1];
                red[(wl * 64 + g0 + 8) * 40 + nn]     += acc[mi][nj][2];
                red[(wl * 64 + g0 + 8) * 40 + nn + 1] += acc[mi][nj][3];
            }
    }
    __syncthreads();

    for (int i = tid; i < 64 * 33; i += 256) {
        int g = i / 33, s = i - g * 33;
        float sum = red[g * 40 + s] + red[(64 + g) * 40 + s]
                  + red[(128 + g) * 40 + s] + red[(192 + g) * 40 + s];
        if (s < 32) g_part[((size_t)bh * NCH2 + pc) * (G_ * D_) + g * D_ + s] = sum;
        else        g_pnorm[((size_t)bh * NCH2 + pc) * G_ + g] = sum;
    }
}

// ------- K4a: reduce partials -> tokens -> qkv -> GxG attention -> g_os --------
__global__ __launch_bounds__(256) void attn_tiny_kernel(
    const float* __restrict__ Wq, const float* __restrict__ bq,
    const float* __restrict__ Wk, const float* __restrict__ bk,
    const float* __restrict__ Wv, const float* __restrict__ bv)
{
    __shared__ float tok[G_][D_ + 1];
    __shared__ float qs[G_][D_ + 1];
    __shared__ float ks[G_][D_ + 1];
    __shared__ float vs[G_][D_ + 1];
    __shared__ float norms[G_];

    int bh = blockIdx.x;
    int tid = threadIdx.x;

    if (tid < G_) {
        float s = 0.f;
        for (int ch = 0; ch < NCH2; ch++)
            s += g_pnorm[((size_t)bh * NCH2 + ch) * G_ + tid];
        norms[tid] = s + 1e-5f;
    }
    __syncthreads();

    #pragma unroll
    for (int i = 0; i < 8; i++) {
        int c = tid + i * 256;
        int g = c >> 5, d = c & 31;
        float s = 0.f;
        for (int ch = 0; ch < NCH2; ch++)
            s += g_part[((size_t)bh * NCH2 + ch) * (G_ * D_) + c];
        tok[g][d] = s / norms[g];
    }
    __syncthreads();

    #pragma unroll
    for (int i = 0; i < 8; i++) {
        int c = tid + i * 256;
        int g = c >> 5, d = c & 31;
        float aq = bq[d], ak = bk[d], av = bv[d];
        for (int e = 0; e < D_; e++) {
            float t = tok[g][e];
            aq += t * Wq[e * D_ + d];
            ak += t * Wk[e * D_ + d];
            av += t * Wv[e * D_ + d];
        }
        qs[g][d] = aq; ks[g][d] = ak; vs[g][d] = av;
    }
    __syncthreads();

    if (tid < G_) {
        float qr[D_];
        #pragma unroll
        for (int d = 0; d < D_; d++) qr[d] = qs[tid][d];
        float s[G_];
        float mx = -1e30f;
        #pragma unroll
        for (int j = 0; j < G_; j++) {
            float a = 0.f;
            #pragma unroll
            for (int d = 0; d < D_; d++) a += qr[d] * ks[j][d];
            a *= 0.17677669529663687f;
            s[j] = a; mx = fmaxf(mx, a);
        }
        float sum = 0.f;
        #pragma unroll
        for (int j = 0; j < G_; j++) { s[j] = __expf(s[j] - mx); sum += s[j]; }
        float inv = 1.f / sum;
        #pragma unroll
        for (int d = 0; d < D_; d++) {
            float a = 0.f;
            #pragma unroll
            for (int j = 0; j < G_; j++) a += s[j] * vs[j][d];
            g_os[(size_t)bh * (G_ * D_) + tid * D_ + d] = a * inv;
        }
    }
}

// ------- K4b: fold into transposed bf16 hi/lo M --------------------------------
__global__ __launch_bounds__(256) void fold_kernel(const float* __restrict__ Wout)
{
    __shared__ float os[G_][D_ + 1];
    __shared__ float Wt[D_][G_ + 1];
    int bh = blockIdx.y;
    int b = bh >> 3, h = bh & 7;
    int col0 = blockIdx.x * 64;
    int tid = threadIdx.x;

    #pragma unroll
    for (int i = 0; i < 8; i++) {
        int idx = tid + i * 256;
        os[idx >> 5][idx & 31] = g_os[(size_t)bh * (G_ * D_) + idx];
    }
    #pragma unroll
    for (int i = 0; i < 8; i++) {
        int idx = tid + i * 256;
        int d = idx >> 6, c = idx & 63;
        Wt[d][c] = Wout[(size_t)(h * D_ + d) * C_ + col0 + c];
    }
    __syncthreads();

    int c = tid & 63, g0 = tid >> 6;
    #pragma unroll
    for (int gi = 0; gi < 16; gi++) {
        int g = g0 * 16 + gi;
        float a = 0.f;
        #pragma unroll
        for (int d = 0; d < D_; d++) a += os[g][d] * Wt[d][c];
        __nv_bfloat16 hb = __float2bfloat16_rn(a);
        size_t o = ((size_t)b * C_ + col0 + c) * (size_t)(H_ * G_) + h * G_ + g;
        g_Mhi[o] = hb;
        g_Mlo[o] = __float2bfloat16_rn(a - __bfloat162float(hb));
    }
}

// ---------------- launch --------------------------------------------------------
extern "C" void kernel_launch(void* const* d_in, const int* in_sizes, int n_in,
                              void* d_out, int out_size)
{
    const float* x_q    = (const float*)d_in[0];
    const float* W_in   = (const float*)d_in[3];
    const float* b_in   = (const float*)d_in[4];
    const float* W_sl   = (const float*)d_in[5];
    const float* b_sl   = (const float*)d_in[6];
    const float* temp   = (const float*)d_in[7];
    const float* W_q    = (const float*)d_in[8];
    const float* b_q    = (const float*)d_in[9];
    const float* W_k    = (const float*)d_in[10];
    const float* b_k    = (const float*)d_in[11];
    const float* W_v    = (const float*)d_in[12];
    const float* b_v    = (const float*)d_in[13];
    const float* W_out  = (const float*)d_in[14];
    const float* b_out  = (const float*)d_in[15];
    float* out = (float*)d_out;

    __nv_bfloat16 *thi_p, *tlo_p, *whi_p, *wlo_p, *mhi_p, *mlo_p, *shi_p, *slo_p;
    cudaGetSymbolAddress((void**)&thi_p, g_tmphi);
    cudaGetSymbolAddress((void**)&tlo_p, g_tmplo);
    cudaGetSymbolAddress((void**)&whi_p, g_Whi);
    cudaGetSymbolAddress((void**)&wlo_p, g_Wlo);
    cudaGetSymbolAddress((void**)&mhi_p, g_Mhi);
    cudaGetSymbolAddress((void**)&mlo_p, g_Mlo);
    cudaGetSymbolAddress((void**)&shi_p, g_swhi);
    cudaGetSymbolAddress((void**)&slo_p, g_swlo);

    static int smem_set = 0;
    if (!smem_set) {
        cudaFuncSetAttribute(hmma_gemm_k1_kernel,
                             cudaFuncAttributeMaxDynamicSharedMemorySize, K1_SMEM);
        cudaFuncSetAttribute(hmma_gemm_ab_kernel,
                             cudaFuncAttributeMaxDynamicSharedMemorySize, AB_SMEM);
        cudaFuncSetAttribute(pool_mma_kernel,
                             cudaFuncAttributeMaxDynamicSharedMemorySize, P_TOTAL);
        smem_set = 1;
    }

    // prep: split W_in
    split_w_kernel<<<C_ * C_ / 256, 256>>>(W_in);

    // K1: tmp = x_q @ W_in + b_in  -> bf16 hi/lo
    hmma_gemm_k1_kernel<<<dim3(C_/128, N_/128), 256, K1_SMEM>>>(
        x_q, C_, whi_p, wlo_p, thi_p, tlo_p, C_, b_in, C_);

    // K2: slice softmax -> bf16 hi/lo
    slicew_kernel<<<(N_ * H_) / 256, 256>>>(W_sl, b_sl, temp);

    // K3: pooling GEMM
    pool_mma_kernel<<<dim3(NCH2, B_ * H_), 256, P_TOTAL>>>();

    // K4a: reduce + tiny attention
    attn_tiny_kernel<<<B_ * H_, 256>>>(W_q, b_q, W_k, b_k, W_v, b_v);

    // K4b: fold W_out into pre-split M
    fold_kernel<<<dim3(4, B_ * H_), 256>>>(W_out);

    // K5: out[b] = SW[b] @ M[b] + b_out  (3-stage, occ 1 — no spills)
    hmma_gemm_ab_kernel<<<dim3(C_/128, T_/128, B_), 256, AB_SMEM>>>(
        shi_p, slo_p, (size_t)T_ * (H_ * G_),
        mhi_p, mlo_p, (size_t)C_ * (H_ * G_),
        out, C_, (size_t)T_ * C_,
        b_out, H_ * G_);
}

// round 11
// speedup vs baseline: 1.2558x; 1.2558x over previous
#include <cuda_runtime.h>
#include <cuda_bf16.h>
#include <cstdint>
#include <math.h>

// Problem constants
#define B_ 8
#define T_ 8192
#define C_ 256
#define H_ 8
#define G_ 64
#define D_ 32
#define N_ (B_*T_)
#define NCH2 16
#define ASTR 40   // GEMM smem row stride (80B, conflict-free for ldmatrix)

// ---------------- scratch ------------------------------------------------------
__device__ __nv_bfloat16 g_tmphi[(size_t)N_ * C_];
__device__ __nv_bfloat16 g_tmplo[(size_t)N_ * C_];
__device__ __nv_bfloat16 g_swhi[(size_t)N_ * H_ * G_];
__device__ float g_part[(size_t)B_ * H_ * NCH2 * G_ * D_];
__device__ float g_pnorm[(size_t)B_ * H_ * NCH2 * G_];
__device__ float g_os[(size_t)B_ * H_ * G_ * D_];
__device__ __nv_bfloat16 g_Whi[(size_t)C_ * C_];
__device__ __nv_bfloat16 g_Wlo[(size_t)C_ * C_];
__device__ __nv_bfloat16 g_Mhi[(size_t)B_ * C_ * (H_ * G_)];
__device__ __nv_bfloat16 g_Mlo[(size_t)B_ * C_ * (H_ * G_)];

// ---------------- small helpers ------------------------------------------------
__device__ __forceinline__ float2 ffma2(float2 a, float2 b, float2 c) {
    float2 d;
    asm("fma.rn.f32x2 %0, %1, %2, %3;"
        : "=l"(reinterpret_cast<unsigned long long&>(d))
        : "l"(reinterpret_cast<unsigned long long&>(a)),
          "l"(reinterpret_cast<unsigned long long&>(b)),
          "l"(reinterpret_cast<unsigned long long&>(c)));
    return d;
}
__device__ __forceinline__ uint32_t smem_to_u32(const void* p) {
    uint32_t a;
    asm("{ .reg .u64 t; cvta.to.shared.u64 t, %1; cvt.u32.u64 %0, t; }" : "=r"(a) : "l"(p));
    return a;
}
__device__ __forceinline__ void ldsm_x4(uint32_t& r0, uint32_t& r1, uint32_t& r2, uint32_t& r3,
                                        uint32_t addr) {
    asm volatile("ldmatrix.sync.aligned.m8n8.x4.shared.b16 {%0,%1,%2,%3}, [%4];"
                 : "=r"(r0), "=r"(r1), "=r"(r2), "=r"(r3) : "r"(addr));
}
__device__ __forceinline__ void ldsm_x4_t(uint32_t& r0, uint32_t& r1, uint32_t& r2, uint32_t& r3,
                                          uint32_t addr) {
    asm volatile("ldmatrix.sync.aligned.m8n8.x4.trans.shared.b16 {%0,%1,%2,%3}, [%4];"
                 : "=r"(r0), "=r"(r1), "=r"(r2), "=r"(r3) : "r"(addr));
}
__device__ __forceinline__ void ldsm_x2_t(uint32_t& r0, uint32_t& r1, uint32_t addr) {
    asm volatile("ldmatrix.sync.aligned.m8n8.x2.trans.shared.b16 {%0,%1}, [%2];"
                 : "=r"(r0), "=r"(r1) : "r"(addr));
}
__device__ __forceinline__ void mma_bf16(float* d, const uint32_t* a, uint32_t b0, uint32_t b1) {
    asm volatile("mma.sync.aligned.m16n8k16.row.col.f32.bf16.bf16.f32 "
        "{%0,%1,%2,%3}, {%4,%5,%6,%7}, {%8,%9}, {%0,%1,%2,%3};"
        : "+f"(d[0]), "+f"(d[1]), "+f"(d[2]), "+f"(d[3])
        : "r"(a[0]), "r"(a[1]), "r"(a[2]), "r"(a[3]), "r"(b0), "r"(b1));
}
__device__ __forceinline__ uint32_t bits2(__nv_bfloat162 h) {
    return *reinterpret_cast<uint32_t*>(&h);
}
__device__ __forceinline__ float2 upk2(uint32_t hu, uint32_t lu) {
    __nv_bfloat162 hh = *reinterpret_cast<__nv_bfloat162*>(&hu);
    __nv_bfloat162 ll = *reinterpret_cast<__nv_bfloat162*>(&lu);
    return make_float2(__bfloat162float(hh.x) + __bfloat162float(ll.x),
                       __bfloat162float(hh.y) + __bfloat162float(ll.y));
}
#define CP_ASYNC16(dst, src) \
    asm volatile("cp.async.cg.shared.global [%0], [%1], 16;" :: "r"(dst), "l"(src))
#define CP_COMMIT() asm volatile("cp.async.commit_group;" ::: "memory")
#define CP_WAIT0()  asm volatile("cp.async.wait_group 0;" ::: "memory")

#define STG_BYTES (128 * ASTR * 2)           // 10240 B per operand buffer

// ---- K1 stage layout (A hi/lo + B hi/lo) ----
#define STAGE_BYTES (4 * STG_BYTES)          // 40960
#define K1_SMEM (2 * STAGE_BYTES)            // 81920
#define OAH 0
#define OAL STG_BYTES
#define OBH (2 * STG_BYTES)
#define OBL (3 * STG_BYTES)

// ---- K5 stage layout (A hi + B hi/lo) ----
#define ST5 (3 * STG_BYTES)                  // 30720
#define AB_SMEM (2 * ST5)                    // 61440 (occ 2 -> 122880/SM)
#define O5AH 0
#define O5BH STG_BYTES
#define O5BL (2 * STG_BYTES)

// ============== GEMM variant 1 (K1): A fp32 in, bf16 hi/lo out =================
__global__ __launch_bounds__(256, 1) void hmma_gemm_k1_kernel(
    const float* __restrict__ A, int lda,
    const __nv_bfloat16* __restrict__ Bhi, const __nv_bfloat16* __restrict__ Blo,
    __nv_bfloat16* __restrict__ Chi, __nv_bfloat16* __restrict__ Clo, int ldc,
    const float* __restrict__ bias, int K)
{
    extern __shared__ __align__(16) char smd[];
    const uint32_t sbase = smem_to_u32(smd);

    const int tid = threadIdx.x;
    const int wid = tid >> 5, lane = tid & 31;
    const int wm = wid & 3, wn = wid >> 2;
    const int m0 = wm * 32, n0w = wn * 64;

    const float* Ab = A + (size_t)blockIdx.y * 128 * lda;
    const __nv_bfloat16* Bhb = Bhi + (size_t)(blockIdx.x * 128) * K;
    const __nv_bfloat16* Blb = Blo + (size_t)(blockIdx.x * 128) * K;

    const int lrow = lane & 15;
    const int lcol = (lane >> 4) * 8;
    const int arow = tid >> 1;
    const int akh  = (tid & 1) << 4;
    const int c0row = tid >> 1, c0seg = (tid & 1) * 2;

    float acc[2][8][4];
    #pragma unroll
    for (int mi = 0; mi < 2; mi++)
        #pragma unroll
        for (int n = 0; n < 8; n++)
            #pragma unroll
            for (int q = 0; q < 4; q++) acc[mi][n][q] = 0.f;

    float fst[16];

    auto load_A_regs = [&](int kt) {
        const float* ap = Ab + (size_t)arow * lda + kt + akh;
        *(float4*)(fst + 0)  = *(const float4*)(ap);
        *(float4*)(fst + 4)  = *(const float4*)(ap + 4);
        *(float4*)(fst + 8)  = *(const float4*)(ap + 8);
        *(float4*)(fst + 12) = *(const float4*)(ap + 12);
    };
    auto cpasync_B = [&](int kt, int stg) {
        uint32_t dst = sbase + stg * STAGE_BYTES + c0row * (ASTR * 2) + c0seg * 16;
        const char* srch = (const char*)(Bhb + (size_t)c0row * K + kt) + c0seg * 16;
        const char* srcl = (const char*)(Blb + (size_t)c0row * K + kt) + c0seg * 16;
        CP_ASYNC16(dst + OBH, srch);
        CP_ASYNC16(dst + OBH + 16, srch + 16);
        CP_ASYNC16(dst + OBL, srcl);
        CP_ASYNC16(dst + OBL + 16, srcl + 16);
    };
    auto store_A = [&](int stg) {
        uint32_t h[8], l[8];
        #pragma unroll
        for (int i = 0; i < 8; i++) {
            __nv_bfloat162 hb = __floats2bfloat162_rn(fst[2*i], fst[2*i+1]);
            float r0 = fst[2*i]   - __bfloat162float(hb.x);
            float r1 = fst[2*i+1] - __bfloat162float(hb.y);
            h[i] = bits2(hb);
            l[i] = bits2(__floats2bfloat162_rn(r0, r1));
        }
        char* dh = smd + stg * STAGE_BYTES + OAH + arow * (ASTR * 2) + akh * 2;
        char* dl = smd + stg * STAGE_BYTES + OAL + arow * (ASTR * 2) + akh * 2;
        ((uint4*)dh)[0] = make_uint4(h[0], h[1], h[2], h[3]);
        ((uint4*)dh)[1] = make_uint4(h[4], h[5], h[6], h[7]);
        ((uint4*)dl)[0] = make_uint4(l[0], l[1], l[2], l[3]);
        ((uint4*)dl)[1] = make_uint4(l[4], l[5], l[6], l[7]);
    };

    load_A_regs(0);
    cpasync_B(0, 0);
    CP_COMMIT();
    store_A(0);
    CP_WAIT0();
    __syncthreads();

    int stage = 0;
    for (int kt = 0; kt < K; kt += 32) {
        const bool has_next = (kt + 32 < K);
        if (has_next) {
            load_A_regs(kt + 32);
            cpasync_B(kt + 32, stage ^ 1);
            CP_COMMIT();
        }

        const uint32_t sb = sbase + stage * STAGE_BYTES;
        #pragma unroll
        for (int ks = 0; ks < 2; ks++) {
            const int cb = ks * 16 + lcol;
            uint32_t ahi[2][4], alo[2][4], bh[4][4], bl[4][4];
            #pragma unroll
            for (int mi = 0; mi < 2; mi++) {
                uint32_t off = ((m0 + mi * 16 + lrow) * ASTR + cb) * 2;
                ldsm_x4(ahi[mi][0], ahi[mi][1], ahi[mi][2], ahi[mi][3], sb + OAH + off);
                ldsm_x4(alo[mi][0], alo[mi][1], alo[mi][2], alo[mi][3], sb + OAL + off);
            }
            #pragma unroll
            for (int nj = 0; nj < 4; nj++) {
                uint32_t off = ((n0w + nj * 16 + lrow) * ASTR + cb) * 2;
                ldsm_x4(bh[nj][0], bh[nj][1], bh[nj][2], bh[nj][3], sb + OBH + off);
                ldsm_x4(bl[nj][0], bl[nj][1], bl[nj][2], bl[nj][3], sb + OBL + off);
            }
            #pragma unroll
            for (int mi = 0; mi < 2; mi++) {
                #pragma unroll
                for (int nj = 0; nj < 4; nj++) {
                    float* d0 = acc[mi][nj * 2];
                    mma_bf16(d0, ahi[mi], bh[nj][0], bh[nj][2]);
                    mma_bf16(d0, ahi[mi], bl[nj][0], bl[nj][2]);
                    mma_bf16(d0, alo[mi], bh[nj][0], bh[nj][2]);
                    float* d1 = acc[mi][nj * 2 + 1];
                    mma_bf16(d1, ahi[mi], bh[nj][1], bh[nj][3]);
                    mma_bf16(d1, ahi[mi], bl[nj][1], bl[nj][3]);
                    mma_bf16(d1, alo[mi], bh[nj][1], bh[nj][3]);
                }
            }
        }

        if (has_next) {
            store_A(stage ^ 1);
            CP_WAIT0();
            __syncthreads();
            stage ^= 1;
        }
    }

    // epilogue: bias + split into bf16 hi/lo
    const int grp = lane >> 2, qid = lane & 3;
    #pragma unroll
    for (int mi = 0; mi < 2; mi++) {
        #pragma unroll
        for (int nj = 0; nj < 8; nj++) {
            int row = blockIdx.y * 128 + m0 + mi * 16 + grp;
            int col = blockIdx.x * 128 + n0w + nj * 8 + qid * 2;
            float b0 = bias[col], b1 = bias[col + 1];
            float v0 = acc[mi][nj][0] + b0, v1 = acc[mi][nj][1] + b1;
            float v2 = acc[mi][nj][2] + b0, v3 = acc[mi][nj][3] + b1;
            __nv_bfloat162 h01 = __floats2bfloat162_rn(v0, v1);
            __nv_bfloat162 h23 = __floats2bfloat162_rn(v2, v3);
            *(uint32_t*)(Chi + (size_t)row * ldc + col) = bits2(h01);
            *(uint32_t*)(Chi + (size_t)(row + 8) * ldc + col) = bits2(h23);
            *(uint32_t*)(Clo + (size_t)row * ldc + col) =
                bits2(__floats2bfloat162_rn(v0 - __bfloat162float(h01.x),
                                            v1 - __bfloat162float(h01.y)));
            *(uint32_t*)(Clo + (size_t)(row + 8) * ldc + col) =
                bits2(__floats2bfloat162_rn(v2 - __bfloat162float(h23.x),
                                            v3 - __bfloat162float(h23.y)));
        }
    }
}

// ============== GEMM variant 2 (K5): A hi only, B hi/lo, 2-stage, occ 2 ========
__global__ __launch_bounds__(256, 2) void hmma_gemm_ab_kernel(
    const __nv_bfloat16* __restrict__ Ahi, size_t strideA,
    const __nv_bfloat16* __restrict__ Bhi, const __nv_bfloat16* __restrict__ Blo,
    size_t strideB,
    float* __restrict__ Cm, int ldc, size_t strideC,
    const float* __restrict__ bias, int K)
{
    extern __shared__ __align__(16) char smd[];
    const uint32_t sbase = smem_to_u32(smd);

    const int tid = threadIdx.x;
    const int wid = tid >> 5, lane = tid & 31;
    const int wm = wid & 3, wn = wid >> 2;
    const int m0 = wm * 32, n0w = wn * 64;

    const __nv_bfloat16* Ahb = Ahi + (size_t)blockIdx.z * strideA + (size_t)(blockIdx.y * 128) * K;
    const __nv_bfloat16* Bhb = Bhi + (size_t)blockIdx.z * strideB + (size_t)(blockIdx.x * 128) * K;
    const __nv_bfloat16* Blb = Blo + (size_t)blockIdx.z * strideB + (size_t)(blockIdx.x * 128) * K;
    float* Cb = Cm + (size_t)blockIdx.z * strideC;

    const int lrow = lane & 15;
    const int lcol = (lane >> 4) * 8;
    const int c0row = tid >> 1, c0seg = (tid & 1) * 2;

    float acc[2][8][4];
    #pragma unroll
    for (int mi = 0; mi < 2; mi++)
        #pragma unroll
        for (int n = 0; n < 8; n++)
            #pragma unroll
            for (int q = 0; q < 4; q++) acc[mi][n][q] = 0.f;

    auto cpasync_all = [&](int kt, int stg) {
        uint32_t dst = sbase + stg * ST5 + c0row * (ASTR * 2) + c0seg * 16;
        const char* sah = (const char*)(Ahb + (size_t)c0row * K + kt) + c0seg * 16;
        const char* sbh = (const char*)(Bhb + (size_t)c0row * K + kt) + c0seg * 16;
        const char* sbl = (const char*)(Blb + (size_t)c0row * K + kt) + c0seg * 16;
        CP_ASYNC16(dst + O5AH, sah); CP_ASYNC16(dst + O5AH + 16, sah + 16);
        CP_ASYNC16(dst + O5BH, sbh); CP_ASYNC16(dst + O5BH + 16, sbh + 16);
        CP_ASYNC16(dst + O5BL, sbl); CP_ASYNC16(dst + O5BL + 16, sbl + 16);
    };

    cpasync_all(0, 0);
    CP_COMMIT();
    CP_WAIT0();
    __syncthreads();

    int stage = 0;
    for (int kt = 0; kt < K; kt += 32) {
        const bool has_next = (kt + 32 < K);
        if (has_next) {
            cpasync_all(kt + 32, stage ^ 1);
            CP_COMMIT();
        }

        const uint32_t sb = sbase + stage * ST5;
        #pragma unroll
        for (int ks = 0; ks < 2; ks++) {
            const int cb = ks * 16 + lcol;
            uint32_t ahi[2][4], bh[4][4], bl[4][4];
            #pragma unroll
            for (int mi = 0; mi < 2; mi++) {
                uint32_t off = ((m0 + mi * 16 + lrow) * ASTR + cb) * 2;
                ldsm_x4(ahi[mi][0], ahi[mi][1], ahi[mi][2], ahi[mi][3], sb + O5AH + off);
            }
            #pragma unroll
            for (int nj = 0; nj < 4; nj++) {
                uint32_t off = ((n0w + nj * 16 + lrow) * ASTR + cb) * 2;
                ldsm_x4(bh[nj][0], bh[nj][1], bh[nj][2], bh[nj][3], sb + O5BH + off);
                ldsm_x4(bl[nj][0], bl[nj][1], bl[nj][2], bl[nj][3], sb + O5BL + off);
            }
            #pragma unroll
            for (int mi = 0; mi < 2; mi++) {
                #pragma unroll
                for (int nj = 0; nj < 4; nj++) {
                    float* d0 = acc[mi][nj * 2];
                    mma_bf16(d0, ahi[mi], bh[nj][0], bh[nj][2]);
                    mma_bf16(d0, ahi[mi], bl[nj][0], bl[nj][2]);
                    float* d1 = acc[mi][nj * 2 + 1];
                    mma_bf16(d1, ahi[mi], bh[nj][1], bh[nj][3]);
                    mma_bf16(d1, ahi[mi], bl[nj][1], bl[nj][3]);
                }
            }
        }

        if (has_next) {
            CP_WAIT0();
            __syncthreads();
            stage ^= 1;
        }
    }

    const int grp = lane >> 2, qid = lane & 3;
    #pragma unroll
    for (int mi = 0; mi < 2; mi++) {
        #pragma unroll
        for (int nj = 0; nj < 8; nj++) {
            int row = blockIdx.y * 128 + m0 + mi * 16 + grp;
            int col = blockIdx.x * 128 + n0w + nj * 8 + qid * 2;
            float b0 = bias[col], b1 = bias[col + 1];
            *(float2*)(Cb + (size_t)row * ldc + col) =
                make_float2(acc[mi][nj][0] + b0, acc[mi][nj][1] + b1);
            *(float2*)(Cb + (size_t)(row + 8) * ldc + col) =
                make_float2(acc[mi][nj][2] + b0, acc[mi][nj][3] + b1);
        }
    }
}

// ---------------- prep: split W_in into transposed bf16 hi/lo ------------------
__global__ __launch_bounds__(256) void split_w_kernel(const float* __restrict__ W)
{
    int idx = blockIdx.x * 256 + threadIdx.x;   // k*256 + n
    int k = idx >> 8, n = idx & 255;
    float v = W[idx];
    __nv_bfloat16 h = __float2bfloat16_rn(v);
    g_Whi[(size_t)n * C_ + k] = h;
    g_Wlo[(size_t)n * C_ + k] = __float2bfloat16_rn(v - __bfloat162float(h));
}

// ---------------- K2: slice weights -> bf16 hi only ----------------------------
__global__ __launch_bounds__(256) void slicew_kernel(
    const float* __restrict__ Wslice, const float* __restrict__ bslice,
    const float* __restrict__ temp)
{
    __shared__ float Ws[D_ * G_];
    __shared__ float bs[G_];
    __shared__ float it[H_];
    int tid = threadIdx.x;
    #pragma unroll
    for (int i = 0; i < 8; i++) Ws[tid + i * 256] = Wslice[tid + i * 256];
    if (tid < G_) bs[tid] = bslice[tid];
    if (tid < H_) it[tid] = 1.f / temp[tid];
    __syncthreads();

    int gid = blockIdx.x * 256 + tid;
    int n = gid >> 3, h = gid & 7;

    float x[D_];
    const uint4* XH = (const uint4*)(g_tmphi + (size_t)n * C_ + h * D_);
    const uint4* XL = (const uint4*)(g_tmplo + (size_t)n * C_ + h * D_);
    #pragma unroll
    for (int i = 0; i < 4; i++) {
        uint4 hv = XH[i], lv = XL[i];
        float2 p0 = upk2(hv.x, lv.x), p1 = upk2(hv.y, lv.y);
        float2 p2 = upk2(hv.z, lv.z), p3 = upk2(hv.w, lv.w);
        x[8*i+0] = p0.x; x[8*i+1] = p0.y; x[8*i+2] = p1.x; x[8*i+3] = p1.y;
        x[8*i+4] = p2.x; x[8*i+5] = p2.y; x[8*i+6] = p3.x; x[8*i+7] = p3.y;
    }

    float2 lg[G_ / 2];
    const float2* bs2 = (const float2*)bs;
    #pragma unroll
    for (int j = 0; j < G_ / 2; j++) lg[j] = bs2[j];

    const float2* Ws2 = (const float2*)Ws;
    for (int d = 0; d < D_; d++) {
        float2 xv = make_float2(x[d], x[d]);
        #pragma unroll
        for (int j = 0; j < G_ / 2; j++) lg[j] = ffma2(xv, Ws2[d * (G_ / 2) + j], lg[j]);
    }

    float sc = it[h];
    float mx = -1e30f;
    #pragma unroll
    for (int j = 0; j < G_ / 2; j++) {
        lg[j].x *= sc; lg[j].y *= sc;
        mx = fmaxf(mx, fmaxf(lg[j].x, lg[j].y));
    }
    float sum = 0.f;
    #pragma unroll
    for (int j = 0; j < G_ / 2; j++) {
        lg[j].x = __expf(lg[j].x - mx);
        lg[j].y = __expf(lg[j].y - mx);
        sum += lg[j].x + lg[j].y;
    }
    float inv = 1.f / sum;

    size_t base = (size_t)n * (H_ * G_) + h * G_;
    uint2* dhi = (uint2*)(g_swhi + base);
    #pragma unroll
    for (int j = 0; j < 16; j++) {
        float v0 = lg[2*j].x * inv, v1 = lg[2*j].y * inv;
        float v2 = lg[2*j+1].x * inv, v3 = lg[2*j+1].y * inv;
        __nv_bfloat162 h01 = __floats2bfloat162_rn(v0, v1);
        __nv_bfloat162 h23 = __floats2bfloat162_rn(v2, v3);
        dhi[j] = make_uint2(bits2(h01), bits2(h23));
    }
}

// ---------------- K3: pooling GEMM (sw hi only; x hi/lo), ping-pong groups -----
#define PG_SWH 0
#define PG_XH  9216
#define PG_XL  14336
#define PG_SIZE 19456
#define P_TOTAL 40960   // max(2*PG_SIZE = 38912, reduce region 4*64*40*4 = 40960)

__global__ __launch_bounds__(256, 1) void pool_mma_kernel()
{
    extern __shared__ __align__(16) char psm[];
    const uint32_t sbm = smem_to_u32(psm);

    const int tid = threadIdx.x, lane = tid & 31, w = tid >> 5;
    const int wg = w >> 2, wl = w & 3;
    const int g_tid = tid & 127;
    const int pc = blockIdx.x, bh = blockIdx.y;
    const int b = bh >> 3, h = bh & 7;
    const uint32_t gb = sbm + wg * PG_SIZE;

    // x pad cols 32-39: ones in hi col 32, zeros elsewhere
    for (int i = tid; i < 128; i += 256) {
        int gg = i >> 6, row = i & 63;
        *(uint4*)(psm + gg * PG_SIZE + PG_XH + row * 80 + 64) =
            make_uint4(0x00003F80u, 0u, 0u, 0u);
        *(uint4*)(psm + gg * PG_SIZE + PG_XL + row * 80 + 64) =
            make_uint4(0u, 0u, 0u, 0u);
    }
    __syncthreads();

    float acc[4][5][4];
    #pragma unroll
    for (int mi = 0; mi < 4; mi++)
        #pragma unroll
        for (int nj = 0; nj < 5; nj++)
            #pragma unroll
            for (int q = 0; q < 4; q++) acc[mi][nj][q] = 0.f;

    const int cb = wl * 16;
    const int trow = cb + ((lane >> 4) << 3) + (lane & 7);
    const int tcol8 = ((lane >> 3) & 1) << 3;
    const int r2 = cb + (((lane >> 3) & 1) << 3) + (lane & 7);

    for (int it = 0; it < 4; it++) {
        int sc = 2 * it + wg;
        size_t gn = (size_t)b * T_ + pc * 512 + (size_t)sc * 64;

        #pragma unroll
        for (int i = 0; i < 4; i++) {
            int c = g_tid + i * 128;
            int row = c >> 3, seg = c & 7;
            const char* sh = (const char*)(g_swhi + (gn + row) * (H_ * G_) + h * G_) + seg * 16;
            CP_ASYNC16(gb + PG_SWH + row * 144 + seg * 16, sh);
        }
        #pragma unroll
        for (int i = 0; i < 2; i++) {
            int c = g_tid + i * 128;
            int row = c >> 2, seg = c & 3;
            const char* xh = (const char*)(g_tmphi + (gn + row) * C_ + h * D_) + seg * 16;
            const char* xl = (const char*)(g_tmplo + (gn + row) * C_ + h * D_) + seg * 16;
            CP_ASYNC16(gb + PG_XH + row * 80 + seg * 16, xh);
            CP_ASYNC16(gb + PG_XL + row * 80 + seg * 16, xl);
        }
        CP_COMMIT();
        CP_WAIT0();
        asm volatile("bar.sync %0, 128;" :: "r"(wg + 1) : "memory");

        uint32_t bxh[2][4], bxl[2][4], b2h[2], b2l[2];
        #pragma unroll
        for (int t = 0; t < 2; t++) {
            uint32_t off = (trow * 40 + t * 16 + tcol8) * 2;
            ldsm_x4_t(bxh[t][0], bxh[t][1], bxh[t][2], bxh[t][3], gb + PG_XH + off);
            ldsm_x4_t(bxl[t][0], bxl[t][1], bxl[t][2], bxl[t][3], gb + PG_XL + off);
        }
        {
            uint32_t off = (r2 * 40 + 32) * 2;
            ldsm_x2_t(b2h[0], b2h[1], gb + PG_XH + off);
            ldsm_x2_t(b2l[0], b2l[1], gb + PG_XL + off);
        }

        #pragma unroll
        for (int mi = 0; mi < 4; mi++) {
            uint32_t ah[4];
            uint32_t off = (trow * 72 + mi * 16 + tcol8) * 2;
            ldsm_x4_t(ah[0], ah[1], ah[2], ah[3], gb + PG_SWH + off);
            #pragma unroll
            for (int nj = 0; nj < 5; nj++) {
                uint32_t b0h, b1h, b0l, b1l;
                if (nj < 4) {
                    int t = nj >> 1, p = nj & 1;
                    b0h = bxh[t][p]; b1h = bxh[t][p + 2];
                    b0l = bxl[t][p]; b1l = bxl[t][p + 2];
                } else {
                    b0h = b2h[0]; b1h = b2h[1];
                    b0l = b2l[0]; b1l = b2l[1];
                }
                float* d = acc[mi][nj];
                mma_bf16(d, ah, b0h, b1h);
                mma_bf16(d, ah, b0l, b1l);
            }
        }
        asm volatile("bar.sync %0, 128;" :: "r"(wg + 1) : "memory");
    }

    __syncthreads();
    float* red = (float*)psm;    // [4 slots][64 g][40] = 40960 B (fits P_TOTAL)
    const int grp = lane >> 2, qid = lane & 3;
    if (wg == 0) {
        #pragma unroll
        for (int mi = 0; mi < 4; mi++)
            #pragma unroll
            for (int nj = 0; nj < 5; nj++) {
                int g0 = mi * 16 + grp, nn = nj * 8 + qid * 2;
                red[(wl * 64 + g0) * 40 + nn]         = acc[mi][nj][0];
                red[(wl * 64 + g0) * 40 + nn + 1]     = acc[mi][nj][1];
                red[(wl * 64 + g0 + 8) * 40 + nn]     = acc[mi][nj][2];
                red[(wl * 64 + g0 + 8) * 40 + nn + 1] = acc[mi][nj][3];
            }
    }
    __syncthreads();
    if (wg == 1) {
        #pragma unroll
        for (int mi = 0; mi < 4; mi++)
            #pragma unroll
            for (int nj = 0; nj < 5; nj++) {
                int g0 = mi * 16 + grp, nn = nj * 8 + qid * 2;
                red[(wl * 64 + g0) * 40 + nn]         += acc[mi][nj][0];
                red[(wl * 64 + g0) * 40 + nn + 1]     += acc[mi][nj][1];
                red[(wl * 64 + g0 + 8) * 40 + nn]     += acc[mi][nj][2];
                red[(wl * 64 + g0 + 8) * 40 + nn + 1] += acc[mi][nj][3];
            }
    }
    __syncthreads();

    for (int i = tid; i < 64 * 33; i += 256) {
        int g = i / 33, s = i - g * 33;
        float sum = red[g * 40 + s] + red[(64 + g) * 40 + s]
                  + red[(128 + g) * 40 + s] + red[(192 + g) * 40 + s];
        if (s < 32) g_part[((size_t)bh * NCH2 + pc) * (G_ * D_) + g * D_ + s] = sum;
        else        g_pnorm[((size_t)bh * NCH2 + pc) * G_ + g] = sum;
    }
}

// ------- K4a: reduce partials -> tokens -> qkv -> GxG attention -> g_os --------
__global__ __launch_bounds__(256) void attn_tiny_kernel(
    const float* __restrict__ Wq, const float* __restrict__ bq,
    const float* __restrict__ Wk, const float* __restrict__ bk,
    const float* __restrict__ Wv, const float* __restrict__ bv)
{
    __shared__ float tok[G_][D_ + 1];
    __shared__ float qs[G_][D_ + 1];
    __shared__ float ks[G_][D_ + 1];
    __shared__ float vs[G_][D_ + 1];
    __shared__ float norms[G_];

    int bh = blockIdx.x;
    int tid = threadIdx.x;

    if (tid < G_) {
        float s = 0.f;
        for (int ch = 0; ch < NCH2; ch++)
            s += g_pnorm[((size_t)bh * NCH2 + ch) * G_ + tid];
        norms[tid] = s + 1e-5f;
    }
    __syncthreads();

    #pragma unroll
    for (int i = 0; i < 8; i++) {
        int c = tid + i * 256;
        int g = c >> 5, d = c & 31;
        float s = 0.f;
        for (int ch = 0; ch < NCH2; ch++)
            s += g_part[((size_t)bh * NCH2 + ch) * (G_ * D_) + c];
        tok[g][d] = s / norms[g];
    }
    __syncthreads();

    #pragma unroll
    for (int i = 0; i < 8; i++) {
        int c = tid + i * 256;
        int g = c >> 5, d = c & 31;
        float aq = bq[d], ak = bk[d], av = bv[d];
        for (int e = 0; e < D_; e++) {
            float t = tok[g][e];
            aq += t * Wq[e * D_ + d];
            ak += t * Wk[e * D_ + d];
            av += t * Wv[e * D_ + d];
        }
        qs[g][d] = aq; ks[g][d] = ak; vs[g][d] = av;
    }
    __syncthreads();

    if (tid < G_) {
        float qr[D_];
        #pragma unroll
        for (int d = 0; d < D_; d++) qr[d] = qs[tid][d];
        float s[G_];
        float mx = -1e30f;
        #pragma unroll
        for (int j = 0; j < G_; j++) {
            float a = 0.f;
            #pragma unroll
            for (int d = 0; d < D_; d++) a += qr[d] * ks[j][d];
            a *= 0.17677669529663687f;
            s[j] = a; mx = fmaxf(mx, a);
        }
        float sum = 0.f;
        #pragma unroll
        for (int j = 0; j < G_; j++) { s[j] = __expf(s[j] - mx); sum += s[j]; }
        float inv = 1.f / sum;
        #pragma unroll
        for (int d = 0; d < D_; d++) {
            float a = 0.f;
            #pragma unroll
            for (int j = 0; j < G_; j++) a += s[j] * vs[j][d];
            g_os[(size_t)bh * (G_ * D_) + tid * D_ + d] = a * inv;
        }
    }
}

// ------- K4b: fold into transposed bf16 hi/lo M --------------------------------
__global__ __launch_bounds__(256) void fold_kernel(const float* __restrict__ Wout)
{
    __shared__ float os[G_][D_ + 1];
    __shared__ float Wt[D_][G_ + 1];
    int bh = blockIdx.y;
    int b = bh >> 3, h = bh & 7;
    int col0 = blockIdx.x * 64;
    int tid = threadIdx.x;

    #pragma unroll
    for (int i = 0; i < 8; i++) {
        int idx = tid + i * 256;
        os[idx >> 5][idx & 31] = g_os[(size_t)bh * (G_ * D_) + idx];
    }
    #pragma unroll
    for (int i = 0; i < 8; i++) {
        int idx = tid + i * 256;
        int d = idx >> 6, c = idx & 63;
        Wt[d][c] = Wout[(size_t)(h * D_ + d) * C_ + col0 + c];
    }
    __syncthreads();

    int c = tid & 63, g0 = tid >> 6;
    #pragma unroll
    for (int gi = 0; gi < 16; gi++) {
        int g = g0 * 16 + gi;
        float a = 0.f;
        #pragma unroll
        for (int d = 0; d < D_; d++) a += os[g][d] * Wt[d][c];
        __nv_bfloat16 hb = __float2bfloat16_rn(a);
        size_t o = ((size_t)b * C_ + col0 + c) * (size_t)(H_ * G_) + h * G_ + g;
        g_Mhi[o] = hb;
        g_Mlo[o] = __float2bfloat16_rn(a - __bfloat162float(hb));
    }
}

// ---------------- launch --------------------------------------------------------
extern "C" void kernel_launch(void* const* d_in, const int* in_sizes, int n_in,
                              void* d_out, int out_size)
{
    const float* x_q    = (const float*)d_in[0];
    const float* W_in   = (const float*)d_in[3];
    const float* b_in   = (const float*)d_in[4];
    const float* W_sl   = (const float*)d_in[5];
    const float* b_sl   = (const float*)d_in[6];
    const float* temp   = (const float*)d_in[7];
    const float* W_q    = (const float*)d_in[8];
    const float* b_q    = (const float*)d_in[9];
    const float* W_k    = (const float*)d_in[10];
    const float* b_k    = (const float*)d_in[11];
    const float* W_v    = (const float*)d_in[12];
    const float* b_v    = (const float*)d_in[13];
    const float* W_out  = (const float*)d_in[14];
    const float* b_out  = (const float*)d_in[15];
    float* out = (float*)d_out;

    __nv_bfloat16 *thi_p, *tlo_p, *whi_p, *wlo_p, *mhi_p, *mlo_p, *shi_p;
    cudaGetSymbolAddress((void**)&thi_p, g_tmphi);
    cudaGetSymbolAddress((void**)&tlo_p, g_tmplo);
    cudaGetSymbolAddress((void**)&whi_p, g_Whi);
    cudaGetSymbolAddress((void**)&wlo_p, g_Wlo);
    cudaGetSymbolAddress((void**)&mhi_p, g_Mhi);
    cudaGetSymbolAddress((void**)&mlo_p, g_Mlo);
    cudaGetSymbolAddress((void**)&shi_p, g_swhi);

    static int smem_set = 0;
    if (!smem_set) {
        cudaFuncSetAttribute(hmma_gemm_k1_kernel,
                             cudaFuncAttributeMaxDynamicSharedMemorySize, K1_SMEM);
        cudaFuncSetAttribute(hmma_gemm_ab_kernel,
                             cudaFuncAttributeMaxDynamicSharedMemorySize, AB_SMEM);
        cudaFuncSetAttribute(pool_mma_kernel,
                             cudaFuncAttributeMaxDynamicSharedMemorySize, P_TOTAL);
        smem_set = 1;
    }

    // prep: split W_in
    split_w_kernel<<<C_ * C_ / 256, 256>>>(W_in);

    // K1: tmp = x_q @ W_in + b_in  -> bf16 hi/lo (full 3-product accuracy)
    hmma_gemm_k1_kernel<<<dim3(C_/128, N_/128), 256, K1_SMEM>>>(
        x_q, C_, whi_p, wlo_p, thi_p, tlo_p, C_, b_in, C_);

    // K2: slice softmax -> bf16 hi only
    slicew_kernel<<<(N_ * H_) / 256, 256>>>(W_sl, b_sl, temp);

    // K3: pooling GEMM (sw hi x [x hi + x lo])
    pool_mma_kernel<<<dim3(NCH2, B_ * H_), 256, P_TOTAL>>>();

    // K4a: reduce + tiny attention
    attn_tiny_kernel<<<B_ * H_, 256>>>(W_q, b_q, W_k, b_k, W_v, b_v);

    // K4b: fold W_out into pre-split M (hi/lo kept for accuracy)
    fold_kernel<<<dim3(4, B_ * H_), 256>>>(W_out);

    // K5: out[b] = SWhi[b] @ (Mhi + Mlo)[b] + b_out  (occ 2, 2-stage)
    hmma_gemm_ab_kernel<<<dim3(C_/128, T_/128, B_), 256, AB_SMEM>>>(
        shi_p, (size_t)T_ * (H_ * G_),
        mhi_p, mlo_p, (size_t)C_ * (H_ * G_),
        out, C_, (size_t)T_ * C_,
        b_out, H_ * G_);
}

// round 13
// speedup vs baseline: 1.2610x; 1.0041x over previous
#include <cuda_runtime.h>
#include <cuda_bf16.h>
#include <cstdint>
#include <math.h>

// Problem constants
#define B_ 8
#define T_ 8192
#define C_ 256
#define H_ 8
#define G_ 64
#define D_ 32
#define N_ (B_*T_)
#define NCH2 16
#define ASTR 40   // GEMM smem row stride (80B, conflict-free for ldmatrix)

// ---------------- scratch ------------------------------------------------------
__device__ __nv_bfloat16 g_tmphi[(size_t)N_ * C_];
__device__ __nv_bfloat16 g_tmplo[(size_t)N_ * C_];
__device__ __nv_bfloat16 g_swhi[(size_t)N_ * H_ * G_];
__device__ float g_part[(size_t)B_ * H_ * NCH2 * G_ * D_];
__device__ float g_pnorm[(size_t)B_ * H_ * NCH2 * G_];
__device__ float g_os[(size_t)B_ * H_ * G_ * D_];
__device__ __nv_bfloat16 g_Whi[(size_t)C_ * C_];
__device__ __nv_bfloat16 g_Wlo[(size_t)C_ * C_];
__device__ __nv_bfloat16 g_Mhi[(size_t)B_ * C_ * (H_ * G_)];
__device__ __nv_bfloat16 g_Mlo[(size_t)B_ * C_ * (H_ * G_)];

// ---------------- small helpers ------------------------------------------------
__device__ __forceinline__ float2 ffma2(float2 a, float2 b, float2 c) {
    float2 d;
    asm("fma.rn.f32x2 %0, %1, %2, %3;"
        : "=l"(reinterpret_cast<unsigned long long&>(d))
        : "l"(reinterpret_cast<unsigned long long&>(a)),
          "l"(reinterpret_cast<unsigned long long&>(b)),
          "l"(reinterpret_cast<unsigned long long&>(c)));
    return d;
}
__device__ __forceinline__ uint32_t smem_to_u32(const void* p) {
    uint32_t a;
    asm("{ .reg .u64 t; cvta.to.shared.u64 t, %1; cvt.u32.u64 %0, t; }" : "=r"(a) : "l"(p));
    return a;
}
__device__ __forceinline__ void ldsm_x4(uint32_t& r0, uint32_t& r1, uint32_t& r2, uint32_t& r3,
                                        uint32_t addr) {
    asm volatile("ldmatrix.sync.aligned.m8n8.x4.shared.b16 {%0,%1,%2,%3}, [%4];"
                 : "=r"(r0), "=r"(r1), "=r"(r2), "=r"(r3) : "r"(addr));
}
__device__ __forceinline__ void ldsm_x4_t(uint32_t& r0, uint32_t& r1, uint32_t& r2, uint32_t& r3,
                                          uint32_t addr) {
    asm volatile("ldmatrix.sync.aligned.m8n8.x4.trans.shared.b16 {%0,%1,%2,%3}, [%4];"
                 : "=r"(r0), "=r"(r1), "=r"(r2), "=r"(r3) : "r"(addr));
}
__device__ __forceinline__ void mma_bf16(float* d, const uint32_t* a, uint32_t b0, uint32_t b1) {
    asm volatile("mma.sync.aligned.m16n8k16.row.col.f32.bf16.bf16.f32 "
        "{%0,%1,%2,%3}, {%4,%5,%6,%7}, {%8,%9}, {%0,%1,%2,%3};"
        : "+f"(d[0]), "+f"(d[1]), "+f"(d[2]), "+f"(d[3])
        : "r"(a[0]), "r"(a[1]), "r"(a[2]), "r"(a[3]), "r"(b0), "r"(b1));
}
__device__ __forceinline__ uint32_t bits2(__nv_bfloat162 h) {
    return *reinterpret_cast<uint32_t*>(&h);
}
__device__ __forceinline__ float2 upk2(uint32_t hu, uint32_t lu) {
    __nv_bfloat162 hh = *reinterpret_cast<__nv_bfloat162*>(&hu);
    __nv_bfloat162 ll = *reinterpret_cast<__nv_bfloat162*>(&lu);
    return make_float2(__bfloat162float(hh.x) + __bfloat162float(ll.x),
                       __bfloat162float(hh.y) + __bfloat162float(ll.y));
}
#define CP_ASYNC16(dst, src) \
    asm volatile("cp.async.cg.shared.global [%0], [%1], 16;" :: "r"(dst), "l"(src))
#define CP_COMMIT() asm volatile("cp.async.commit_group;" ::: "memory")
#define CP_WAIT0()  asm volatile("cp.async.wait_group 0;" ::: "memory")

#define STG_BYTES (128 * ASTR * 2)           // 10240 B per operand buffer

// ---- K1 stage layout (A hi/lo + B hi/lo) ----
#define STAGE_BYTES (4 * STG_BYTES)          // 40960
#define K1_SMEM (2 * STAGE_BYTES)            // 81920
#define OAH 0
#define OAL STG_BYTES
#define OBH (2 * STG_BYTES)
#define OBL (3 * STG_BYTES)

// ---- K5 stage layout (A hi + B hi/lo) ----
#define ST5 (3 * STG_BYTES)                  // 30720
#define AB_SMEM (2 * ST5)                    // 61440 (occ 2)
#define O5AH 0
#define O5BH STG_BYTES
#define O5BL (2 * STG_BYTES)

// ============== GEMM variant 1 (K1): A fp32 in, bf16 hi/lo out =================
__global__ __launch_bounds__(256, 1) void hmma_gemm_k1_kernel(
    const float* __restrict__ A, int lda,
    const __nv_bfloat16* __restrict__ Bhi, const __nv_bfloat16* __restrict__ Blo,
    __nv_bfloat16* __restrict__ Chi, __nv_bfloat16* __restrict__ Clo, int ldc,
    const float* __restrict__ bias, int K)
{
    extern __shared__ __align__(16) char smd[];
    const uint32_t sbase = smem_to_u32(smd);

    const int tid = threadIdx.x;
    const int wid = tid >> 5, lane = tid & 31;
    const int wm = wid & 3, wn = wid >> 2;
    const int m0 = wm * 32, n0w = wn * 64;

    const float* Ab = A + (size_t)blockIdx.y * 128 * lda;
    const __nv_bfloat16* Bhb = Bhi + (size_t)(blockIdx.x * 128) * K;
    const __nv_bfloat16* Blb = Blo + (size_t)(blockIdx.x * 128) * K;

    const int lrow = lane & 15;
    const int lcol = (lane >> 4) * 8;
    const int arow = tid >> 1;
    const int akh  = (tid & 1) << 4;
    const int c0row = tid >> 1, c0seg = (tid & 1) * 2;

    float acc[2][8][4];
    #pragma unroll
    for (int mi = 0; mi < 2; mi++)
        #pragma unroll
        for (int n = 0; n < 8; n++)
            #pragma unroll
            for (int q = 0; q < 4; q++) acc[mi][n][q] = 0.f;

    float fst[16];

    auto load_A_regs = [&](int kt) {
        const float* ap = Ab + (size_t)arow * lda + kt + akh;
        *(float4*)(fst + 0)  = *(const float4*)(ap);
        *(float4*)(fst + 4)  = *(const float4*)(ap + 4);
        *(float4*)(fst + 8)  = *(const float4*)(ap + 8);
        *(float4*)(fst + 12) = *(const float4*)(ap + 12);
    };
    auto cpasync_B = [&](int kt, int stg) {
        uint32_t dst = sbase + stg * STAGE_BYTES + c0row * (ASTR * 2) + c0seg * 16;
        const char* srch = (const char*)(Bhb + (size_t)c0row * K + kt) + c0seg * 16;
        const char* srcl = (const char*)(Blb + (size_t)c0row * K + kt) + c0seg * 16;
        CP_ASYNC16(dst + OBH, srch);
        CP_ASYNC16(dst + OBH + 16, srch + 16);
        CP_ASYNC16(dst + OBL, srcl);
        CP_ASYNC16(dst + OBL + 16, srcl + 16);
    };
    auto store_A = [&](int stg) {
        uint32_t h[8], l[8];
        #pragma unroll
        for (int i = 0; i < 8; i++) {
            __nv_bfloat162 hb = __floats2bfloat162_rn(fst[2*i], fst[2*i+1]);
            float r0 = fst[2*i]   - __bfloat162float(hb.x);
            float r1 = fst[2*i+1] - __bfloat162float(hb.y);
            h[i] = bits2(hb);
            l[i] = bits2(__floats2bfloat162_rn(r0, r1));
        }
        char* dh = smd + stg * STAGE_BYTES + OAH + arow * (ASTR * 2) + akh * 2;
        char* dl = smd + stg * STAGE_BYTES + OAL + arow * (ASTR * 2) + akh * 2;
        ((uint4*)dh)[0] = make_uint4(h[0], h[1], h[2], h[3]);
        ((uint4*)dh)[1] = make_uint4(h[4], h[5], h[6], h[7]);
        ((uint4*)dl)[0] = make_uint4(l[0], l[1], l[2], l[3]);
        ((uint4*)dl)[1] = make_uint4(l[4], l[5], l[6], l[7]);
    };

    load_A_regs(0);
    cpasync_B(0, 0);
    CP_COMMIT();
    store_A(0);
    CP_WAIT0();
    __syncthreads();

    int stage = 0;
    for (int kt = 0; kt < K; kt += 32) {
        const bool has_next = (kt + 32 < K);
        if (has_next) {
            load_A_regs(kt + 32);
            cpasync_B(kt + 32, stage ^ 1);
            CP_COMMIT();
        }

        const uint32_t sb = sbase + stage * STAGE_BYTES;
        #pragma unroll
        for (int ks = 0; ks < 2; ks++) {
            const int cb = ks * 16 + lcol;
            uint32_t ahi[2][4], alo[2][4], bh[4][4], bl[4][4];
            #pragma unroll
            for (int mi = 0; mi < 2; mi++) {
                uint32_t off = ((m0 + mi * 16 + lrow) * ASTR + cb) * 2;
                ldsm_x4(ahi[mi][0], ahi[mi][1], ahi[mi][2], ahi[mi][3], sb + OAH + off);
                ldsm_x4(alo[mi][0], alo[mi][1], alo[mi][2], alo[mi][3], sb + OAL + off);
            }
            #pragma unroll
            for (int nj = 0; nj < 4; nj++) {
                uint32_t off = ((n0w + nj * 16 + lrow) * ASTR + cb) * 2;
                ldsm_x4(bh[nj][0], bh[nj][1], bh[nj][2], bh[nj][3], sb + OBH + off);
                ldsm_x4(bl[nj][0], bl[nj][1], bl[nj][2], bl[nj][3], sb + OBL + off);
            }
            #pragma unroll
            for (int mi = 0; mi < 2; mi++) {
                #pragma unroll
                for (int nj = 0; nj < 4; nj++) {
                    float* d0 = acc[mi][nj * 2];
                    mma_bf16(d0, ahi[mi], bh[nj][0], bh[nj][2]);
                    mma_bf16(d0, ahi[mi], bl[nj][0], bl[nj][2]);
                    mma_bf16(d0, alo[mi], bh[nj][0], bh[nj][2]);
                    float* d1 = acc[mi][nj * 2 + 1];
                    mma_bf16(d1, ahi[mi], bh[nj][1], bh[nj][3]);
                    mma_bf16(d1, ahi[mi], bl[nj][1], bl[nj][3]);
                    mma_bf16(d1, alo[mi], bh[nj][1], bh[nj][3]);
                }
            }
        }

        if (has_next) {
            store_A(stage ^ 1);
            CP_WAIT0();
            __syncthreads();
            stage ^= 1;
        }
    }

    // epilogue: bias + split into bf16 hi/lo
    const int grp = lane >> 2, qid = lane & 3;
    #pragma unroll
    for (int mi = 0; mi < 2; mi++) {
        #pragma unroll
        for (int nj = 0; nj < 8; nj++) {
            int row = blockIdx.y * 128 + m0 + mi * 16 + grp;
            int col = blockIdx.x * 128 + n0w + nj * 8 + qid * 2;
            float b0 = bias[col], b1 = bias[col + 1];
            float v0 = acc[mi][nj][0] + b0, v1 = acc[mi][nj][1] + b1;
            float v2 = acc[mi][nj][2] + b0, v3 = acc[mi][nj][3] + b1;
            __nv_bfloat162 h01 = __floats2bfloat162_rn(v0, v1);
            __nv_bfloat162 h23 = __floats2bfloat162_rn(v2, v3);
            *(uint32_t*)(Chi + (size_t)row * ldc + col) = bits2(h01);
            *(uint32_t*)(Chi + (size_t)(row + 8) * ldc + col) = bits2(h23);
            *(uint32_t*)(Clo + (size_t)row * ldc + col) =
                bits2(__floats2bfloat162_rn(v0 - __bfloat162float(h01.x),
                                            v1 - __bfloat162float(h01.y)));
            *(uint32_t*)(Clo + (size_t)(row + 8) * ldc + col) =
                bits2(__floats2bfloat162_rn(v2 - __bfloat162float(h23.x),
                                            v3 - __bfloat162float(h23.y)));
        }
    }
}

// ============== GEMM variant 2 (K5): A hi only, B hi/lo, 2-stage, occ 2 ========
__global__ __launch_bounds__(256, 2) void hmma_gemm_ab_kernel(
    const __nv_bfloat16* __restrict__ Ahi, size_t strideA,
    const __nv_bfloat16* __restrict__ Bhi, const __nv_bfloat16* __restrict__ Blo,
    size_t strideB,
    float* __restrict__ Cm, int ldc, size_t strideC,
    const float* __restrict__ bias, int K)
{
    extern __shared__ __align__(16) char smd[];
    const uint32_t sbase = smem_to_u32(smd);

    const int tid = threadIdx.x;
    const int wid = tid >> 5, lane = tid & 31;
    const int wm = wid & 3, wn = wid >> 2;
    const int m0 = wm * 32, n0w = wn * 64;

    const __nv_bfloat16* Ahb = Ahi + (size_t)blockIdx.z * strideA + (size_t)(blockIdx.y * 128) * K;
    const __nv_bfloat16* Bhb = Bhi + (size_t)blockIdx.z * strideB + (size_t)(blockIdx.x * 128) * K;
    const __nv_bfloat16* Blb = Blo + (size_t)blockIdx.z * strideB + (size_t)(blockIdx.x * 128) * K;
    float* Cb = Cm + (size_t)blockIdx.z * strideC;

    const int lrow = lane & 15;
    const int lcol = (lane >> 4) * 8;
    const int c0row = tid >> 1, c0seg = (tid & 1) * 2;

    float acc[2][8][4];
    #pragma unroll
    for (int mi = 0; mi < 2; mi++)
        #pragma unroll
        for (int n = 0; n < 8; n++)
            #pragma unroll
            for (int q = 0; q < 4; q++) acc[mi][n][q] = 0.f;

    auto cpasync_all = [&](int kt, int stg) {
        uint32_t dst = sbase + stg * ST5 + c0row * (ASTR * 2) + c0seg * 16;
        const char* sah = (const char*)(Ahb + (size_t)c0row * K + kt) + c0seg * 16;
        const char* sbh = (const char*)(Bhb + (size_t)c0row * K + kt) + c0seg * 16;
        const char* sbl = (const char*)(Blb + (size_t)c0row * K + kt) + c0seg * 16;
        CP_ASYNC16(dst + O5AH, sah); CP_ASYNC16(dst + O5AH + 16, sah + 16);
        CP_ASYNC16(dst + O5BH, sbh); CP_ASYNC16(dst + O5BH + 16, sbh + 16);
        CP_ASYNC16(dst + O5BL, sbl); CP_ASYNC16(dst + O5BL + 16, sbl + 16);
    };

    cpasync_all(0, 0);
    CP_COMMIT();
    CP_WAIT0();
    __syncthreads();

    int stage = 0;
    for (int kt = 0; kt < K; kt += 32) {
        const bool has_next = (kt + 32 < K);
        if (has_next) {
            cpasync_all(kt + 32, stage ^ 1);
            CP_COMMIT();
        }

        const uint32_t sb = sbase + stage * ST5;
        #pragma unroll
        for (int ks = 0; ks < 2; ks++) {
            const int cb = ks * 16 + lcol;
            uint32_t ahi[2][4], bh[4][4], bl[4][4];
            #pragma unroll
            for (int mi = 0; mi < 2; mi++) {
                uint32_t off = ((m0 + mi * 16 + lrow) * ASTR + cb) * 2;
                ldsm_x4(ahi[mi][0], ahi[mi][1], ahi[mi][2], ahi[mi][3], sb + O5AH + off);
            }
            #pragma unroll
            for (int nj = 0; nj < 4; nj++) {
                uint32_t off = ((n0w + nj * 16 + lrow) * ASTR + cb) * 2;
                ldsm_x4(bh[nj][0], bh[nj][1], bh[nj][2], bh[nj][3], sb + O5BH + off);
                ldsm_x4(bl[nj][0], bl[nj][1], bl[nj][2], bl[nj][3], sb + O5BL + off);
            }
            #pragma unroll
            for (int mi = 0; mi < 2; mi++) {
                #pragma unroll
                for (int nj = 0; nj < 4; nj++) {
                    float* d0 = acc[mi][nj * 2];
                    mma_bf16(d0, ahi[mi], bh[nj][0], bh[nj][2]);
                    mma_bf16(d0, ahi[mi], bl[nj][0], bl[nj][2]);
                    float* d1 = acc[mi][nj * 2 + 1];
                    mma_bf16(d1, ahi[mi], bh[nj][1], bh[nj][3]);
                    mma_bf16(d1, ahi[mi], bl[nj][1], bl[nj][3]);
                }
            }
        }

        if (has_next) {
            CP_WAIT0();
            __syncthreads();
            stage ^= 1;
        }
    }

    const int grp = lane >> 2, qid = lane & 3;
    #pragma unroll
    for (int mi = 0; mi < 2; mi++) {
        #pragma unroll
        for (int nj = 0; nj < 8; nj++) {
            int row = blockIdx.y * 128 + m0 + mi * 16 + grp;
            int col = blockIdx.x * 128 + n0w + nj * 8 + qid * 2;
            float b0 = bias[col], b1 = bias[col + 1];
            *(float2*)(Cb + (size_t)row * ldc + col) =
                make_float2(acc[mi][nj][0] + b0, acc[mi][nj][1] + b1);
            *(float2*)(Cb + (size_t)(row + 8) * ldc + col) =
                make_float2(acc[mi][nj][2] + b0, acc[mi][nj][3] + b1);
        }
    }
}

// ---------------- prep: split W_in into transposed bf16 hi/lo ------------------
__global__ __launch_bounds__(256) void split_w_kernel(const float* __restrict__ W)
{
    int idx = blockIdx.x * 256 + threadIdx.x;   // k*256 + n
    int k = idx >> 8, n = idx & 255;
    float v = W[idx];
    __nv_bfloat16 h = __float2bfloat16_rn(v);
    g_Whi[(size_t)n * C_ + k] = h;
    g_Wlo[(size_t)n * C_ + k] = __float2bfloat16_rn(v - __bfloat162float(h));
}

// ---------------- K2: slice weights -> bf16 hi only ----------------------------
__global__ __launch_bounds__(256) void slicew_kernel(
    const float* __restrict__ Wslice, const float* __restrict__ bslice,
    const float* __restrict__ temp)
{
    __shared__ float Ws[D_ * G_];
    __shared__ float bs[G_];
    __shared__ float it[H_];
    int tid = threadIdx.x;
    #pragma unroll
    for (int i = 0; i < 8; i++) Ws[tid + i * 256] = Wslice[tid + i * 256];
    if (tid < G_) bs[tid] = bslice[tid];
    if (tid < H_) it[tid] = 1.f / temp[tid];
    __syncthreads();

    int gid = blockIdx.x * 256 + tid;
    int n = gid >> 3, h = gid & 7;

    float x[D_];
    const uint4* XH = (const uint4*)(g_tmphi + (size_t)n * C_ + h * D_);
    const uint4* XL = (const uint4*)(g_tmplo + (size_t)n * C_ + h * D_);
    #pragma unroll
    for (int i = 0; i < 4; i++) {
        uint4 hv = XH[i], lv = XL[i];
        float2 p0 = upk2(hv.x, lv.x), p1 = upk2(hv.y, lv.y);
        float2 p2 = upk2(hv.z, lv.z), p3 = upk2(hv.w, lv.w);
        x[8*i+0] = p0.x; x[8*i+1] = p0.y; x[8*i+2] = p1.x; x[8*i+3] = p1.y;
        x[8*i+4] = p2.x; x[8*i+5] = p2.y; x[8*i+6] = p3.x; x[8*i+7] = p3.y;
    }

    float2 lg[G_ / 2];
    const float2* bs2 = (const float2*)bs;
    #pragma unroll
    for (int j = 0; j < G_ / 2; j++) lg[j] = bs2[j];

    const float2* Ws2 = (const float2*)Ws;
    for (int d = 0; d < D_; d++) {
        float2 xv = make_float2(x[d], x[d]);
        #pragma unroll
        for (int j = 0; j < G_ / 2; j++) lg[j] = ffma2(xv, Ws2[d * (G_ / 2) + j], lg[j]);
    }

    float sc = it[h];
    float mx = -1e30f;
    #pragma unroll
    for (int j = 0; j < G_ / 2; j++) {
        lg[j].x *= sc; lg[j].y *= sc;
        mx = fmaxf(mx, fmaxf(lg[j].x, lg[j].y));
    }
    float sum = 0.f;
    #pragma unroll
    for (int j = 0; j < G_ / 2; j++) {
        lg[j].x = __expf(lg[j].x - mx);
        lg[j].y = __expf(lg[j].y - mx);
        sum += lg[j].x + lg[j].y;
    }
    float inv = 1.f / sum;

    size_t base = (size_t)n * (H_ * G_) + h * G_;
    uint2* dhi = (uint2*)(g_swhi + base);
    #pragma unroll
    for (int j = 0; j < 16; j++) {
        float v0 = lg[2*j].x * inv, v1 = lg[2*j].y * inv;
        float v2 = lg[2*j+1].x * inv, v3 = lg[2*j+1].y * inv;
        dhi[j] = make_uint2(bits2(__floats2bfloat162_rn(v0, v1)),
                            bits2(__floats2bfloat162_rn(v2, v3)));
    }
}

// ---------------- K3: pooling GEMM (sw hi; x hi/lo), const-ones norm -----------
#define PG_SWH 0
#define PG_XH  9216
#define PG_XL  14336
#define PG_SIZE 19456
#define P_TOTAL 40960   // max(2*PG_SIZE = 38912, reduce region 4*64*40*4 = 40960)

__global__ __launch_bounds__(256, 1) void pool_mma_kernel()
{
    extern __shared__ __align__(16) char psm[];
    const uint32_t sbm = smem_to_u32(psm);

    const int tid = threadIdx.x, lane = tid & 31, w = tid >> 5;
    const int wg = w >> 2, wl = w & 3;
    const int g_tid = tid & 127;
    const int pc = blockIdx.x, bh = blockIdx.y;
    const int b = bh >> 3, h = bh & 7;
    const uint32_t gb = sbm + wg * PG_SIZE;

    float acc[4][5][4];
    #pragma unroll
    for (int mi = 0; mi < 4; mi++)
        #pragma unroll
        for (int nj = 0; nj < 5; nj++)
            #pragma unroll
            for (int q = 0; q < 4; q++) acc[mi][nj][q] = 0.f;

    const int cb = wl * 16;
    const int trow = cb + ((lane >> 4) << 3) + (lane & 7);
    const int tcol8 = ((lane >> 3) & 1) << 3;
    // constant B fragment for the ones-column (norm): B[k][n]=1 iff n==0
    const uint32_t onesf = ((lane >> 2) == 0) ? 0x3F803F80u : 0u;

    for (int it = 0; it < 4; it++) {
        int sc = 2 * it + wg;
        size_t gn = (size_t)b * T_ + pc * 512 + (size_t)sc * 64;

        #pragma unroll
        for (int i = 0; i < 4; i++) {
            int c = g_tid + i * 128;
            int row = c >> 3, seg = c & 7;
            const char* sh = (const char*)(g_swhi + (gn + row) * (H_ * G_) + h * G_) + seg * 16;
            CP_ASYNC16(gb + PG_SWH + row * 144 + seg * 16, sh);
        }
        #pragma unroll
        for (int i = 0; i < 2; i++) {
            int c = g_tid + i * 128;
            int row = c >> 2, seg = c & 3;
            const char* xh = (const char*)(g_tmphi + (gn + row) * C_ + h * D_) + seg * 16;
            const char* xl = (const char*)(g_tmplo + (gn + row) * C_ + h * D_) + seg * 16;
            CP_ASYNC16(gb + PG_XH + row * 80 + seg * 16, xh);
            CP_ASYNC16(gb + PG_XL + row * 80 + seg * 16, xl);
        }
        CP_COMMIT();
        CP_WAIT0();
        asm volatile("bar.sync %0, 128;" :: "r"(wg + 1) : "memory");

        uint32_t bxh[2][4], bxl[2][4];
        #pragma unroll
        for (int t = 0; t < 2; t++) {
            uint32_t off = (trow * 40 + t * 16 + tcol8) * 2;
            ldsm_x4_t(bxh[t][0], bxh[t][1], bxh[t][2], bxh[t][3], gb + PG_XH + off);
            ldsm_x4_t(bxl[t][0], bxl[t][1], bxl[t][2], bxl[t][3], gb + PG_XL + off);
        }

        #pragma unroll
        for (int mi = 0; mi < 4; mi++) {
            uint32_t ah[4];
            uint32_t off = (trow * 72 + mi * 16 + tcol8) * 2;
            ldsm_x4_t(ah[0], ah[1], ah[2], ah[3], gb + PG_SWH + off);
            #pragma unroll
            for (int nj = 0; nj < 4; nj++) {
                int t = nj >> 1, p = nj & 1;
                float* d = acc[mi][nj];
                mma_bf16(d, ah, bxh[t][p], bxh[t][p + 2]);
                mma_bf16(d, ah, bxl[t][p], bxl[t][p + 2]);
            }
            mma_bf16(acc[mi][4], ah, onesf, onesf);
        }
        asm volatile("bar.sync %0, 128;" :: "r"(wg + 1) : "memory");
    }

    __syncthreads();
    float* red = (float*)psm;    // [4 slots][64 g][40] = 40960 B (fits P_TOTAL)
    const int grp = lane >> 2, qid = lane & 3;
    if (wg == 0) {
        #pragma unroll
        for (int mi = 0; mi < 4; mi++)
            #pragma unroll
            for (int nj = 0; nj < 5; nj++) {
                int g0 = mi * 16 + grp, nn = nj * 8 + qid * 2;
                red[(wl * 64 + g0) * 40 + nn]         = acc[mi][nj][0];
                red[(wl * 64 + g0) * 40 + nn + 1]     = acc[mi][nj][1];
                red[(wl * 64 + g0 + 8) * 40 + nn]     = acc[mi][nj][2];
                red[(wl * 64 + g0 + 8) * 40 + nn + 1] = acc[mi][nj][3];
            }
    }
    __syncthreads();
    if (wg == 1) {
        #pragma unroll
        for (int mi = 0; mi < 4; mi++)
            #pragma unroll
            for (int nj = 0; nj < 5; nj++) {
                int g0 = mi * 16 + grp, nn = nj * 8 + qid * 2;
                red[(wl * 64 + g0) * 40 + nn]         += acc[mi][nj][0];
                red[(wl * 64 + g0) * 40 + nn + 1]     += acc[mi][nj][1];
                red[(wl * 64 + g0 + 8) * 40 + nn]     += acc[mi][nj][2];
                red[(wl * 64 + g0 + 8) * 40 + nn + 1] += acc[mi][nj][3];
            }
    }
    __syncthreads();

    for (int i = tid; i < 64 * 33; i += 256) {
        int g = i / 33, s = i - g * 33;
        float sum = red[g * 40 + s] + red[(64 + g) * 40 + s]
                  + red[(128 + g) * 40 + s] + red[(192 + g) * 40 + s];
        if (s < 32) g_part[((size_t)bh * NCH2 + pc) * (G_ * D_) + g * D_ + s] = sum;
        else        g_pnorm[((size_t)bh * NCH2 + pc) * G_ + g] = sum;
    }
}

// ------- K4a: reduce partials -> tokens -> qkv -> GxG attention -> g_os --------
__global__ __launch_bounds__(256) void attn_tiny_kernel(
    const float* __restrict__ Wq, const float* __restrict__ bq,
    const float* __restrict__ Wk, const float* __restrict__ bk,
    const float* __restrict__ Wv, const float* __restrict__ bv)
{
    __shared__ float tok[G_][D_ + 1];
    __shared__ float qs[G_][D_ + 1];
    __shared__ float ks[G_][D_ + 1];
    __shared__ float vs[G_][D_ + 1];
    __shared__ float norms[G_];

    int bh = blockIdx.x;
    int tid = threadIdx.x;

    if (tid < G_) {
        float s = 0.f;
        for (int ch = 0; ch < NCH2; ch++)
            s += g_pnorm[((size_t)bh * NCH2 + ch) * G_ + tid];
        norms[tid] = s + 1e-5f;
    }
    __syncthreads();

    #pragma unroll
    for (int i = 0; i < 8; i++) {
        int c = tid + i * 256;
        int g = c >> 5, d = c & 31;
        float s = 0.f;
        for (int ch = 0; ch < NCH2; ch++)
            s += g_part[((size_t)bh * NCH2 + ch) * (G_ * D_) + c];
        tok[g][d] = s / norms[g];
    }
    __syncthreads();

    #pragma unroll
    for (int i = 0; i < 8; i++) {
        int c = tid + i * 256;
        int g = c >> 5, d = c & 31;
        float aq = bq[d], ak = bk[d], av = bv[d];
        for (int e = 0; e < D_; e++) {
            float t = tok[g][e];
            aq += t * Wq[e * D_ + d];
            ak += t * Wk[e * D_ + d];
            av += t * Wv[e * D_ + d];
        }
        qs[g][d] = aq; ks[g][d] = ak; vs[g][d] = av;
    }
    __syncthreads();

    if (tid < G_) {
        float qr[D_];
        #pragma unroll
        for (int d = 0; d < D_; d++) qr[d] = qs[tid][d];
        float s[G_];
        float mx = -1e30f;
        #pragma unroll
        for (int j = 0; j < G_; j++) {
            float a = 0.f;
            #pragma unroll
            for (int d = 0; d < D_; d++) a += qr[d] * ks[j][d];
            a *= 0.17677669529663687f;
            s[j] = a; mx = fmaxf(mx, a);
        }
        float sum = 0.f;
        #pragma unroll
        for (int j = 0; j < G_; j++) { s[j] = __expf(s[j] - mx); sum += s[j]; }
        float inv = 1.f / sum;
        #pragma unroll
        for (int d = 0; d < D_; d++) {
            float a = 0.f;
            #pragma unroll
            for (int j = 0; j < G_; j++) a += s[j] * vs[j][d];
            g_os[(size_t)bh * (G_ * D_) + tid * D_ + d] = a * inv;
        }
    }
}

// ------- K4b: fold into transposed bf16 hi/lo M --------------------------------
__global__ __launch_bounds__(256) void fold_kernel(const float* __restrict__ Wout)
{
    __shared__ float os[G_][D_ + 1];
    __shared__ float Wt[D_][G_ + 1];
    int bh = blockIdx.y;
    int b = bh >> 3, h = bh & 7;
    int col0 = blockIdx.x * 64;
    int tid = threadIdx.x;

    #pragma unroll
    for (int i = 0; i < 8; i++) {
        int idx = tid + i * 256;
        os[idx >> 5][idx & 31] = g_os[(size_t)bh * (G_ * D_) + idx];
    }
    #pragma unroll
    for (int i = 0; i < 8; i++) {
        int idx = tid + i * 256;
        int d = idx >> 6, c = idx & 63;
        Wt[d][c] = Wout[(size_t)(h * D_ + d) * C_ + col0 + c];
    }
    __syncthreads();

    int c = tid & 63, g0 = tid >> 6;
    #pragma unroll
    for (int gi = 0; gi < 16; gi++) {
        int g = g0 * 16 + gi;
        float a = 0.f;
        #pragma unroll
        for (int d = 0; d < D_; d++) a += os[g][d] * Wt[d][c];
        __nv_bfloat16 hb = __float2bfloat16_rn(a);
        size_t o = ((size_t)b * C_ + col0 + c) * (size_t)(H_ * G_) + h * G_ + g;
        g_Mhi[o] = hb;
        g_Mlo[o] = __float2bfloat16_rn(a - __bfloat162float(hb));
    }
}

// ---------------- launch --------------------------------------------------------
extern "C" void kernel_launch(void* const* d_in, const int* in_sizes, int n_in,
                              void* d_out, int out_size)
{
    const float* x_q    = (const float*)d_in[0];
    const float* W_in   = (const float*)d_in[3];
    const float* b_in   = (const float*)d_in[4];
    const float* W_sl   = (const float*)d_in[5];
    const float* b_sl   = (const float*)d_in[6];
    const float* temp   = (const float*)d_in[7];
    const float* W_q    = (const float*)d_in[8];
    const float* b_q    = (const float*)d_in[9];
    const float* W_k    = (const float*)d_in[10];
    const float* b_k    = (const float*)d_in[11];
    const float* W_v    = (const float*)d_in[12];
    const float* b_v    = (const float*)d_in[13];
    const float* W_out  = (const float*)d_in[14];
    const float* b_out  = (const float*)d_in[15];
    float* out = (float*)d_out;

    __nv_bfloat16 *thi_p, *tlo_p, *whi_p, *wlo_p, *mhi_p, *mlo_p, *shi_p;
    cudaGetSymbolAddress((void**)&thi_p, g_tmphi);
    cudaGetSymbolAddress((void**)&tlo_p, g_tmplo);
    cudaGetSymbolAddress((void**)&whi_p, g_Whi);
    cudaGetSymbolAddress((void**)&wlo_p, g_Wlo);
    cudaGetSymbolAddress((void**)&mhi_p, g_Mhi);
    cudaGetSymbolAddress((void**)&mlo_p, g_Mlo);
    cudaGetSymbolAddress((void**)&shi_p, g_swhi);

    static int smem_set = 0;
    if (!smem_set) {
        cudaFuncSetAttribute(hmma_gemm_k1_kernel,
                             cudaFuncAttributeMaxDynamicSharedMemorySize, K1_SMEM);
        cudaFuncSetAttribute(hmma_gemm_ab_kernel,
                             cudaFuncAttributeMaxDynamicSharedMemorySize, AB_SMEM);
        cudaFuncSetAttribute(pool_mma_kernel,
                             cudaFuncAttributeMaxDynamicSharedMemorySize, P_TOTAL);
        smem_set = 1;
    }

    // prep: split W_in
    split_w_kernel<<<C_ * C_ / 256, 256>>>(W_in);

    // K1: tmp = x_q @ W_in + b_in  -> bf16 hi/lo
    hmma_gemm_k1_kernel<<<dim3(C_/128, N_/128), 256, K1_SMEM>>>(
        x_q, C_, whi_p, wlo_p, thi_p, tlo_p, C_, b_in, C_);

    // K2: slice softmax -> bf16 hi only (reads x hi+lo)
    slicew_kernel<<<(N_ * H_) / 256, 256>>>(W_sl, b_sl, temp);

    // K3: pooling GEMM (swhi x [xhi + xlo], const-ones norm column)
    pool_mma_kernel<<<dim3(NCH2, B_ * H_), 256, P_TOTAL>>>();

    // K4a: reduce + tiny attention
    attn_tiny_kernel<<<B_ * H_, 256>>>(W_q, b_q, W_k, b_k, W_v, b_v);

    // K4b: fold W_out into pre-split M (hi/lo kept for accuracy)
    fold_kernel<<<dim3(4, B_ * H_), 256>>>(W_out);

    // K5: out[b] = SWhi[b] @ (Mhi + Mlo)[b] + b_out  (occ 2, 2-stage)
    hmma_gemm_ab_kernel<<<dim3(C_/128, T_/128, B_), 256, AB_SMEM>>>(
        shi_p, (size_t)T_ * (H_ * G_),
        mhi_p, mlo_p, (size_t)C_ * (H_ * G_),
        out, C_, (size_t)T_ * C_,
        b_out, H_ * G_);
}

// round 15
// speedup vs baseline: 1.5568x; 1.2346x over previous
#include <cuda_runtime.h>
#include <cuda_fp16.h>
#include <cstdint>
#include <math.h>

// Problem constants
#define B_ 8
#define T_ 8192
#define C_ 256
#define H_ 8
#define G_ 64
#define D_ 32
#define N_ (B_*T_)
#define NCH2 16
#define ASTR 40   // GEMM smem row stride (80B, conflict-free for ldmatrix)

// ---------------- scratch (all fp16 now) ---------------------------------------
__device__ __half g_tmphi[(size_t)N_ * C_];
__device__ __half g_tmplo[(size_t)N_ * C_];
__device__ __half g_swhi[(size_t)N_ * H_ * G_];
__device__ float g_part[(size_t)B_ * H_ * NCH2 * G_ * D_];
__device__ float g_pnorm[(size_t)B_ * H_ * NCH2 * G_];
__device__ float g_os[(size_t)B_ * H_ * G_ * D_];
__device__ __half g_Whi[(size_t)C_ * C_];
__device__ __half g_M[(size_t)B_ * C_ * (H_ * G_)];

// ---------------- small helpers ------------------------------------------------
__device__ __forceinline__ float2 ffma2(float2 a, float2 b, float2 c) {
    float2 d;
    asm("fma.rn.f32x2 %0, %1, %2, %3;"
        : "=l"(reinterpret_cast<unsigned long long&>(d))
        : "l"(reinterpret_cast<unsigned long long&>(a)),
          "l"(reinterpret_cast<unsigned long long&>(b)),
          "l"(reinterpret_cast<unsigned long long&>(c)));
    return d;
}
__device__ __forceinline__ uint32_t smem_to_u32(const void* p) {
    uint32_t a;
    asm("{ .reg .u64 t; cvta.to.shared.u64 t, %1; cvt.u32.u64 %0, t; }" : "=r"(a) : "l"(p));
    return a;
}
__device__ __forceinline__ void ldsm_x4(uint32_t& r0, uint32_t& r1, uint32_t& r2, uint32_t& r3,
                                        uint32_t addr) {
    asm volatile("ldmatrix.sync.aligned.m8n8.x4.shared.b16 {%0,%1,%2,%3}, [%4];"
                 : "=r"(r0), "=r"(r1), "=r"(r2), "=r"(r3) : "r"(addr));
}
__device__ __forceinline__ void ldsm_x4_t(uint32_t& r0, uint32_t& r1, uint32_t& r2, uint32_t& r3,
                                          uint32_t addr) {
    asm volatile("ldmatrix.sync.aligned.m8n8.x4.trans.shared.b16 {%0,%1,%2,%3}, [%4];"
                 : "=r"(r0), "=r"(r1), "=r"(r2), "=r"(r3) : "r"(addr));
}
__device__ __forceinline__ void mma_f16(float* d, const uint32_t* a, uint32_t b0, uint32_t b1) {
    asm volatile("mma.sync.aligned.m16n8k16.row.col.f32.f16.f16.f32 "
        "{%0,%1,%2,%3}, {%4,%5,%6,%7}, {%8,%9}, {%0,%1,%2,%3};"
        : "+f"(d[0]), "+f"(d[1]), "+f"(d[2]), "+f"(d[3])
        : "r"(a[0]), "r"(a[1]), "r"(a[2]), "r"(a[3]), "r"(b0), "r"(b1));
}
__device__ __forceinline__ uint32_t bits2(__half2 h) {
    return *reinterpret_cast<uint32_t*>(&h);
}
__device__ __forceinline__ float2 upk2(uint32_t hu, uint32_t lu) {
    __half2 hh = *reinterpret_cast<__half2*>(&hu);
    __half2 ll = *reinterpret_cast<__half2*>(&lu);
    return make_float2(__half2float(hh.x) + __half2float(ll.x),
                       __half2float(hh.y) + __half2float(ll.y));
}
#define CP_ASYNC16(dst, src) \
    asm volatile("cp.async.cg.shared.global [%0], [%1], 16;" :: "r"(dst), "l"(src))
#define CP_COMMIT() asm volatile("cp.async.commit_group;" ::: "memory")
#define CP_WAIT0()  asm volatile("cp.async.wait_group 0;" ::: "memory")

#define STG_BYTES (128 * ASTR * 2)           // 10240 B per operand buffer

// ---- K1 stage layout (A hi/lo + B single) ----
#define ST1 (3 * STG_BYTES)                  // 30720
#define K1_SMEM (2 * ST1)                    // 61440
#define O1AH 0
#define O1AL STG_BYTES
#define O1BH (2 * STG_BYTES)

// ---- K5 stage layout (A single + B single) ----
#define ST5 (2 * STG_BYTES)                  // 20480
#define AB_SMEM (2 * ST5)                    // 40960 (occ 2 -> 81920/SM)
#define O5AH 0
#define O5BH STG_BYTES

// ============== GEMM variant 1 (K1): A fp32 in (hi/lo fp16), B fp16 single =====
// 2-product: AhiB + AloB.  Output: fp16 hi/lo.
__global__ __launch_bounds__(256, 1) void hmma_gemm_k1_kernel(
    const float* __restrict__ A, int lda,
    const __half* __restrict__ Bh,
    __half* __restrict__ Chi, __half* __restrict__ Clo, int ldc,
    const float* __restrict__ bias, int K)
{
    extern __shared__ __align__(16) char smd[];
    const uint32_t sbase = smem_to_u32(smd);

    const int tid = threadIdx.x;
    const int wid = tid >> 5, lane = tid & 31;
    const int wm = wid & 3, wn = wid >> 2;
    const int m0 = wm * 32, n0w = wn * 64;

    const float* Ab = A + (size_t)blockIdx.y * 128 * lda;
    const __half* Bhb = Bh + (size_t)(blockIdx.x * 128) * K;

    const int lrow = lane & 15;
    const int lcol = (lane >> 4) * 8;
    const int arow = tid >> 1;
    const int akh  = (tid & 1) << 4;
    const int c0row = tid >> 1, c0seg = (tid & 1) * 2;

    float acc[2][8][4];
    #pragma unroll
    for (int mi = 0; mi < 2; mi++)
        #pragma unroll
        for (int n = 0; n < 8; n++)
            #pragma unroll
            for (int q = 0; q < 4; q++) acc[mi][n][q] = 0.f;

    float fst[16];

    auto load_A_regs = [&](int kt) {
        const float* ap = Ab + (size_t)arow * lda + kt + akh;
        *(float4*)(fst + 0)  = *(const float4*)(ap);
        *(float4*)(fst + 4)  = *(const float4*)(ap + 4);
        *(float4*)(fst + 8)  = *(const float4*)(ap + 8);
        *(float4*)(fst + 12) = *(const float4*)(ap + 12);
    };
    auto cpasync_B = [&](int kt, int stg) {
        uint32_t dst = sbase + stg * ST1 + O1BH + c0row * (ASTR * 2) + c0seg * 16;
        const char* srch = (const char*)(Bhb + (size_t)c0row * K + kt) + c0seg * 16;
        CP_ASYNC16(dst, srch);
        CP_ASYNC16(dst + 16, srch + 16);
    };
    auto store_A = [&](int stg) {
        uint32_t h[8], l[8];
        #pragma unroll
        for (int i = 0; i < 8; i++) {
            __half2 hb = __floats2half2_rn(fst[2*i], fst[2*i+1]);
            float r0 = fst[2*i]   - __half2float(hb.x);
            float r1 = fst[2*i+1] - __half2float(hb.y);
            h[i] = bits2(hb);
            l[i] = bits2(__floats2half2_rn(r0, r1));
        }
        char* dh = smd + stg * ST1 + O1AH + arow * (ASTR * 2) + akh * 2;
        char* dl = smd + stg * ST1 + O1AL + arow * (ASTR * 2) + akh * 2;
        ((uint4*)dh)[0] = make_uint4(h[0], h[1], h[2], h[3]);
        ((uint4*)dh)[1] = make_uint4(h[4], h[5], h[6], h[7]);
        ((uint4*)dl)[0] = make_uint4(l[0], l[1], l[2], l[3]);
        ((uint4*)dl)[1] = make_uint4(l[4], l[5], l[6], l[7]);
    };

    load_A_regs(0);
    cpasync_B(0, 0);
    CP_COMMIT();
    store_A(0);
    CP_WAIT0();
    __syncthreads();

    int stage = 0;
    for (int kt = 0; kt < K; kt += 32) {
        const bool has_next = (kt + 32 < K);
        if (has_next) {
            load_A_regs(kt + 32);
            cpasync_B(kt + 32, stage ^ 1);
            CP_COMMIT();
        }

        const uint32_t sb = sbase + stage * ST1;
        #pragma unroll
        for (int ks = 0; ks < 2; ks++) {
            const int cb = ks * 16 + lcol;
            uint32_t ahi[2][4], alo[2][4], bh[4][4];
            #pragma unroll
            for (int mi = 0; mi < 2; mi++) {
                uint32_t off = ((m0 + mi * 16 + lrow) * ASTR + cb) * 2;
                ldsm_x4(ahi[mi][0], ahi[mi][1], ahi[mi][2], ahi[mi][3], sb + O1AH + off);
                ldsm_x4(alo[mi][0], alo[mi][1], alo[mi][2], alo[mi][3], sb + O1AL + off);
            }
            #pragma unroll
            for (int nj = 0; nj < 4; nj++) {
                uint32_t off = ((n0w + nj * 16 + lrow) * ASTR + cb) * 2;
                ldsm_x4(bh[nj][0], bh[nj][1], bh[nj][2], bh[nj][3], sb + O1BH + off);
            }
            #pragma unroll
            for (int mi = 0; mi < 2; mi++) {
                #pragma unroll
                for (int nj = 0; nj < 4; nj++) {
                    float* d0 = acc[mi][nj * 2];
                    mma_f16(d0, ahi[mi], bh[nj][0], bh[nj][2]);
                    mma_f16(d0, alo[mi], bh[nj][0], bh[nj][2]);
                    float* d1 = acc[mi][nj * 2 + 1];
                    mma_f16(d1, ahi[mi], bh[nj][1], bh[nj][3]);
                    mma_f16(d1, alo[mi], bh[nj][1], bh[nj][3]);
                }
            }
        }

        if (has_next) {
            store_A(stage ^ 1);
            CP_WAIT0();
            __syncthreads();
            stage ^= 1;
        }
    }

    // epilogue: bias + split into fp16 hi/lo
    const int grp = lane >> 2, qid = lane & 3;
    #pragma unroll
    for (int mi = 0; mi < 2; mi++) {
        #pragma unroll
        for (int nj = 0; nj < 8; nj++) {
            int row = blockIdx.y * 128 + m0 + mi * 16 + grp;
            int col = blockIdx.x * 128 + n0w + nj * 8 + qid * 2;
            float b0 = bias[col], b1 = bias[col + 1];
            float v0 = acc[mi][nj][0] + b0, v1 = acc[mi][nj][1] + b1;
            float v2 = acc[mi][nj][2] + b0, v3 = acc[mi][nj][3] + b1;
            __half2 h01 = __floats2half2_rn(v0, v1);
            __half2 h23 = __floats2half2_rn(v2, v3);
            *(uint32_t*)(Chi + (size_t)row * ldc + col) = bits2(h01);
            *(uint32_t*)(Chi + (size_t)(row + 8) * ldc + col) = bits2(h23);
            *(uint32_t*)(Clo + (size_t)row * ldc + col) =
                bits2(__floats2half2_rn(v0 - __half2float(h01.x),
                                        v1 - __half2float(h01.y)));
            *(uint32_t*)(Clo + (size_t)(row + 8) * ldc + col) =
                bits2(__floats2half2_rn(v2 - __half2float(h23.x),
                                        v3 - __half2float(h23.y)));
        }
    }
}

// ============== GEMM variant 2 (K5): A fp16 single, B fp16 single, occ 2 ======
__global__ __launch_bounds__(256, 2) void hmma_gemm_ab_kernel(
    const __half* __restrict__ Ah, size_t strideA,
    const __half* __restrict__ Bh, size_t strideB,
    float* __restrict__ Cm, int ldc, size_t strideC,
    const float* __restrict__ bias, int K)
{
    extern __shared__ __align__(16) char smd[];
    const uint32_t sbase = smem_to_u32(smd);

    const int tid = threadIdx.x;
    const int wid = tid >> 5, lane = tid & 31;
    const int wm = wid & 3, wn = wid >> 2;
    const int m0 = wm * 32, n0w = wn * 64;

    const __half* Ahb = Ah + (size_t)blockIdx.z * strideA + (size_t)(blockIdx.y * 128) * K;
    const __half* Bhb = Bh + (size_t)blockIdx.z * strideB + (size_t)(blockIdx.x * 128) * K;
    float* Cb = Cm + (size_t)blockIdx.z * strideC;

    const int lrow = lane & 15;
    const int lcol = (lane >> 4) * 8;
    const int c0row = tid >> 1, c0seg = (tid & 1) * 2;

    float acc[2][8][4];
    #pragma unroll
    for (int mi = 0; mi < 2; mi++)
        #pragma unroll
        for (int n = 0; n < 8; n++)
            #pragma unroll
            for (int q = 0; q < 4; q++) acc[mi][n][q] = 0.f;

    auto cpasync_all = [&](int kt, int stg) {
        uint32_t dst = sbase + stg * ST5 + c0row * (ASTR * 2) + c0seg * 16;
        const char* sah = (const char*)(Ahb + (size_t)c0row * K + kt) + c0seg * 16;
        const char* sbh = (const char*)(Bhb + (size_t)c0row * K + kt) + c0seg * 16;
        CP_ASYNC16(dst + O5AH, sah); CP_ASYNC16(dst + O5AH + 16, sah + 16);
        CP_ASYNC16(dst + O5BH, sbh); CP_ASYNC16(dst + O5BH + 16, sbh + 16);
    };

    cpasync_all(0, 0);
    CP_COMMIT();
    CP_WAIT0();
    __syncthreads();

    int stage = 0;
    for (int kt = 0; kt < K; kt += 32) {
        const bool has_next = (kt + 32 < K);
        if (has_next) {
            cpasync_all(kt + 32, stage ^ 1);
            CP_COMMIT();
        }

        const uint32_t sb = sbase + stage * ST5;
        #pragma unroll
        for (int ks = 0; ks < 2; ks++) {
            const int cb = ks * 16 + lcol;
            uint32_t ah[2][4], bh[4][4];
            #pragma unroll
            for (int mi = 0; mi < 2; mi++) {
                uint32_t off = ((m0 + mi * 16 + lrow) * ASTR + cb) * 2;
                ldsm_x4(ah[mi][0], ah[mi][1], ah[mi][2], ah[mi][3], sb + O5AH + off);
            }
            #pragma unroll
            for (int nj = 0; nj < 4; nj++) {
                uint32_t off = ((n0w + nj * 16 + lrow) * ASTR + cb) * 2;
                ldsm_x4(bh[nj][0], bh[nj][1], bh[nj][2], bh[nj][3], sb + O5BH + off);
            }
            #pragma unroll
            for (int mi = 0; mi < 2; mi++) {
                #pragma unroll
                for (int nj = 0; nj < 4; nj++) {
                    mma_f16(acc[mi][nj * 2],     ah[mi], bh[nj][0], bh[nj][2]);
                    mma_f16(acc[mi][nj * 2 + 1], ah[mi], bh[nj][1], bh[nj][3]);
                }
            }
        }

        if (has_next) {
            CP_WAIT0();
            __syncthreads();
            stage ^= 1;
        }
    }

    const int grp = lane >> 2, qid = lane & 3;
    #pragma unroll
    for (int mi = 0; mi < 2; mi++) {
        #pragma unroll
        for (int nj = 0; nj < 8; nj++) {
            int row = blockIdx.y * 128 + m0 + mi * 16 + grp;
            int col = blockIdx.x * 128 + n0w + nj * 8 + qid * 2;
            float b0 = bias[col], b1 = bias[col + 1];
            *(float2*)(Cb + (size_t)row * ldc + col) =
                make_float2(acc[mi][nj][0] + b0, acc[mi][nj][1] + b1);
            *(float2*)(Cb + (size_t)(row + 8) * ldc + col) =
                make_float2(acc[mi][nj][2] + b0, acc[mi][nj][3] + b1);
        }
    }
}

// ---------------- prep: W_in -> transposed fp16 --------------------------------
__global__ __launch_bounds__(256) void split_w_kernel(const float* __restrict__ W)
{
    int idx = blockIdx.x * 256 + threadIdx.x;   // k*256 + n
    int k = idx >> 8, n = idx & 255;
    g_Whi[(size_t)n * C_ + k] = __float2half_rn(W[idx]);
}

// ---------------- K2: slice weights -> fp16 ------------------------------------
__global__ __launch_bounds__(256) void slicew_kernel(
    const float* __restrict__ Wslice, const float* __restrict__ bslice,
    const float* __restrict__ temp)
{
    __shared__ float Ws[D_ * G_];
    __shared__ float bs[G_];
    __shared__ float it[H_];
    int tid = threadIdx.x;
    #pragma unroll
    for (int i = 0; i < 8; i++) Ws[tid + i * 256] = Wslice[tid + i * 256];
    if (tid < G_) bs[tid] = bslice[tid];
    if (tid < H_) it[tid] = 1.f / temp[tid];
    __syncthreads();

    int gid = blockIdx.x * 256 + tid;
    int n = gid >> 3, h = gid & 7;

    float x[D_];
    const uint4* XH = (const uint4*)(g_tmphi + (size_t)n * C_ + h * D_);
    const uint4* XL = (const uint4*)(g_tmplo + (size_t)n * C_ + h * D_);
    #pragma unroll
    for (int i = 0; i < 4; i++) {
        uint4 hv = XH[i], lv = XL[i];
        float2 p0 = upk2(hv.x, lv.x), p1 = upk2(hv.y, lv.y);
        float2 p2 = upk2(hv.z, lv.z), p3 = upk2(hv.w, lv.w);
        x[8*i+0] = p0.x; x[8*i+1] = p0.y; x[8*i+2] = p1.x; x[8*i+3] = p1.y;
        x[8*i+4] = p2.x; x[8*i+5] = p2.y; x[8*i+6] = p3.x; x[8*i+7] = p3.y;
    }

    float2 lg[G_ / 2];
    const float2* bs2 = (const float2*)bs;
    #pragma unroll
    for (int j = 0; j < G_ / 2; j++) lg[j] = bs2[j];

    const float2* Ws2 = (const float2*)Ws;
    for (int d = 0; d < D_; d++) {
        float2 xv = make_float2(x[d], x[d]);
        #pragma unroll
        for (int j = 0; j < G_ / 2; j++) lg[j] = ffma2(xv, Ws2[d * (G_ / 2) + j], lg[j]);
    }

    float sc = it[h];
    float mx = -1e30f;
    #pragma unroll
    for (int j = 0; j < G_ / 2; j++) {
        lg[j].x *= sc; lg[j].y *= sc;
        mx = fmaxf(mx, fmaxf(lg[j].x, lg[j].y));
    }
    float sum = 0.f;
    #pragma unroll
    for (int j = 0; j < G_ / 2; j++) {
        lg[j].x = __expf(lg[j].x - mx);
        lg[j].y = __expf(lg[j].y - mx);
        sum += lg[j].x + lg[j].y;
    }
    float inv = 1.f / sum;

    size_t base = (size_t)n * (H_ * G_) + h * G_;
    uint2* dhi = (uint2*)(g_swhi + base);
    #pragma unroll
    for (int j = 0; j < 16; j++) {
        float v0 = lg[2*j].x * inv, v1 = lg[2*j].y * inv;
        float v2 = lg[2*j+1].x * inv, v3 = lg[2*j+1].y * inv;
        dhi[j] = make_uint2(bits2(__floats2half2_rn(v0, v1)),
                            bits2(__floats2half2_rn(v2, v3)));
    }
}

// ---------------- K3: pooling GEMM (sw fp16; x fp16 hi/lo), const-ones norm ----
#define PG_SWH 0
#define PG_XH  9216
#define PG_XL  14336
#define PG_SIZE 19456
#define P_TOTAL 40960   // max(2*PG_SIZE = 38912, reduce region 4*64*40*4 = 40960)

__global__ __launch_bounds__(256, 1) void pool_mma_kernel()
{
    extern __shared__ __align__(16) char psm[];
    const uint32_t sbm = smem_to_u32(psm);

    const int tid = threadIdx.x, lane = tid & 31, w = tid >> 5;
    const int wg = w >> 2, wl = w & 3;
    const int g_tid = tid & 127;
    const int pc = blockIdx.x, bh = blockIdx.y;
    const int b = bh >> 3, h = bh & 7;
    const uint32_t gb = sbm + wg * PG_SIZE;

    float acc[4][5][4];
    #pragma unroll
    for (int mi = 0; mi < 4; mi++)
        #pragma unroll
        for (int nj = 0; nj < 5; nj++)
            #pragma unroll
            for (int q = 0; q < 4; q++) acc[mi][nj][q] = 0.f;

    const int cb = wl * 16;
    const int trow = cb + ((lane >> 4) << 3) + (lane & 7);
    const int tcol8 = ((lane >> 3) & 1) << 3;
    // fp16 1.0 = 0x3C00; ones-column fragment (norm): B[k][n]=1 iff n==0
    const uint32_t onesf = ((lane >> 2) == 0) ? 0x3C003C00u : 0u;

    for (int it = 0; it < 4; it++) {
        int sc = 2 * it + wg;
        size_t gn = (size_t)b * T_ + pc * 512 + (size_t)sc * 64;

        #pragma unroll
        for (int i = 0; i < 4; i++) {
            int c = g_tid + i * 128;
            int row = c >> 3, seg = c & 7;
            const char* sh = (const char*)(g_swhi + (gn + row) * (H_ * G_) + h * G_) + seg * 16;
            CP_ASYNC16(gb + PG_SWH + row * 144 + seg * 16, sh);
        }
        #pragma unroll
        for (int i = 0; i < 2; i++) {
            int c = g_tid + i * 128;
            int row = c >> 2, seg = c & 3;
            const char* xh = (const char*)(g_tmphi + (gn + row) * C_ + h * D_) + seg * 16;
            const char* xl = (const char*)(g_tmplo + (gn + row) * C_ + h * D_) + seg * 16;
            CP_ASYNC16(gb + PG_XH + row * 80 + seg * 16, xh);
            CP_ASYNC16(gb + PG_XL + row * 80 + seg * 16, xl);
        }
        CP_COMMIT();
        CP_WAIT0();
        asm volatile("bar.sync %0, 128;" :: "r"(wg + 1) : "memory");

        uint32_t bxh[2][4], bxl[2][4];
        #pragma unroll
        for (int t = 0; t < 2; t++) {
            uint32_t off = (trow * 40 + t * 16 + tcol8) * 2;
            ldsm_x4_t(bxh[t][0], bxh[t][1], bxh[t][2], bxh[t][3], gb + PG_XH + off);
            ldsm_x4_t(bxl[t][0], bxl[t][1], bxl[t][2], bxl[t][3], gb + PG_XL + off);
        }

        #pragma unroll
        for (int mi = 0; mi < 4; mi++) {
            uint32_t ah[4];
            uint32_t off = (trow * 72 + mi * 16 + tcol8) * 2;
            ldsm_x4_t(ah[0], ah[1], ah[2], ah[3], gb + PG_SWH + off);
            #pragma unroll
            for (int nj = 0; nj < 4; nj++) {
                int t = nj >> 1, p = nj & 1;
                float* d = acc[mi][nj];
                mma_f16(d, ah, bxh[t][p], bxh[t][p + 2]);
                mma_f16(d, ah, bxl[t][p], bxl[t][p + 2]);
            }
            mma_f16(acc[mi][4], ah, onesf, onesf);
        }
        asm volatile("bar.sync %0, 128;" :: "r"(wg + 1) : "memory");
    }

    __syncthreads();
    float* red = (float*)psm;    // [4 slots][64 g][40] = 40960 B
    const int grp = lane >> 2, qid = lane & 3;
    if (wg == 0) {
        #pragma unroll
        for (int mi = 0; mi < 4; mi++)
            #pragma unroll
            for (int nj = 0; nj < 5; nj++) {
                int g0 = mi * 16 + grp, nn = nj * 8 + qid * 2;
                red[(wl * 64 + g0) * 40 + nn]         = acc[mi][nj][0];
                red[(wl * 64 + g0) * 40 + nn + 1]     = acc[mi][nj][1];
                red[(wl * 64 + g0 + 8) * 40 + nn]     = acc[mi][nj][2];
                red[(wl * 64 + g0 + 8) * 40 + nn + 1] = acc[mi][nj][3];
            }
    }
    __syncthreads();
    if (wg == 1) {
        #pragma unroll
        for (int mi = 0; mi < 4; mi++)
            #pragma unroll
            for (int nj = 0; nj < 5; nj++) {
                int g0 = mi * 16 + grp, nn = nj * 8 + qid * 2;
                red[(wl * 64 + g0) * 40 + nn]         += acc[mi][nj][0];
                red[(wl * 64 + g0) * 40 + nn + 1]     += acc[mi][nj][1];
                red[(wl * 64 + g0 + 8) * 40 + nn]     += acc[mi][nj][2];
                red[(wl * 64 + g0 + 8) * 40 + nn + 1] += acc[mi][nj][3];
            }
    }
    __syncthreads();

    for (int i = tid; i < 64 * 33; i += 256) {
        int g = i / 33, s = i - g * 33;
        float sum = red[g * 40 + s] + red[(64 + g) * 40 + s]
                  + red[(128 + g) * 40 + s] + red[(192 + g) * 40 + s];
        if (s < 32) g_part[((size_t)bh * NCH2 + pc) * (G_ * D_) + g * D_ + s] = sum;
        else        g_pnorm[((size_t)bh * NCH2 + pc) * G_ + g] = sum;
    }
}

// ------- K4a: reduce partials -> tokens -> qkv -> GxG attention -> g_os --------
__global__ __launch_bounds__(256) void attn_tiny_kernel(
    const float* __restrict__ Wq, const float* __restrict__ bq,
    const float* __restrict__ Wk, const float* __restrict__ bk,
    const float* __restrict__ Wv, const float* __restrict__ bv)
{
    __shared__ float tok[G_][D_ + 1];
    __shared__ float qs[G_][D_ + 1];
    __shared__ float ks[G_][D_ + 1];
    __shared__ float vs[G_][D_ + 1];
    __shared__ float norms[G_];

    int bh = blockIdx.x;
    int tid = threadIdx.x;

    if (tid < G_) {
        float s = 0.f;
        for (int ch = 0; ch < NCH2; ch++)
            s += g_pnorm[((size_t)bh * NCH2 + ch) * G_ + tid];
        norms[tid] = s + 1e-5f;
    }
    __syncthreads();

    #pragma unroll
    for (int i = 0; i < 8; i++) {
        int c = tid + i * 256;
        int g = c >> 5, d = c & 31;
        float s = 0.f;
        for (int ch = 0; ch < NCH2; ch++)
            s += g_part[((size_t)bh * NCH2 + ch) * (G_ * D_) + c];
        tok[g][d] = s / norms[g];
    }
    __syncthreads();

    #pragma unroll
    for (int i = 0; i < 8; i++) {
        int c = tid + i * 256;
        int g = c >> 5, d = c & 31;
        float aq = bq[d], ak = bk[d], av = bv[d];
        for (int e = 0; e < D_; e++) {
            float t = tok[g][e];
            aq += t * Wq[e * D_ + d];
            ak += t * Wk[e * D_ + d];
            av += t * Wv[e * D_ + d];
        }
        qs[g][d] = aq; ks[g][d] = ak; vs[g][d] = av;
    }
    __syncthreads();

    if (tid < G_) {
        float qr[D_];
        #pragma unroll
        for (int d = 0; d < D_; d++) qr[d] = qs[tid][d];
        float s[G_];
        float mx = -1e30f;
        #pragma unroll
        for (int j = 0; j < G_; j++) {
            float a = 0.f;
            #pragma unroll
            for (int d = 0; d < D_; d++) a += qr[d] * ks[j][d];
            a *= 0.17677669529663687f;
            s[j] = a; mx = fmaxf(mx, a);
        }
        float sum = 0.f;
        #pragma unroll
        for (int j = 0; j < G_; j++) { s[j] = __expf(s[j] - mx); sum += s[j]; }
        float inv = 1.f / sum;
        #pragma unroll
        for (int d = 0; d < D_; d++) {
            float a = 0.f;
            #pragma unroll
            for (int j = 0; j < G_; j++) a += s[j] * vs[j][d];
            g_os[(size_t)bh * (G_ * D_) + tid * D_ + d] = a * inv;
        }
    }
}

// ------- K4b: fold into transposed fp16 M --------------------------------------
__global__ __launch_bounds__(256) void fold_kernel(const float* __restrict__ Wout)
{
    __shared__ float os[G_][D_ + 1];
    __shared__ float Wt[D_][G_ + 1];
    int bh = blockIdx.y;
    int b = bh >> 3, h = bh & 7;
    int col0 = blockIdx.x * 64;
    int tid = threadIdx.x;

    #pragma unroll
    for (int i = 0; i < 8; i++) {
        int idx = tid + i * 256;
        os[idx >> 5][idx & 31] = g_os[(size_t)bh * (G_ * D_) + idx];
    }
    #pragma unroll
    for (int i = 0; i < 8; i++) {
        int idx = tid + i * 256;
        int d = idx >> 6, c = idx & 63;
        Wt[d][c] = Wout[(size_t)(h * D_ + d) * C_ + col0 + c];
    }
    __syncthreads();

    int c = tid & 63, g0 = tid >> 6;
    #pragma unroll
    for (int gi = 0; gi < 16; gi++) {
        int g = g0 * 16 + gi;
        float a = 0.f;
        #pragma unroll
        for (int d = 0; d < D_; d++) a += os[g][d] * Wt[d][c];
        size_t o = ((size_t)b * C_ + col0 + c) * (size_t)(H_ * G_) + h * G_ + g;
        g_M[o] = __float2half_rn(a);
    }
}

// ---------------- launch --------------------------------------------------------
extern "C" void kernel_launch(void* const* d_in, const int* in_sizes, int n_in,
                              void* d_out, int out_size)
{
    const float* x_q    = (const float*)d_in[0];
    const float* W_in   = (const float*)d_in[3];
    const float* b_in   = (const float*)d_in[4];
    const float* W_sl   = (const float*)d_in[5];
    const float* b_sl   = (const float*)d_in[6];
    const float* temp   = (const float*)d_in[7];
    const float* W_q    = (const float*)d_in[8];
    const float* b_q    = (const float*)d_in[9];
    const float* W_k    = (const float*)d_in[10];
    const float* b_k    = (const float*)d_in[11];
    const float* W_v    = (const float*)d_in[12];
    const float* b_v    = (const float*)d_in[13];
    const float* W_out  = (const float*)d_in[14];
    const float* b_out  = (const float*)d_in[15];
    float* out = (float*)d_out;

    __half *thi_p, *tlo_p, *whi_p, *m_p, *shi_p;
    cudaGetSymbolAddress((void**)&thi_p, g_tmphi);
    cudaGetSymbolAddress((void**)&tlo_p, g_tmplo);
    cudaGetSymbolAddress((void**)&whi_p, g_Whi);
    cudaGetSymbolAddress((void**)&m_p, g_M);
    cudaGetSymbolAddress((void**)&shi_p, g_swhi);

    static int smem_set = 0;
    if (!smem_set) {
        cudaFuncSetAttribute(hmma_gemm_k1_kernel,
                             cudaFuncAttributeMaxDynamicSharedMemorySize, K1_SMEM);
        cudaFuncSetAttribute(hmma_gemm_ab_kernel,
                             cudaFuncAttributeMaxDynamicSharedMemorySize, AB_SMEM);
        cudaFuncSetAttribute(pool_mma_kernel,
                             cudaFuncAttributeMaxDynamicSharedMemorySize, P_TOTAL);
        smem_set = 1;
    }

    // prep: W_in -> fp16 (transposed)
    split_w_kernel<<<C_ * C_ / 256, 256>>>(W_in);

    // K1: tmp = x_q @ W_in + b_in  -> fp16 hi/lo (2-product: Ahi/Alo x W)
    hmma_gemm_k1_kernel<<<dim3(C_/128, N_/128), 256, K1_SMEM>>>(
        x_q, C_, whi_p, thi_p, tlo_p, C_, b_in, C_);

    // K2: slice softmax -> fp16 (reads x hi+lo)
    slicew_kernel<<<(N_ * H_) / 256, 256>>>(W_sl, b_sl, temp);

    // K3: pooling GEMM (sw x [xhi + xlo], const-ones norm column)
    pool_mma_kernel<<<dim3(NCH2, B_ * H_), 256, P_TOTAL>>>();

    // K4a: reduce + tiny attention
    attn_tiny_kernel<<<B_ * H_, 256>>>(W_q, b_q, W_k, b_k, W_v, b_v);

    // K4b: fold W_out into fp16 M
    fold_kernel<<<dim3(4, B_ * H_), 256>>>(W_out);

    // K5: out[b] = SW[b] @ M[b] + b_out  (single-product fp16, occ 2, 2-stage)
    hmma_gemm_ab_kernel<<<dim3(C_/128, T_/128, B_), 256, AB_SMEM>>>(
        shi_p, (size_t)T_ * (H_ * G_),
        m_p, (size_t)C_ * (H_ * G_),
        out, C_, (size_t)T_ * C_,
        b_out, H_ * G_);
}

// round 16
// speedup vs baseline: 1.6620x; 1.0676x over previous
#include <cuda_runtime.h>
#include <cuda_fp16.h>
#include <cstdint>
#include <math.h>

// Problem constants
#define B_ 8
#define T_ 8192
#define C_ 256
#define H_ 8
#define G_ 64
#define D_ 32
#define N_ (B_*T_)
#define NCH2 16
#define ASTR 40   // GEMM smem row stride (80B, conflict-free for ldmatrix)

// ---------------- scratch (fp16) -------------------------------------------------
__device__ __half g_tmphi[(size_t)N_ * C_];
__device__ __half g_swhi[(size_t)N_ * H_ * G_];
__device__ float g_part[(size_t)B_ * H_ * NCH2 * G_ * D_];
__device__ float g_pnorm[(size_t)B_ * H_ * NCH2 * G_];
__device__ float g_os[(size_t)B_ * H_ * G_ * D_];
__device__ __half g_Whi[(size_t)C_ * C_];
__device__ __half g_M[(size_t)B_ * C_ * (H_ * G_)];

// ---------------- small helpers ------------------------------------------------
__device__ __forceinline__ float2 ffma2(float2 a, float2 b, float2 c) {
    float2 d;
    asm("fma.rn.f32x2 %0, %1, %2, %3;"
        : "=l"(reinterpret_cast<unsigned long long&>(d))
        : "l"(reinterpret_cast<unsigned long long&>(a)),
          "l"(reinterpret_cast<unsigned long long&>(b)),
          "l"(reinterpret_cast<unsigned long long&>(c)));
    return d;
}
__device__ __forceinline__ uint32_t smem_to_u32(const void* p) {
    uint32_t a;
    asm("{ .reg .u64 t; cvta.to.shared.u64 t, %1; cvt.u32.u64 %0, t; }" : "=r"(a) : "l"(p));
    return a;
}
__device__ __forceinline__ void ldsm_x4(uint32_t& r0, uint32_t& r1, uint32_t& r2, uint32_t& r3,
                                        uint32_t addr) {
    asm volatile("ldmatrix.sync.aligned.m8n8.x4.shared.b16 {%0,%1,%2,%3}, [%4];"
                 : "=r"(r0), "=r"(r1), "=r"(r2), "=r"(r3) : "r"(addr));
}
__device__ __forceinline__ void ldsm_x4_t(uint32_t& r0, uint32_t& r1, uint32_t& r2, uint32_t& r3,
                                          uint32_t addr) {
    asm volatile("ldmatrix.sync.aligned.m8n8.x4.trans.shared.b16 {%0,%1,%2,%3}, [%4];"
                 : "=r"(r0), "=r"(r1), "=r"(r2), "=r"(r3) : "r"(addr));
}
__device__ __forceinline__ void mma_f16(float* d, const uint32_t* a, uint32_t b0, uint32_t b1) {
    asm volatile("mma.sync.aligned.m16n8k16.row.col.f32.f16.f16.f32 "
        "{%0,%1,%2,%3}, {%4,%5,%6,%7}, {%8,%9}, {%0,%1,%2,%3};"
        : "+f"(d[0]), "+f"(d[1]), "+f"(d[2]), "+f"(d[3])
        : "r"(a[0]), "r"(a[1]), "r"(a[2]), "r"(a[3]), "r"(b0), "r"(b1));
}
__device__ __forceinline__ uint32_t bits2(__half2 h) {
    return *reinterpret_cast<uint32_t*>(&h);
}
#define CP_ASYNC16(dst, src) \
    asm volatile("cp.async.cg.shared.global [%0], [%1], 16;" :: "r"(dst), "l"(src))
#define CP_COMMIT() asm volatile("cp.async.commit_group;" ::: "memory")
#define CP_WAIT0()  asm volatile("cp.async.wait_group 0;" ::: "memory")

#define STG_BYTES (128 * ASTR * 2)           // 10240 B per operand buffer

// ---- K1 stage layout (A hi/lo + B single) ----
#define ST1 (3 * STG_BYTES)                  // 30720
#define K1_SMEM (2 * ST1)                    // 61440
#define O1AH 0
#define O1AL STG_BYTES
#define O1BH (2 * STG_BYTES)

// ---- K5 stage layout (A single + B single) ----
#define ST5 (2 * STG_BYTES)                  // 20480
#define AB_SMEM (2 * ST5)                    // 40960 (occ 2)
#define O5AH 0
#define O5BH STG_BYTES

// ============== GEMM variant 1 (K1): A fp32 in (hi/lo fp16), B fp16 single =====
// 2-product compute: AhiB + AloB.  Output: fp16 hi only.
__global__ __launch_bounds__(256, 1) void hmma_gemm_k1_kernel(
    const float* __restrict__ A, int lda,
    const __half* __restrict__ Bh,
    __half* __restrict__ Chi, int ldc,
    const float* __restrict__ bias, int K)
{
    extern __shared__ __align__(16) char smd[];
    const uint32_t sbase = smem_to_u32(smd);

    const int tid = threadIdx.x;
    const int wid = tid >> 5, lane = tid & 31;
    const int wm = wid & 3, wn = wid >> 2;
    const int m0 = wm * 32, n0w = wn * 64;

    const float* Ab = A + (size_t)blockIdx.y * 128 * lda;
    const __half* Bhb = Bh + (size_t)(blockIdx.x * 128) * K;

    const int lrow = lane & 15;
    const int lcol = (lane >> 4) * 8;
    const int arow = tid >> 1;
    const int akh  = (tid & 1) << 4;
    const int c0row = tid >> 1, c0seg = (tid & 1) * 2;

    float acc[2][8][4];
    #pragma unroll
    for (int mi = 0; mi < 2; mi++)
        #pragma unroll
        for (int n = 0; n < 8; n++)
            #pragma unroll
            for (int q = 0; q < 4; q++) acc[mi][n][q] = 0.f;

    float fst[16];

    auto load_A_regs = [&](int kt) {
        const float* ap = Ab + (size_t)arow * lda + kt + akh;
        *(float4*)(fst + 0)  = *(const float4*)(ap);
        *(float4*)(fst + 4)  = *(const float4*)(ap + 4);
        *(float4*)(fst + 8)  = *(const float4*)(ap + 8);
        *(float4*)(fst + 12) = *(const float4*)(ap + 12);
    };
    auto cpasync_B = [&](int kt, int stg) {
        uint32_t dst = sbase + stg * ST1 + O1BH + c0row * (ASTR * 2) + c0seg * 16;
        const char* srch = (const char*)(Bhb + (size_t)c0row * K + kt) + c0seg * 16;
        CP_ASYNC16(dst, srch);
        CP_ASYNC16(dst + 16, srch + 16);
    };
    auto store_A = [&](int stg) {
        uint32_t h[8], l[8];
        #pragma unroll
        for (int i = 0; i < 8; i++) {
            __half2 hb = __floats2half2_rn(fst[2*i], fst[2*i+1]);
            float r0 = fst[2*i]   - __half2float(hb.x);
            float r1 = fst[2*i+1] - __half2float(hb.y);
            h[i] = bits2(hb);
            l[i] = bits2(__floats2half2_rn(r0, r1));
        }
        char* dh = smd + stg * ST1 + O1AH + arow * (ASTR * 2) + akh * 2;
        char* dl = smd + stg * ST1 + O1AL + arow * (ASTR * 2) + akh * 2;
        ((uint4*)dh)[0] = make_uint4(h[0], h[1], h[2], h[3]);
        ((uint4*)dh)[1] = make_uint4(h[4], h[5], h[6], h[7]);
        ((uint4*)dl)[0] = make_uint4(l[0], l[1], l[2], l[3]);
        ((uint4*)dl)[1] = make_uint4(l[4], l[5], l[6], l[7]);
    };

    load_A_regs(0);
    cpasync_B(0, 0);
    CP_COMMIT();
    store_A(0);
    CP_WAIT0();
    __syncthreads();

    int stage = 0;
    for (int kt = 0; kt < K; kt += 32) {
        const bool has_next = (kt + 32 < K);
        if (has_next) {
            load_A_regs(kt + 32);
            cpasync_B(kt + 32, stage ^ 1);
            CP_COMMIT();
        }

        const uint32_t sb = sbase + stage * ST1;
        #pragma unroll
        for (int ks = 0; ks < 2; ks++) {
            const int cb = ks * 16 + lcol;
            uint32_t ahi[2][4], alo[2][4], bh[4][4];
            #pragma unroll
            for (int mi = 0; mi < 2; mi++) {
                uint32_t off = ((m0 + mi * 16 + lrow) * ASTR + cb) * 2;
                ldsm_x4(ahi[mi][0], ahi[mi][1], ahi[mi][2], ahi[mi][3], sb + O1AH + off);
                ldsm_x4(alo[mi][0], alo[mi][1], alo[mi][2], alo[mi][3], sb + O1AL + off);
            }
            #pragma unroll
            for (int nj = 0; nj < 4; nj++) {
                uint32_t off = ((n0w + nj * 16 + lrow) * ASTR + cb) * 2;
                ldsm_x4(bh[nj][0], bh[nj][1], bh[nj][2], bh[nj][3], sb + O1BH + off);
            }
            #pragma unroll
            for (int mi = 0; mi < 2; mi++) {
                #pragma unroll
                for (int nj = 0; nj < 4; nj++) {
                    float* d0 = acc[mi][nj * 2];
                    mma_f16(d0, ahi[mi], bh[nj][0], bh[nj][2]);
                    mma_f16(d0, alo[mi], bh[nj][0], bh[nj][2]);
                    float* d1 = acc[mi][nj * 2 + 1];
                    mma_f16(d1, ahi[mi], bh[nj][1], bh[nj][3]);
                    mma_f16(d1, alo[mi], bh[nj][1], bh[nj][3]);
                }
            }
        }

        if (has_next) {
            store_A(stage ^ 1);
            CP_WAIT0();
            __syncthreads();
            stage ^= 1;
        }
    }

    // epilogue: bias + fp16 hi only
    const int grp = lane >> 2, qid = lane & 3;
    #pragma unroll
    for (int mi = 0; mi < 2; mi++) {
        #pragma unroll
        for (int nj = 0; nj < 8; nj++) {
            int row = blockIdx.y * 128 + m0 + mi * 16 + grp;
            int col = blockIdx.x * 128 + n0w + nj * 8 + qid * 2;
            float b0 = bias[col], b1 = bias[col + 1];
            float v0 = acc[mi][nj][0] + b0, v1 = acc[mi][nj][1] + b1;
            float v2 = acc[mi][nj][2] + b0, v3 = acc[mi][nj][3] + b1;
            *(uint32_t*)(Chi + (size_t)row * ldc + col) = bits2(__floats2half2_rn(v0, v1));
            *(uint32_t*)(Chi + (size_t)(row + 8) * ldc + col) = bits2(__floats2half2_rn(v2, v3));
        }
    }
}

// ============== GEMM variant 2 (K5): A fp16 single, B fp16 single, occ 2 ======
__global__ __launch_bounds__(256, 2) void hmma_gemm_ab_kernel(
    const __half* __restrict__ Ah, size_t strideA,
    const __half* __restrict__ Bh, size_t strideB,
    float* __restrict__ Cm, int ldc, size_t strideC,
    const float* __restrict__ bias, int K)
{
    extern __shared__ __align__(16) char smd[];
    const uint32_t sbase = smem_to_u32(smd);

    const int tid = threadIdx.x;
    const int wid = tid >> 5, lane = tid & 31;
    const int wm = wid & 3, wn = wid >> 2;
    const int m0 = wm * 32, n0w = wn * 64;

    const __half* Ahb = Ah + (size_t)blockIdx.z * strideA + (size_t)(blockIdx.y * 128) * K;
    const __half* Bhb = Bh + (size_t)blockIdx.z * strideB + (size_t)(blockIdx.x * 128) * K;
    float* Cb = Cm + (size_t)blockIdx.z * strideC;

    const int lrow = lane & 15;
    const int lcol = (lane >> 4) * 8;
    const int c0row = tid >> 1, c0seg = (tid & 1) * 2;

    float acc[2][8][4];
    #pragma unroll
    for (int mi = 0; mi < 2; mi++)
        #pragma unroll
        for (int n = 0; n < 8; n++)
            #pragma unroll
            for (int q = 0; q < 4; q++) acc[mi][n][q] = 0.f;

    auto cpasync_all = [&](int kt, int stg) {
        uint32_t dst = sbase + stg * ST5 + c0row * (ASTR * 2) + c0seg * 16;
        const char* sah = (const char*)(Ahb + (size_t)c0row * K + kt) + c0seg * 16;
        const char* sbh = (const char*)(Bhb + (size_t)c0row * K + kt) + c0seg * 16;
        CP_ASYNC16(dst + O5AH, sah); CP_ASYNC16(dst + O5AH + 16, sah + 16);
        CP_ASYNC16(dst + O5BH, sbh); CP_ASYNC16(dst + O5BH + 16, sbh + 16);
    };

    cpasync_all(0, 0);
    CP_COMMIT();
    CP_WAIT0();
    __syncthreads();

    int stage = 0;
    for (int kt = 0; kt < K; kt += 32) {
        const bool has_next = (kt + 32 < K);
        if (has_next) {
            cpasync_all(kt + 32, stage ^ 1);
            CP_COMMIT();
        }

        const uint32_t sb = sbase + stage * ST5;
        #pragma unroll
        for (int ks = 0; ks < 2; ks++) {
            const int cb = ks * 16 + lcol;
            uint32_t ah[2][4], bh[4][4];
            #pragma unroll
            for (int mi = 0; mi < 2; mi++) {
                uint32_t off = ((m0 + mi * 16 + lrow) * ASTR + cb) * 2;
                ldsm_x4(ah[mi][0], ah[mi][1], ah[mi][2], ah[mi][3], sb + O5AH + off);
            }
            #pragma unroll
            for (int nj = 0; nj < 4; nj++) {
                uint32_t off = ((n0w + nj * 16 + lrow) * ASTR + cb) * 2;
                ldsm_x4(bh[nj][0], bh[nj][1], bh[nj][2], bh[nj][3], sb + O5BH + off);
            }
            #pragma unroll
            for (int mi = 0; mi < 2; mi++) {
                #pragma unroll
                for (int nj = 0; nj < 4; nj++) {
                    mma_f16(acc[mi][nj * 2],     ah[mi], bh[nj][0], bh[nj][2]);
                    mma_f16(acc[mi][nj * 2 + 1], ah[mi], bh[nj][1], bh[nj][3]);
                }
            }
        }

        if (has_next) {
            CP_WAIT0();
            __syncthreads();
            stage ^= 1;
        }
    }

    const int grp = lane >> 2, qid = lane & 3;
    #pragma unroll
    for (int mi = 0; mi < 2; mi++) {
        #pragma unroll
        for (int nj = 0; nj < 8; nj++) {
            int row = blockIdx.y * 128 + m0 + mi * 16 + grp;
            int col = blockIdx.x * 128 + n0w + nj * 8 + qid * 2;
            float b0 = bias[col], b1 = bias[col + 1];
            *(float2*)(Cb + (size_t)row * ldc + col) =
                make_float2(acc[mi][nj][0] + b0, acc[mi][nj][1] + b1);
            *(float2*)(Cb + (size_t)(row + 8) * ldc + col) =
                make_float2(acc[mi][nj][2] + b0, acc[mi][nj][3] + b1);
        }
    }
}

// ---------------- prep: W_in -> transposed fp16 --------------------------------
__global__ __launch_bounds__(256) void split_w_kernel(const float* __restrict__ W)
{
    int idx = blockIdx.x * 256 + threadIdx.x;   // k*256 + n
    int k = idx >> 8, n = idx & 255;
    g_Whi[(size_t)n * C_ + k] = __float2half_rn(W[idx]);
}

// ---------------- K2: slice weights -> fp16 (x hi only) ------------------------
__global__ __launch_bounds__(256) void slicew_kernel(
    const float* __restrict__ Wslice, const float* __restrict__ bslice,
    const float* __restrict__ temp)
{
    __shared__ float Ws[D_ * G_];
    __shared__ float bs[G_];
    __shared__ float it[H_];
    int tid = threadIdx.x;
    #pragma unroll
    for (int i = 0; i < 8; i++) Ws[tid + i * 256] = Wslice[tid + i * 256];
    if (tid < G_) bs[tid] = bslice[tid];
    if (tid < H_) it[tid] = 1.f / temp[tid];
    __syncthreads();

    int gid = blockIdx.x * 256 + tid;
    int n = gid >> 3, h = gid & 7;

    float x[D_];
    const uint4* XH = (const uint4*)(g_tmphi + (size_t)n * C_ + h * D_);
    #pragma unroll
    for (int i = 0; i < 4; i++) {
        uint4 hv = XH[i];
        __half2 p0 = *reinterpret_cast<__half2*>(&hv.x);
        __half2 p1 = *reinterpret_cast<__half2*>(&hv.y);
        __half2 p2 = *reinterpret_cast<__half2*>(&hv.z);
        __half2 p3 = *reinterpret_cast<__half2*>(&hv.w);
        x[8*i+0] = __half2float(p0.x); x[8*i+1] = __half2float(p0.y);
        x[8*i+2] = __half2float(p1.x); x[8*i+3] = __half2float(p1.y);
        x[8*i+4] = __half2float(p2.x); x[8*i+5] = __half2float(p2.y);
        x[8*i+6] = __half2float(p3.x); x[8*i+7] = __half2float(p3.y);
    }

    float2 lg[G_ / 2];
    const float2* bs2 = (const float2*)bs;
    #pragma unroll
    for (int j = 0; j < G_ / 2; j++) lg[j] = bs2[j];

    const float2* Ws2 = (const float2*)Ws;
    for (int d = 0; d < D_; d++) {
        float2 xv = make_float2(x[d], x[d]);
        #pragma unroll
        for (int j = 0; j < G_ / 2; j++) lg[j] = ffma2(xv, Ws2[d * (G_ / 2) + j], lg[j]);
    }

    float sc = it[h];
    float mx = -1e30f;
    #pragma unroll
    for (int j = 0; j < G_ / 2; j++) {
        lg[j].x *= sc; lg[j].y *= sc;
        mx = fmaxf(mx, fmaxf(lg[j].x, lg[j].y));
    }
    float sum = 0.f;
    #pragma unroll
    for (int j = 0; j < G_ / 2; j++) {
        lg[j].x = __expf(lg[j].x - mx);
        lg[j].y = __expf(lg[j].y - mx);
        sum += lg[j].x + lg[j].y;
    }
    float inv = 1.f / sum;

    size_t base = (size_t)n * (H_ * G_) + h * G_;
    uint2* dhi = (uint2*)(g_swhi + base);
    #pragma unroll
    for (int j = 0; j < 16; j++) {
        float v0 = lg[2*j].x * inv, v1 = lg[2*j].y * inv;
        float v2 = lg[2*j+1].x * inv, v3 = lg[2*j+1].y * inv;
        dhi[j] = make_uint2(bits2(__floats2half2_rn(v0, v1)),
                            bits2(__floats2half2_rn(v2, v3)));
    }
}

// ---------------- K3: pooling GEMM (sw x xhi), const-ones norm -----------------
#define PG_SWH 0
#define PG_XH  9216
#define PG_SIZE 14336
#define P_TOTAL 40960   // max(2*PG_SIZE = 28672, reduce region 4*64*40*4 = 40960)

__global__ __launch_bounds__(256, 1) void pool_mma_kernel()
{
    extern __shared__ __align__(16) char psm[];
    const uint32_t sbm = smem_to_u32(psm);

    const int tid = threadIdx.x, lane = tid & 31, w = tid >> 5;
    const int wg = w >> 2, wl = w & 3;
    const int g_tid = tid & 127;
    const int pc = blockIdx.x, bh = blockIdx.y;
    const int b = bh >> 3, h = bh & 7;
    const uint32_t gb = sbm + wg * PG_SIZE;

    float acc[4][5][4];
    #pragma unroll
    for (int mi = 0; mi < 4; mi++)
        #pragma unroll
        for (int nj = 0; nj < 5; nj++)
            #pragma unroll
            for (int q = 0; q < 4; q++) acc[mi][nj][q] = 0.f;

    const int cb = wl * 16;
    const int trow = cb + ((lane >> 4) << 3) + (lane & 7);
    const int tcol8 = ((lane >> 3) & 1) << 3;
    const uint32_t onesf = ((lane >> 2) == 0) ? 0x3C003C00u : 0u;  // fp16 ones col

    for (int it = 0; it < 4; it++) {
        int sc = 2 * it + wg;
        size_t gn = (size_t)b * T_ + pc * 512 + (size_t)sc * 64;

        #pragma unroll
        for (int i = 0; i < 4; i++) {
            int c = g_tid + i * 128;
            int row = c >> 3, seg = c & 7;
            const char* sh = (const char*)(g_swhi + (gn + row) * (H_ * G_) + h * G_) + seg * 16;
            CP_ASYNC16(gb + PG_SWH + row * 144 + seg * 16, sh);
        }
        #pragma unroll
        for (int i = 0; i < 1; i++) {
            int c = g_tid;
            int row = c >> 2, seg = c & 3;
            const char* xh = (const char*)(g_tmphi + (gn + row) * C_ + h * D_) + seg * 16;
            CP_ASYNC16(gb + PG_XH + row * 80 + seg * 16, xh);
            int c2 = g_tid + 128;
            int row2 = c2 >> 2, seg2 = c2 & 3;
            const char* xh2 = (const char*)(g_tmphi + (gn + row2) * C_ + h * D_) + seg2 * 16;
            CP_ASYNC16(gb + PG_XH + row2 * 80 + seg2 * 16, xh2);
        }
        CP_COMMIT();
        CP_WAIT0();
        asm volatile("bar.sync %0, 128;" :: "r"(wg + 1) : "memory");

        uint32_t bxh[2][4];
        #pragma unroll
        for (int t = 0; t < 2; t++) {
            uint32_t off = (trow * 40 + t * 16 + tcol8) * 2;
            ldsm_x4_t(bxh[t][0], bxh[t][1], bxh[t][2], bxh[t][3], gb + PG_XH + off);
        }

        #pragma unroll
        for (int mi = 0; mi < 4; mi++) {
            uint32_t ah[4];
            uint32_t off = (trow * 72 + mi * 16 + tcol8) * 2;
            ldsm_x4_t(ah[0], ah[1], ah[2], ah[3], gb + PG_SWH + off);
            #pragma unroll
            for (int nj = 0; nj < 4; nj++) {
                int t = nj >> 1, p = nj & 1;
                mma_f16(acc[mi][nj], ah, bxh[t][p], bxh[t][p + 2]);
            }
            mma_f16(acc[mi][4], ah, onesf, onesf);
        }
        asm volatile("bar.sync %0, 128;" :: "r"(wg + 1) : "memory");
    }

    __syncthreads();
    float* red = (float*)psm;    // [4 slots][64 g][40] = 40960 B
    const int grp = lane >> 2, qid = lane & 3;
    if (wg == 0) {
        #pragma unroll
        for (int mi = 0; mi < 4; mi++)
            #pragma unroll
            for (int nj = 0; nj < 5; nj++) {
                int g0 = mi * 16 + grp, nn = nj * 8 + qid * 2;
                red[(wl * 64 + g0) * 40 + nn]         = acc[mi][nj][0];
                red[(wl * 64 + g0) * 40 + nn + 1]     = acc[mi][nj][1];
                red[(wl * 64 + g0 + 8) * 40 + nn]     = acc[mi][nj][2];
                red[(wl * 64 + g0 + 8) * 40 + nn + 1] = acc[mi][nj][3];
            }
    }
    __syncthreads();
    if (wg == 1) {
        #pragma unroll
        for (int mi = 0; mi < 4; mi++)
            #pragma unroll
            for (int nj = 0; nj < 5; nj++) {
                int g0 = mi * 16 + grp, nn = nj * 8 + qid * 2;
                red[(wl * 64 + g0) * 40 + nn]         += acc[mi][nj][0];
                red[(wl * 64 + g0) * 40 + nn + 1]     += acc[mi][nj][1];
                red[(wl * 64 + g0 + 8) * 40 + nn]     += acc[mi][nj][2];
                red[(wl * 64 + g0 + 8) * 40 + nn + 1] += acc[mi][nj][3];
            }
    }
    __syncthreads();

    for (int i = tid; i < 64 * 33; i += 256) {
        int g = i / 33, s = i - g * 33;
        float sum = red[g * 40 + s] + red[(64 + g) * 40 + s]
                  + red[(128 + g) * 40 + s] + red[(192 + g) * 40 + s];
        if (s < 32) g_part[((size_t)bh * NCH2 + pc) * (G_ * D_) + g * D_ + s] = sum;
        else        g_pnorm[((size_t)bh * NCH2 + pc) * G_ + g] = sum;
    }
}

// ------- K4a: reduce partials -> tokens -> qkv -> GxG attention -> g_os --------
__global__ __launch_bounds__(256) void attn_tiny_kernel(
    const float* __restrict__ Wq, const float* __restrict__ bq,
    const float* __restrict__ Wk, const float* __restrict__ bk,
    const float* __restrict__ Wv, const float* __restrict__ bv)
{
    __shared__ float tok[G_][D_ + 1];
    __shared__ float qs[G_][D_ + 1];
    __shared__ float ks[G_][D_ + 1];
    __shared__ float vs[G_][D_ + 1];
    __shared__ float norms[G_];

    int bh = blockIdx.x;
    int tid = threadIdx.x;

    if (tid < G_) {
        float s = 0.f;
        for (int ch = 0; ch < NCH2; ch++)
            s += g_pnorm[((size_t)bh * NCH2 + ch) * G_ + tid];
        norms[tid] = s + 1e-5f;
    }
    __syncthreads();

    #pragma unroll
    for (int i = 0; i < 8; i++) {
        int c = tid + i * 256;
        int g = c >> 5, d = c & 31;
        float s = 0.f;
        for (int ch = 0; ch < NCH2; ch++)
            s += g_part[((size_t)bh * NCH2 + ch) * (G_ * D_) + c];
        tok[g][d] = s / norms[g];
    }
    __syncthreads();

    #pragma unroll
    for (int i = 0; i < 8; i++) {
        int c = tid + i * 256;
        int g = c >> 5, d = c & 31;
        float aq = bq[d], ak = bk[d], av = bv[d];
        for (int e = 0; e < D_; e++) {
            float t = tok[g][e];
            aq += t * Wq[e * D_ + d];
            ak += t * Wk[e * D_ + d];
            av += t * Wv[e * D_ + d];
        }
        qs[g][d] = aq; ks[g][d] = ak; vs[g][d] = av;
    }
    __syncthreads();

    if (tid < G_) {
        float qr[D_];
        #pragma unroll
        for (int d = 0; d < D_; d++) qr[d] = qs[tid][d];
        float s[G_];
        float mx = -1e30f;
        #pragma unroll
        for (int j = 0; j < G_; j++) {
            float a = 0.f;
            #pragma unroll
            for (int d = 0; d < D_; d++) a += qr[d] * ks[j][d];
            a *= 0.17677669529663687f;
            s[j] = a; mx = fmaxf(mx, a);
        }
        float sum = 0.f;
        #pragma unroll
        for (int j = 0; j < G_; j++) { s[j] = __expf(s[j] - mx); sum += s[j]; }
        float inv = 1.f / sum;
        #pragma unroll
        for (int d = 0; d < D_; d++) {
            float a = 0.f;
            #pragma unroll
            for (int j = 0; j < G_; j++) a += s[j] * vs[j][d];
            g_os[(size_t)bh * (G_ * D_) + tid * D_ + d] = a * inv;
        }
    }
}

// ------- K4b: fold into transposed fp16 M --------------------------------------
__global__ __launch_bounds__(256) void fold_kernel(const float* __restrict__ Wout)
{
    __shared__ float os[G_][D_ + 1];
    __shared__ float Wt[D_][G_ + 1];
    int bh = blockIdx.y;
    int b = bh >> 3, h = bh & 7;
    int col0 = blockIdx.x * 64;
    int tid = threadIdx.x;

    #pragma unroll
    for (int i = 0; i < 8; i++) {
        int idx = tid + i * 256;
        os[idx >> 5][idx & 31] = g_os[(size_t)bh * (G_ * D_) + idx];
    }
    #pragma unroll
    for (int i = 0; i < 8; i++) {
        int idx = tid + i * 256;
        int d = idx >> 6, c = idx & 63;
        Wt[d][c] = Wout[(size_t)(h * D_ + d) * C_ + col0 + c];
    }
    __syncthreads();

    int c = tid & 63, g0 = tid >> 6;
    #pragma unroll
    for (int gi = 0; gi < 16; gi++) {
        int g = g0 * 16 + gi;
        float a = 0.f;
        #pragma unroll
        for (int d = 0; d < D_; d++) a += os[g][d] * Wt[d][c];
        size_t o = ((size_t)b * C_ + col0 + c) * (size_t)(H_ * G_) + h * G_ + g;
        g_M[o] = __float2half_rn(a);
    }
}

// ---------------- launch --------------------------------------------------------
extern "C" void kernel_launch(void* const* d_in, const int* in_sizes, int n_in,
                              void* d_out, int out_size)
{
    const float* x_q    = (const float*)d_in[0];
    const float* W_in   = (const float*)d_in[3];
    const float* b_in   = (const float*)d_in[4];
    const float* W_sl   = (const float*)d_in[5];
    const float* b_sl   = (const float*)d_in[6];
    const float* temp   = (const float*)d_in[7];
    const float* W_q    = (const float*)d_in[8];
    const float* b_q    = (const float*)d_in[9];
    const float* W_k    = (const float*)d_in[10];
    const float* b_k    = (const float*)d_in[11];
    const float* W_v    = (const float*)d_in[12];
    const float* b_v    = (const float*)d_in[13];
    const float* W_out  = (const float*)d_in[14];
    const float* b_out  = (const float*)d_in[15];
    float* out = (float*)d_out;

    __half *thi_p, *whi_p, *m_p, *shi_p;
    cudaGetSymbolAddress((void**)&thi_p, g_tmphi);
    cudaGetSymbolAddress((void**)&whi_p, g_Whi);
    cudaGetSymbolAddress((void**)&m_p, g_M);
    cudaGetSymbolAddress((void**)&shi_p, g_swhi);

    static int smem_set = 0;
    if (!smem_set) {
        cudaFuncSetAttribute(hmma_gemm_k1_kernel,
                             cudaFuncAttributeMaxDynamicSharedMemorySize, K1_SMEM);
        cudaFuncSetAttribute(hmma_gemm_ab_kernel,
                             cudaFuncAttributeMaxDynamicSharedMemorySize, AB_SMEM);
        cudaFuncSetAttribute(pool_mma_kernel,
                             cudaFuncAttributeMaxDynamicSharedMemorySize, P_TOTAL);
        smem_set = 1;
    }

    // prep: W_in -> fp16 (transposed)
    split_w_kernel<<<C_ * C_ / 256, 256>>>(W_in);

    // K1: tmp = x_q @ W_in + b_in  -> fp16 hi only (2-product compute)
    hmma_gemm_k1_kernel<<<dim3(C_/128, N_/128), 256, K1_SMEM>>>(
        x_q, C_, whi_p, thi_p, C_, b_in, C_);

    // K2: slice softmax -> fp16 (x hi only)
    slicew_kernel<<<(N_ * H_) / 256, 256>>>(W_sl, b_sl, temp);

    // K3: pooling GEMM (sw x xhi, const-ones norm column)
    pool_mma_kernel<<<dim3(NCH2, B_ * H_), 256, P_TOTAL>>>();

    // K4a: reduce + tiny attention
    attn_tiny_kernel<<<B_ * H_, 256>>>(W_q, b_q, W_k, b_k, W_v, b_v);

    // K4b: fold W_out into fp16 M
    fold_kernel<<<dim3(4, B_ * H_), 256>>>(W_out);

    // K5: out[b] = SW[b] @ M[b] + b_out  (single-product fp16, occ 2, 2-stage)
    hmma_gemm_ab_kernel<<<dim3(C_/128, T_/128, B_), 256, AB_SMEM>>>(
        shi_p, (size_t)T_ * (H_ * G_),
        m_p, (size_t)C_ * (H_ * G_),
        out, C_, (size_t)T_ * C_,
        b_out, H_ * G_);
}

// round 17
// speedup vs baseline: 1.7189x; 1.0343x over previous
#include <cuda_runtime.h>
#include <cuda_fp16.h>
#include <cstdint>
#include <math.h>

// Problem constants
#define B_ 8
#define T_ 8192
#define C_ 256
#define H_ 8
#define G_ 64
#define D_ 32
#define N_ (B_*T_)
#define NCH2 16
#define ASTR 40   // GEMM smem row stride (80B, conflict-free for ldmatrix)

// ---------------- scratch (fp16) -------------------------------------------------
__device__ __half g_tmphi[(size_t)N_ * C_];
__device__ __half g_swhi[(size_t)N_ * H_ * G_];
__device__ float g_part[(size_t)B_ * H_ * NCH2 * G_ * D_];
__device__ float g_pnorm[(size_t)B_ * H_ * NCH2 * G_];
__device__ float g_os[(size_t)B_ * H_ * G_ * D_];
__device__ __half g_Whi[(size_t)C_ * C_];
__device__ __half g_M[(size_t)B_ * C_ * (H_ * G_)];

// ---------------- small helpers ------------------------------------------------
__device__ __forceinline__ float2 ffma2(float2 a, float2 b, float2 c) {
    float2 d;
    asm("fma.rn.f32x2 %0, %1, %2, %3;"
        : "=l"(reinterpret_cast<unsigned long long&>(d))
        : "l"(reinterpret_cast<unsigned long long&>(a)),
          "l"(reinterpret_cast<unsigned long long&>(b)),
          "l"(reinterpret_cast<unsigned long long&>(c)));
    return d;
}
__device__ __forceinline__ uint32_t smem_to_u32(const void* p) {
    uint32_t a;
    asm("{ .reg .u64 t; cvta.to.shared.u64 t, %1; cvt.u32.u64 %0, t; }" : "=r"(a) : "l"(p));
    return a;
}
__device__ __forceinline__ void ldsm_x4(uint32_t& r0, uint32_t& r1, uint32_t& r2, uint32_t& r3,
                                        uint32_t addr) {
    asm volatile("ldmatrix.sync.aligned.m8n8.x4.shared.b16 {%0,%1,%2,%3}, [%4];"
                 : "=r"(r0), "=r"(r1), "=r"(r2), "=r"(r3) : "r"(addr));
}
__device__ __forceinline__ void ldsm_x4_t(uint32_t& r0, uint32_t& r1, uint32_t& r2, uint32_t& r3,
                                          uint32_t addr) {
    asm volatile("ldmatrix.sync.aligned.m8n8.x4.trans.shared.b16 {%0,%1,%2,%3}, [%4];"
                 : "=r"(r0), "=r"(r1), "=r"(r2), "=r"(r3) : "r"(addr));
}
__device__ __forceinline__ void mma_f16(float* d, const uint32_t* a, uint32_t b0, uint32_t b1) {
    asm volatile("mma.sync.aligned.m16n8k16.row.col.f32.f16.f16.f32 "
        "{%0,%1,%2,%3}, {%4,%5,%6,%7}, {%8,%9}, {%0,%1,%2,%3};"
        : "+f"(d[0]), "+f"(d[1]), "+f"(d[2]), "+f"(d[3])
        : "r"(a[0]), "r"(a[1]), "r"(a[2]), "r"(a[3]), "r"(b0), "r"(b1));
}
__device__ __forceinline__ uint32_t bits2(__half2 h) {
    return *reinterpret_cast<uint32_t*>(&h);
}
#define CP_ASYNC16(dst, src) \
    asm volatile("cp.async.cg.shared.global [%0], [%1], 16;" :: "r"(dst), "l"(src))
#define CP_COMMIT() asm volatile("cp.async.commit_group;" ::: "memory")
#define CP_WAIT0()  asm volatile("cp.async.wait_group 0;" ::: "memory")
#define CP_WAIT1()  asm volatile("cp.async.wait_group 1;" ::: "memory")

#define STG_BYTES (128 * ASTR * 2)           // 10240 B per operand buffer

// ---- K1 stage layout (A hi/lo + B single) ----
#define ST1 (3 * STG_BYTES)                  // 30720
#define K1_SMEM (2 * ST1)                    // 61440
#define O1AH 0
#define O1AL STG_BYTES
#define O1BH (2 * STG_BYTES)

// ---- K5 stage layout (A single + B single), 3 stages ----
#define ST5 (2 * STG_BYTES)                  // 20480
#define AB_SMEM (3 * ST5)                    // 61440 (occ 2 -> 122880/SM)
#define O5AH 0
#define O5BH STG_BYTES

// ============== GEMM variant 1 (K1): A fp32 in (hi/lo fp16), B fp16 single =====
__global__ __launch_bounds__(256, 1) void hmma_gemm_k1_kernel(
    const float* __restrict__ A, int lda,
    const __half* __restrict__ Bh,
    __half* __restrict__ Chi, int ldc,
    const float* __restrict__ bias, int K)
{
    extern __shared__ __align__(16) char smd[];
    const uint32_t sbase = smem_to_u32(smd);

    const int tid = threadIdx.x;
    const int wid = tid >> 5, lane = tid & 31;
    const int wm = wid & 3, wn = wid >> 2;
    const int m0 = wm * 32, n0w = wn * 64;

    const float* Ab = A + (size_t)blockIdx.y * 128 * lda;
    const __half* Bhb = Bh + (size_t)(blockIdx.x * 128) * K;

    const int lrow = lane & 15;
    const int lcol = (lane >> 4) * 8;
    const int arow = tid >> 1;
    const int akh  = (tid & 1) << 4;
    const int c0row = tid >> 1, c0seg = (tid & 1) * 2;

    float acc[2][8][4];
    #pragma unroll
    for (int mi = 0; mi < 2; mi++)
        #pragma unroll
        for (int n = 0; n < 8; n++)
            #pragma unroll
            for (int q = 0; q < 4; q++) acc[mi][n][q] = 0.f;

    float fst[16];

    auto load_A_regs = [&](int kt) {
        const float* ap = Ab + (size_t)arow * lda + kt + akh;
        *(float4*)(fst + 0)  = *(const float4*)(ap);
        *(float4*)(fst + 4)  = *(const float4*)(ap + 4);
        *(float4*)(fst + 8)  = *(const float4*)(ap + 8);
        *(float4*)(fst + 12) = *(const float4*)(ap + 12);
    };
    auto cpasync_B = [&](int kt, int stg) {
        uint32_t dst = sbase + stg * ST1 + O1BH + c0row * (ASTR * 2) + c0seg * 16;
        const char* srch = (const char*)(Bhb + (size_t)c0row * K + kt) + c0seg * 16;
        CP_ASYNC16(dst, srch);
        CP_ASYNC16(dst + 16, srch + 16);
    };
    auto store_A = [&](int stg) {
        uint32_t h[8], l[8];
        #pragma unroll
        for (int i = 0; i < 8; i++) {
            __half2 hb = __floats2half2_rn(fst[2*i], fst[2*i+1]);
            float r0 = fst[2*i]   - __half2float(hb.x);
            float r1 = fst[2*i+1] - __half2float(hb.y);
            h[i] = bits2(hb);
            l[i] = bits2(__floats2half2_rn(r0, r1));
        }
        char* dh = smd + stg * ST1 + O1AH + arow * (ASTR * 2) + akh * 2;
        char* dl = smd + stg * ST1 + O1AL + arow * (ASTR * 2) + akh * 2;
        ((uint4*)dh)[0] = make_uint4(h[0], h[1], h[2], h[3]);
        ((uint4*)dh)[1] = make_uint4(h[4], h[5], h[6], h[7]);
        ((uint4*)dl)[0] = make_uint4(l[0], l[1], l[2], l[3]);
        ((uint4*)dl)[1] = make_uint4(l[4], l[5], l[6], l[7]);
    };

    load_A_regs(0);
    cpasync_B(0, 0);
    CP_COMMIT();
    store_A(0);
    CP_WAIT0();
    __syncthreads();

    int stage = 0;
    for (int kt = 0; kt < K; kt += 32) {
        const bool has_next = (kt + 32 < K);
        if (has_next) {
            load_A_regs(kt + 32);
            cpasync_B(kt + 32, stage ^ 1);
            CP_COMMIT();
        }

        const uint32_t sb = sbase + stage * ST1;
        #pragma unroll
        for (int ks = 0; ks < 2; ks++) {
            const int cb = ks * 16 + lcol;
            uint32_t ahi[2][4], alo[2][4], bh[4][4];
            #pragma unroll
            for (int mi = 0; mi < 2; mi++) {
                uint32_t off = ((m0 + mi * 16 + lrow) * ASTR + cb) * 2;
                ldsm_x4(ahi[mi][0], ahi[mi][1], ahi[mi][2], ahi[mi][3], sb + O1AH + off);
                ldsm_x4(alo[mi][0], alo[mi][1], alo[mi][2], alo[mi][3], sb + O1AL + off);
            }
            #pragma unroll
            for (int nj = 0; nj < 4; nj++) {
                uint32_t off = ((n0w + nj * 16 + lrow) * ASTR + cb) * 2;
                ldsm_x4(bh[nj][0], bh[nj][1], bh[nj][2], bh[nj][3], sb + O1BH + off);
            }
            #pragma unroll
            for (int mi = 0; mi < 2; mi++) {
                #pragma unroll
                for (int nj = 0; nj < 4; nj++) {
                    float* d0 = acc[mi][nj * 2];
                    mma_f16(d0, ahi[mi], bh[nj][0], bh[nj][2]);
                    mma_f16(d0, alo[mi], bh[nj][0], bh[nj][2]);
                    float* d1 = acc[mi][nj * 2 + 1];
                    mma_f16(d1, ahi[mi], bh[nj][1], bh[nj][3]);
                    mma_f16(d1, alo[mi], bh[nj][1], bh[nj][3]);
                }
            }
        }

        if (has_next) {
            store_A(stage ^ 1);
            CP_WAIT0();
            __syncthreads();
            stage ^= 1;
        }
    }

    const int grp = lane >> 2, qid = lane & 3;
    #pragma unroll
    for (int mi = 0; mi < 2; mi++) {
        #pragma unroll
        for (int nj = 0; nj < 8; nj++) {
            int row = blockIdx.y * 128 + m0 + mi * 16 + grp;
            int col = blockIdx.x * 128 + n0w + nj * 8 + qid * 2;
            float b0 = bias[col], b1 = bias[col + 1];
            float v0 = acc[mi][nj][0] + b0, v1 = acc[mi][nj][1] + b1;
            float v2 = acc[mi][nj][2] + b0, v3 = acc[mi][nj][3] + b1;
            *(uint32_t*)(Chi + (size_t)row * ldc + col) = bits2(__floats2half2_rn(v0, v1));
            *(uint32_t*)(Chi + (size_t)(row + 8) * ldc + col) = bits2(__floats2half2_rn(v2, v3));
        }
    }
}

// ============== GEMM variant 2 (K5): fp16 single x single, 3-stage, occ 2 ======
__global__ __launch_bounds__(256, 2) void hmma_gemm_ab_kernel(
    const __half* __restrict__ Ah, size_t strideA,
    const __half* __restrict__ Bh, size_t strideB,
    float* __restrict__ Cm, int ldc, size_t strideC,
    const float* __restrict__ bias, int K)
{
    extern __shared__ __align__(16) char smd[];
    const uint32_t sbase = smem_to_u32(smd);

    const int tid = threadIdx.x;
    const int wid = tid >> 5, lane = tid & 31;
    const int wm = wid & 3, wn = wid >> 2;
    const int m0 = wm * 32, n0w = wn * 64;

    const __half* Ahb = Ah + (size_t)blockIdx.z * strideA + (size_t)(blockIdx.y * 128) * K;
    const __half* Bhb = Bh + (size_t)blockIdx.z * strideB + (size_t)(blockIdx.x * 128) * K;
    float* Cb = Cm + (size_t)blockIdx.z * strideC;

    const int lrow = lane & 15;
    const int lcol = (lane >> 4) * 8;
    const int c0row = tid >> 1, c0seg = (tid & 1) * 2;

    float acc[2][8][4];
    #pragma unroll
    for (int mi = 0; mi < 2; mi++)
        #pragma unroll
        for (int n = 0; n < 8; n++)
            #pragma unroll
            for (int q = 0; q < 4; q++) acc[mi][n][q] = 0.f;

    auto cpasync_all = [&](int kt, int stg) {
        uint32_t dst = sbase + stg * ST5 + c0row * (ASTR * 2) + c0seg * 16;
        const char* sah = (const char*)(Ahb + (size_t)c0row * K + kt) + c0seg * 16;
        const char* sbh = (const char*)(Bhb + (size_t)c0row * K + kt) + c0seg * 16;
        CP_ASYNC16(dst + O5AH, sah); CP_ASYNC16(dst + O5AH + 16, sah + 16);
        CP_ASYNC16(dst + O5BH, sbh); CP_ASYNC16(dst + O5BH + 16, sbh + 16);
    };

    const int NT = K >> 5;
    cpasync_all(0, 0);
    CP_COMMIT();
    if (NT > 1) { cpasync_all(32, 1); CP_COMMIT(); CP_WAIT1(); }
    else        { CP_WAIT0(); }
    __syncthreads();

    for (int t = 0; t < NT; t++) {
        const bool has_n2 = (t + 2 < NT);
        if (has_n2) {
            cpasync_all((t + 2) * 32, (t + 2) % 3);
            CP_COMMIT();
        }

        const uint32_t sb = sbase + (t % 3) * ST5;
        #pragma unroll
        for (int ks = 0; ks < 2; ks++) {
            const int cb = ks * 16 + lcol;
            uint32_t ah[2][4], bh[4][4];
            #pragma unroll
            for (int mi = 0; mi < 2; mi++) {
                uint32_t off = ((m0 + mi * 16 + lrow) * ASTR + cb) * 2;
                ldsm_x4(ah[mi][0], ah[mi][1], ah[mi][2], ah[mi][3], sb + O5AH + off);
            }
            #pragma unroll
            for (int nj = 0; nj < 4; nj++) {
                uint32_t off = ((n0w + nj * 16 + lrow) * ASTR + cb) * 2;
                ldsm_x4(bh[nj][0], bh[nj][1], bh[nj][2], bh[nj][3], sb + O5BH + off);
            }
            #pragma unroll
            for (int mi = 0; mi < 2; mi++) {
                #pragma unroll
                for (int nj = 0; nj < 4; nj++) {
                    mma_f16(acc[mi][nj * 2],     ah[mi], bh[nj][0], bh[nj][2]);
                    mma_f16(acc[mi][nj * 2 + 1], ah[mi], bh[nj][1], bh[nj][3]);
                }
            }
        }

        if (t + 1 < NT) {
            if (has_n2) { CP_WAIT1(); } else { CP_WAIT0(); }
            __syncthreads();
        }
    }

    const int grp = lane >> 2, qid = lane & 3;
    #pragma unroll
    for (int mi = 0; mi < 2; mi++) {
        #pragma unroll
        for (int nj = 0; nj < 8; nj++) {
            int row = blockIdx.y * 128 + m0 + mi * 16 + grp;
            int col = blockIdx.x * 128 + n0w + nj * 8 + qid * 2;
            float b0 = bias[col], b1 = bias[col + 1];
            *(float2*)(Cb + (size_t)row * ldc + col) =
                make_float2(acc[mi][nj][0] + b0, acc[mi][nj][1] + b1);
            *(float2*)(Cb + (size_t)(row + 8) * ldc + col) =
                make_float2(acc[mi][nj][2] + b0, acc[mi][nj][3] + b1);
        }
    }
}

// ---------------- prep: W_in -> transposed fp16 --------------------------------
__global__ __launch_bounds__(256) void split_w_kernel(const float* __restrict__ W)
{
    int idx = blockIdx.x * 256 + threadIdx.x;   // k*256 + n
    int k = idx >> 8, n = idx & 255;
    g_Whi[(size_t)n * C_ + k] = __float2half_rn(W[idx]);
}

// ---------------- K2: slice weights -> fp16 (x hi only) ------------------------
__global__ __launch_bounds__(256) void slicew_kernel(
    const float* __restrict__ Wslice, const float* __restrict__ bslice,
    const float* __restrict__ temp)
{
    __shared__ float Ws[D_ * G_];
    __shared__ float bs[G_];
    __shared__ float it[H_];
    int tid = threadIdx.x;
    #pragma unroll
    for (int i = 0; i < 8; i++) Ws[tid + i * 256] = Wslice[tid + i * 256];
    if (tid < G_) bs[tid] = bslice[tid];
    if (tid < H_) it[tid] = 1.f / temp[tid];
    __syncthreads();

    int gid = blockIdx.x * 256 + tid;
    int n = gid >> 3, h = gid & 7;

    float x[D_];
    const uint4* XH = (const uint4*)(g_tmphi + (size_t)n * C_ + h * D_);
    #pragma unroll
    for (int i = 0; i < 4; i++) {
        uint4 hv = XH[i];
        __half2 p0 = *reinterpret_cast<__half2*>(&hv.x);
        __half2 p1 = *reinterpret_cast<__half2*>(&hv.y);
        __half2 p2 = *reinterpret_cast<__half2*>(&hv.z);
        __half2 p3 = *reinterpret_cast<__half2*>(&hv.w);
        x[8*i+0] = __half2float(p0.x); x[8*i+1] = __half2float(p0.y);
        x[8*i+2] = __half2float(p1.x); x[8*i+3] = __half2float(p1.y);
        x[8*i+4] = __half2float(p2.x); x[8*i+5] = __half2float(p2.y);
        x[8*i+6] = __half2float(p3.x); x[8*i+7] = __half2float(p3.y);
    }

    float2 lg[G_ / 2];
    const float2* bs2 = (const float2*)bs;
    #pragma unroll
    for (int j = 0; j < G_ / 2; j++) lg[j] = bs2[j];

    const float2* Ws2 = (const float2*)Ws;
    for (int d = 0; d < D_; d++) {
        float2 xv = make_float2(x[d], x[d]);
        #pragma unroll
        for (int j = 0; j < G_ / 2; j++) lg[j] = ffma2(xv, Ws2[d * (G_ / 2) + j], lg[j]);
    }

    float sc = it[h];
    float mx = -1e30f;
    #pragma unroll
    for (int j = 0; j < G_ / 2; j++) {
        lg[j].x *= sc; lg[j].y *= sc;
        mx = fmaxf(mx, fmaxf(lg[j].x, lg[j].y));
    }
    float sum = 0.f;
    #pragma unroll
    for (int j = 0; j < G_ / 2; j++) {
        lg[j].x = __expf(lg[j].x - mx);
        lg[j].y = __expf(lg[j].y - mx);
        sum += lg[j].x + lg[j].y;
    }
    float inv = 1.f / sum;

    size_t base = (size_t)n * (H_ * G_) + h * G_;
    uint2* dhi = (uint2*)(g_swhi + base);
    #pragma unroll
    for (int j = 0; j < 16; j++) {
        float v0 = lg[2*j].x * inv, v1 = lg[2*j].y * inv;
        float v2 = lg[2*j+1].x * inv, v3 = lg[2*j+1].y * inv;
        dhi[j] = make_uint2(bits2(__floats2half2_rn(v0, v1)),
                            bits2(__floats2half2_rn(v2, v3)));
    }
}

// ---------------- K3: pooling GEMM, per-group double-buffered ------------------
#define PG_SWH 0
#define PG_XH  9216
#define PG_SIZE 14336
// layout: group0 buf0 | group0 buf1 | group1 buf0 | group1 buf1 -> 57344 B
#define P_TOTAL 57344

__global__ __launch_bounds__(256, 1) void pool_mma_kernel()
{
    extern __shared__ __align__(16) char psm[];
    const uint32_t sbm = smem_to_u32(psm);

    const int tid = threadIdx.x, lane = tid & 31, w = tid >> 5;
    const int wg = w >> 2, wl = w & 3;
    const int g_tid = tid & 127;
    const int pc = blockIdx.x, bh = blockIdx.y;
    const int b = bh >> 3, h = bh & 7;
    const uint32_t gb0 = sbm + wg * (2 * PG_SIZE);   // group base (2 buffers)

    float acc[4][5][4];
    #pragma unroll
    for (int mi = 0; mi < 4; mi++)
        #pragma unroll
        for (int nj = 0; nj < 5; nj++)
            #pragma unroll
            for (int q = 0; q < 4; q++) acc[mi][nj][q] = 0.f;

    const int cb = wl * 16;
    const int trow = cb + ((lane >> 4) << 3) + (lane & 7);
    const int tcol8 = ((lane >> 3) & 1) << 3;
    const uint32_t onesf = ((lane >> 2) == 0) ? 0x3C003C00u : 0u;

    auto issue = [&](int it, int buf) {
        int sc = 2 * it + wg;
        size_t gn = (size_t)b * T_ + pc * 512 + (size_t)sc * 64;
        uint32_t gb = gb0 + buf * PG_SIZE;
        #pragma unroll
        for (int i = 0; i < 4; i++) {
            int c = g_tid + i * 128;
            int row = c >> 3, seg = c & 7;
            const char* sh = (const char*)(g_swhi + (gn + row) * (H_ * G_) + h * G_) + seg * 16;
            CP_ASYNC16(gb + PG_SWH + row * 144 + seg * 16, sh);
        }
        {
            int c = g_tid;
            int row = c >> 2, seg = c & 3;
            const char* xh = (const char*)(g_tmphi + (gn + row) * C_ + h * D_) + seg * 16;
            CP_ASYNC16(gb + PG_XH + row * 80 + seg * 16, xh);
            int c2 = g_tid + 128;
            int row2 = c2 >> 2, seg2 = c2 & 3;
            const char* xh2 = (const char*)(g_tmphi + (gn + row2) * C_ + h * D_) + seg2 * 16;
            CP_ASYNC16(gb + PG_XH + row2 * 80 + seg2 * 16, xh2);
        }
        CP_COMMIT();
    };

    issue(0, 0);

    for (int it = 0; it < 4; it++) {
        const bool has_next = (it + 1 < 4);
        if (has_next) issue(it + 1, (it + 1) & 1);

        if (has_next) { CP_WAIT1(); } else { CP_WAIT0(); }
        asm volatile("bar.sync %0, 128;" :: "r"(wg + 1) : "memory");

        const uint32_t gb = gb0 + (it & 1) * PG_SIZE;
        uint32_t bxh[2][4];
        #pragma unroll
        for (int t = 0; t < 2; t++) {
            uint32_t off = (trow * 40 + t * 16 + tcol8) * 2;
            ldsm_x4_t(bxh[t][0], bxh[t][1], bxh[t][2], bxh[t][3], gb + PG_XH + off);
        }

        #pragma unroll
        for (int mi = 0; mi < 4; mi++) {
            uint32_t ah[4];
            uint32_t off = (trow * 72 + mi * 16 + tcol8) * 2;
            ldsm_x4_t(ah[0], ah[1], ah[2], ah[3], gb + PG_SWH + off);
            #pragma unroll
            for (int nj = 0; nj < 4; nj++) {
                int t = nj >> 1, p = nj & 1;
                mma_f16(acc[mi][nj], ah, bxh[t][p], bxh[t][p + 2]);
            }
            mma_f16(acc[mi][4], ah, onesf, onesf);
        }
        asm volatile("bar.sync %0, 128;" :: "r"(wg + 1) : "memory");
    }

    // cross-group reduction: red [4 slots][64 g][40] = 40960 B (reuses smem)
    __syncthreads();
    float* red = (float*)psm;
    const int grp = lane >> 2, qid = lane & 3;
    if (wg == 0) {
        #pragma unroll
        for (int mi = 0; mi < 4; mi++)
            #pragma unroll
            for (int nj = 0; nj < 5; nj++) {
                int g0 = mi * 16 + grp, nn = nj * 8 + qid * 2;
                red[(wl * 64 + g0) * 40 + nn]         = acc[mi][nj][0];
                red[(wl * 64 + g0) * 40 + nn + 1]     = acc[mi][nj][1];
                red[(wl * 64 + g0 + 8) * 40 + nn]     = acc[mi][nj][2];
                red[(wl * 64 + g0 + 8) * 40 + nn + 1] = acc[mi][nj][3];
            }
    }
    __syncthreads();
    if (wg == 1) {
        #pragma unroll
        for (int mi = 0; mi < 4; mi++)
            #pragma unroll
            for (int nj = 0; nj < 5; nj++) {
                int g0 = mi * 16 + grp, nn = nj * 8 + qid * 2;
                red[(wl * 64 + g0) * 40 + nn]         += acc[mi][nj][0];
                red[(wl * 64 + g0) * 40 + nn + 1]     += acc[mi][nj][1];
                red[(wl * 64 + g0 + 8) * 40 + nn]     += acc[mi][nj][2];
                red[(wl * 64 + g0 + 8) * 40 + nn + 1] += acc[mi][nj][3];
            }
    }
    __syncthreads();

    for (int i = tid; i < 64 * 33; i += 256) {
        int g = i / 33, s = i - g * 33;
        float sum = red[g * 40 + s] + red[(64 + g) * 40 + s]
                  + red[(128 + g) * 40 + s] + red[(192 + g) * 40 + s];
        if (s < 32) g_part[((size_t)bh * NCH2 + pc) * (G_ * D_) + g * D_ + s] = sum;
        else        g_pnorm[((size_t)bh * NCH2 + pc) * G_ + g] = sum;
    }
}

// ------- K4a: reduce partials -> tokens -> qkv -> GxG attention -> g_os --------
__global__ __launch_bounds__(256) void attn_tiny_kernel(
    const float* __restrict__ Wq, const float* __restrict__ bq,
    const float* __restrict__ Wk, const float* __restrict__ bk,
    const float* __restrict__ Wv, const float* __restrict__ bv)
{
    __shared__ float tok[G_][D_ + 1];
    __shared__ float qs[G_][D_ + 1];
    __shared__ float ks[G_][D_ + 1];
    __shared__ float vs[G_][D_ + 1];
    __shared__ float norms[G_];

    int bh = blockIdx.x;
    int tid = threadIdx.x;

    if (tid < G_) {
        float s = 0.f;
        for (int ch = 0; ch < NCH2; ch++)
            s += g_pnorm[((size_t)bh * NCH2 + ch) * G_ + tid];
        norms[tid] = s + 1e-5f;
    }
    __syncthreads();

    #pragma unroll
    for (int i = 0; i < 8; i++) {
        int c = tid + i * 256;
        int g = c >> 5, d = c & 31;
        float s = 0.f;
        for (int ch = 0; ch < NCH2; ch++)
            s += g_part[((size_t)bh * NCH2 + ch) * (G_ * D_) + c];
        tok[g][d] = s / norms[g];
    }
    __syncthreads();

    #pragma unroll
    for (int i = 0; i < 8; i++) {
        int c = tid + i * 256;
        int g = c >> 5, d = c & 31;
        float aq = bq[d], ak = bk[d], av = bv[d];
        for (int e = 0; e < D_; e++) {
            float t = tok[g][e];
            aq += t * Wq[e * D_ + d];
            ak += t * Wk[e * D_ + d];
            av += t * Wv[e * D_ + d];
        }
        qs[g][d] = aq; ks[g][d] = ak; vs[g][d] = av;
    }
    __syncthreads();

    if (tid < G_) {
        float qr[D_];
        #pragma unroll
        for (int d = 0; d < D_; d++) qr[d] = qs[tid][d];
        float s[G_];
        float mx = -1e30f;
        #pragma unroll
        for (int j = 0; j < G_; j++) {
            float a = 0.f;
            #pragma unroll
            for (int d = 0; d < D_; d++) a += qr[d] * ks[j][d];
            a *= 0.17677669529663687f;
            s[j] = a; mx = fmaxf(mx, a);
        }
        float sum = 0.f;
        #pragma unroll
        for (int j = 0; j < G_; j++) { s[j] = __expf(s[j] - mx); sum += s[j]; }
        float inv = 1.f / sum;
        #pragma unroll
        for (int d = 0; d < D_; d++) {
            float a = 0.f;
            #pragma unroll
            for (int j = 0; j < G_; j++) a += s[j] * vs[j][d];
            g_os[(size_t)bh * (G_ * D_) + tid * D_ + d] = a * inv;
        }
    }
}

// ------- K4b: fold into transposed fp16 M --------------------------------------
__global__ __launch_bounds__(256) void fold_kernel(const float* __restrict__ Wout)
{
    __shared__ float os[G_][D_ + 1];
    __shared__ float Wt[D_][G_ + 1];
    int bh = blockIdx.y;
    int b = bh >> 3, h = bh & 7;
    int col0 = blockIdx.x * 64;
    int tid = threadIdx.x;

    #pragma unroll
    for (int i = 0; i < 8; i++) {
        int idx = tid + i * 256;
        os[idx >> 5][idx & 31] = g_os[(size_t)bh * (G_ * D_) + idx];
    }
    #pragma unroll
    for (int i = 0; i < 8; i++) {
        int idx = tid + i * 256;
        int d = idx >> 6, c = idx & 63;
        Wt[d][c] = Wout[(size_t)(h * D_ + d) * C_ + col0 + c];
    }
    __syncthreads();

    int c = tid & 63, g0 = tid >> 6;
    #pragma unroll
    for (int gi = 0; gi < 16; gi++) {
        int g = g0 * 16 + gi;
        float a = 0.f;
        #pragma unroll
        for (int d = 0; d < D_; d++) a += os[g][d] * Wt[d][c];
        size_t o = ((size_t)b * C_ + col0 + c) * (size_t)(H_ * G_) + h * G_ + g;
        g_M[o] = __float2half_rn(a);
    }
}

// ---------------- launch --------------------------------------------------------
extern "C" void kernel_launch(void* const* d_in, const int* in_sizes, int n_in,
                              void* d_out, int out_size)
{
    const float* x_q    = (const float*)d_in[0];
    const float* W_in   = (const float*)d_in[3];
    const float* b_in   = (const float*)d_in[4];
    const float* W_sl   = (const float*)d_in[5];
    const float* b_sl   = (const float*)d_in[6];
    const float* temp   = (const float*)d_in[7];
    const float* W_q    = (const float*)d_in[8];
    const float* b_q    = (const float*)d_in[9];
    const float* W_k    = (const float*)d_in[10];
    const float* b_k    = (const float*)d_in[11];
    const float* W_v    = (const float*)d_in[12];
    const float* b_v    = (const float*)d_in[13];
    const float* W_out  = (const float*)d_in[14];
    const float* b_out  = (const float*)d_in[15];
    float* out = (float*)d_out;

    __half *thi_p, *whi_p, *m_p, *shi_p;
    cudaGetSymbolAddress((void**)&thi_p, g_tmphi);
    cudaGetSymbolAddress((void**)&whi_p, g_Whi);
    cudaGetSymbolAddress((void**)&m_p, g_M);
    cudaGetSymbolAddress((void**)&shi_p, g_swhi);

    static int smem_set = 0;
    if (!smem_set) {
        cudaFuncSetAttribute(hmma_gemm_k1_kernel,
                             cudaFuncAttributeMaxDynamicSharedMemorySize, K1_SMEM);
        cudaFuncSetAttribute(hmma_gemm_ab_kernel,
                             cudaFuncAttributeMaxDynamicSharedMemorySize, AB_SMEM);
        cudaFuncSetAttribute(pool_mma_kernel,
                             cudaFuncAttributeMaxDynamicSharedMemorySize, P_TOTAL);
        smem_set = 1;
    }

    // prep: W_in -> fp16 (transposed)
    split_w_kernel<<<C_ * C_ / 256, 256>>>(W_in);

    // K1: tmp = x_q @ W_in + b_in  -> fp16 hi (2-product compute)
    hmma_gemm_k1_kernel<<<dim3(C_/128, N_/128), 256, K1_SMEM>>>(
        x_q, C_, whi_p, thi_p, C_, b_in, C_);

    // K2: slice softmax -> fp16
    slicew_kernel<<<(N_ * H_) / 256, 256>>>(W_sl, b_sl, temp);

    // K3: pooling GEMM (double-buffered per group)
    pool_mma_kernel<<<dim3(NCH2, B_ * H_), 256, P_TOTAL>>>();

    // K4a: reduce + tiny attention
    attn_tiny_kernel<<<B_ * H_, 256>>>(W_q, b_q, W_k, b_k, W_v, b_v);

    // K4b: fold W_out into fp16 M
    fold_kernel<<<dim3(4, B_ * H_), 256>>>(W_out);

    // K5: out[b] = SW[b] @ M[b] + b_out  (3-stage, occ 2)
    hmma_gemm_ab_kernel<<<dim3(C_/128, T_/128, B_), 256, AB_SMEM>>>(
        shi_p, (size_t)T_ * (H_ * G_),
        m_p, (size_t)C_ * (H_ * G_),
        out, C_, (size_t)T_ * C_,
        b_out, H_ * G_);
}